// round 12
// baseline (speedup 1.0000x reference)
#include <cuda_runtime.h>
#include <cuda_fp16.h>
#include <math.h>
#include <stdint.h>

#define DD     512
#define SS     1024
#define NBB    16
#define QQ     64
#define NDOC   8

// ---- read-side f32 scratch (full 16 batches; half-2 uses +offset views) ----
__device__ float g_X   [16384 * 512];
__device__ float g_V   [16384 * 512];
__device__ float g_Kb  [16384 * 512];
// ---- write-side f32 scratch ----
__device__ float g_Xw  [8192 * 512];
__device__ float g_Vw  [8192 * 512];
__device__ float g_Kw  [8192 * 512];
__device__ float g_S1  [8 * 64 * 1024];
__device__ float g_Kdoc[8192 * 512];
__device__ float g_Vdoc[8192 * 512];
__device__ float g_A1S [8 * 64 * 512];
__device__ float g_A2SC[16384 * 64];
__device__ float g_A2  [16384 * 512];
__device__ float g_sin [1024 * 256];
__device__ float g_cos [1024 * 256];
__device__ float g_BIASW[8 * 1024];
__device__ float g_BIASR[16 * 1024];

#define WLO 6815744LL
#define LO  8388608LL
#define LOW 4194304LL
__device__ __align__(16) __half g_PW  [2 * 26 * 262144];
__device__ __align__(16) __half g_Praw[4194304];
__device__ __align__(16) __half g_Ppd [8388608];
// read-side planes (full; half-2 offsets stay inside hi / lo blocks)
__device__ __align__(16) __half g_Px  [2 * 8388608];
__device__ __align__(16) __half g_Pq  [8388608];
__device__ __align__(16) __half g_Pk  [8388608];
__device__ __align__(16) __half g_Pvt [8388608];
__device__ __align__(16) __half g_Pp  [16777216];
__device__ __align__(16) __half g_Pbq [2 * 8388608];
__device__ __align__(16) __half g_Ph  [2 * 8388608];
__device__ __align__(16) __half g_Sh  [16 * 1048576];
// write-side planes
__device__ __align__(16) __half g_Pxw [2 * 4194304];
__device__ __align__(16) __half g_Pqw [4194304];
__device__ __align__(16) __half g_Pkw [4194304];
__device__ __align__(16) __half g_Pvtw[4194304];
__device__ __align__(16) __half g_Ppw [8388608];
__device__ __align__(16) __half g_Pbqw[2 * 4194304];
__device__ __align__(16) __half g_Phw [2 * 4194304];
__device__ __align__(16) __half g_Shw [8 * 1048576];
// misc planes
__device__ __align__(16) __half g_Pk2 [8388608];
__device__ __align__(16) __half g_Pa2 [1048576];
__device__ __align__(16) __half g_Psel[524288];
__device__ __align__(16) __half g_Pqst[32768];

__device__ __forceinline__ uint32_t smem_u32(const void* p) {
    uint32_t a;
    asm("{ .reg .u64 t; cvta.to.shared.u64 t, %1; cvt.u32.u64 %0, t; }"
        : "=r"(a) : "l"(p));
    return a;
}

__device__ __forceinline__ void ldsm4(uint32_t* r, uint32_t addr) {
    asm volatile("ldmatrix.sync.aligned.m8n8.x4.shared.b16 {%0,%1,%2,%3}, [%4];"
                 : "=r"(r[0]), "=r"(r[1]), "=r"(r[2]), "=r"(r[3]) : "r"(addr));
}

__device__ __forceinline__ void mma_f16(float* c, const uint32_t* a,
                                        uint32_t b0, uint32_t b1) {
    asm volatile(
        "mma.sync.aligned.m16n8k16.row.col.f32.f16.f16.f32 "
        "{%0,%1,%2,%3}, {%4,%5,%6,%7}, {%8,%9}, {%0,%1,%2,%3};"
        : "+f"(c[0]), "+f"(c[1]), "+f"(c[2]), "+f"(c[3])
        : "r"(a[0]), "r"(a[1]), "r"(a[2]), "r"(a[3]), "r"(b0), "r"(b1));
}

__device__ __forceinline__ void cpasync16(uint32_t dst, const void* src) {
    asm volatile("cp.async.cg.shared.global [%0], [%1], 16;" :: "r"(dst), "l"(src));
}
#define CP_COMMIT() asm volatile("cp.async.commit_group;" ::: "memory")
#define CP_WAIT(n)  asm volatile("cp.async.wait_group %0;" :: "n"(n) : "memory")

__device__ __forceinline__ void split_pair(float x0, float x1,
                                           __half2& h, __half2& l) {
    h = __floats2half2_rn(x0, x1);
    l = __floats2half2_rn(x0 - __low2float(h), x1 - __high2float(h));
}

// ---------------------------------------------------------------------------
// 3-term split GEMM (fp16 planes): residual-path GEMMs (Wo, FF)
// ---------------------------------------------------------------------------
#define PLANE  10240
#define TSTAGE 40960
#define TG_SMEM (4 * 40960)

__global__ void __launch_bounds__(512)
tgemm3(const __half* __restrict__ Ah0, const __half* __restrict__ Bh0,
       const float* __restrict__ bias, float* __restrict__ Cf,
       __half* __restrict__ Ch0,
       int M, int N, int K,
       long long loA, long long loB, long long loC,
       long long sA, long long sB, long long sC, long long sCp,
       float alpha, int epi)
{
    extern __shared__ char smem[];
    const uint32_t sbu = smem_u32(smem);
    const int t = threadIdx.x, w = t >> 5, lane = t & 31;
    const int wm = w & 3, wn = w >> 2;
    const int z = blockIdx.z;
    const int m0 = blockIdx.y * 128, n0 = blockIdx.x * 128;

    const __half* Ah = Ah0 + (size_t)z * sA;
    const __half* Bh = Bh0 + (size_t)z * sB;

    const int lrow = t >> 2, seg = t & 3;
    const __half* pr[4];
    pr[0] = Ah + (size_t)(m0 + lrow) * K + seg * 8;
    pr[1] = pr[0] + loA;
    pr[2] = Bh + (size_t)(n0 + lrow) * K + seg * 8;
    pr[3] = pr[2] + loB;

    float acc[2][4][4];
#pragma unroll
    for (int i = 0; i < 2; i++)
#pragma unroll
        for (int j = 0; j < 4; j++)
#pragma unroll
            for (int e = 0; e < 4; e++) acc[i][j][e] = 0.0f;

    const int nch = K >> 5;
    const uint32_t sdbase = sbu + (uint32_t)(lrow * 80 + seg * 16);

#define ISSUE(ch) do {                                                      \
    uint32_t _sd = sdbase + (uint32_t)((ch) & 3) * TSTAGE;                  \
    const int _cb = (ch) * 32;                                              \
    _Pragma("unroll")                                                       \
    for (int _p = 0; _p < 4; _p++)                                          \
        cpasync16(_sd + _p * PLANE, pr[_p] + _cb);                          \
    CP_COMMIT();                                                            \
} while (0)

    ISSUE(0);
    ISSUE(1);
    if (nch > 2) ISSUE(2);

    const uint32_t lmoff = (uint32_t)((lane & 15) * 80 + (lane >> 4) * 16);

    for (int ch = 0; ch < nch; ch++) {
        const int rem = nch - 1 - ch;
        if (rem >= 2)      { CP_WAIT(2); }
        else if (rem == 1) { CP_WAIT(1); }
        else               { CP_WAIT(0); }
        __syncthreads();
        if (ch + 3 < nch) ISSUE(ch + 3);

        const uint32_t sAh = sbu + (uint32_t)(ch & 3) * TSTAGE;
        const uint32_t sBh = sAh + 2 * PLANE;
#pragma unroll
        for (int kk = 0; kk < 2; kk++) {
            uint32_t ah[2][4], al[2][4], bh[2][4], bl[2][4];
#pragma unroll
            for (int mt = 0; mt < 2; mt++) {
                uint32_t aaddr = sAh + (uint32_t)((wm * 32 + mt * 16) * 80 + kk * 32) + lmoff;
                ldsm4(ah[mt], aaddr);
                ldsm4(al[mt], aaddr + PLANE);
            }
#pragma unroll
            for (int ng = 0; ng < 2; ng++) {
                uint32_t baddr = sBh + (uint32_t)((wn * 32 + ng * 16) * 80 + kk * 32) + lmoff;
                ldsm4(bh[ng], baddr);
                ldsm4(bl[ng], baddr + PLANE);
            }
#pragma unroll
            for (int ng = 0; ng < 2; ng++)
#pragma unroll
                for (int mt = 0; mt < 2; mt++)
#pragma unroll
                    for (int h2 = 0; h2 < 2; h2++)
                        mma_f16(acc[mt][ng * 2 + h2], ah[mt], bh[ng][h2], bh[ng][h2 + 2]);
#pragma unroll
            for (int ng = 0; ng < 2; ng++)
#pragma unroll
                for (int mt = 0; mt < 2; mt++)
#pragma unroll
                    for (int h2 = 0; h2 < 2; h2++)
                        mma_f16(acc[mt][ng * 2 + h2], ah[mt], bl[ng][h2], bl[ng][h2 + 2]);
#pragma unroll
            for (int ng = 0; ng < 2; ng++)
#pragma unroll
                for (int mt = 0; mt < 2; mt++)
#pragma unroll
                    for (int h2 = 0; h2 < 2; h2++)
                        mma_f16(acc[mt][ng * 2 + h2], al[mt], bh[ng][h2], bh[ng][h2 + 2]);
        }
    }
#undef ISSUE

    const float GC = 0.7978845608028654f;
    const int crow = m0 + wm * 32 + (lane >> 2);
    const int ccol = n0 + wn * 32 + (lane & 3) * 2;

    float* Cfz = Cf ? Cf + (size_t)z * sC : (float*)0;
    __half* Chz = Ch0 ? Ch0 + (size_t)z * sCp : (__half*)0;
    __half* Clz = Chz ? Chz + loC : (__half*)0;
#pragma unroll
    for (int mt = 0; mt < 2; mt++) {
#pragma unroll
        for (int n8 = 0; n8 < 4; n8++) {
            const float* c = acc[mt][n8];
            const int col = ccol + n8 * 8;
            float b0 = bias ? bias[col]     : 0.0f;
            float b1 = bias ? bias[col + 1] : 0.0f;
#pragma unroll
            for (int h = 0; h < 2; h++) {
                const int row = crow + mt * 16 + h * 8;
                float x0 = c[h * 2 + 0] * alpha + b0;
                float x1 = c[h * 2 + 1] * alpha + b1;
                if (epi == 1) {
                    x0 = 0.5f * x0 * (1.0f + tanhf(GC * (x0 + 0.044715f * x0 * x0 * x0)));
                    x1 = 0.5f * x1 * (1.0f + tanhf(GC * (x1 + 0.044715f * x1 * x1 * x1)));
                }
                if (Cfz)
                    *(float2*)&Cfz[(size_t)row * N + col] = make_float2(x0, x1);
                if (Chz) {
                    __half2 hh, ll;
                    split_pair(x0, x1, hh, ll);
                    *(__half2*)&Chz[(size_t)row * N + col] = hh;
                    *(__half2*)&Clz[(size_t)row * N + col] = ll;
                }
            }
        }
    }
}

static void tg3(const __half* Ah, long long loA, long long sA,
                const __half* Bh, long long loB, long long sB,
                const float* bias, float* Cf, long long sC,
                __half* Ch, long long loC, long long sCp,
                int M, int N, int K, int batch, float alpha, int epi,
                cudaStream_t st)
{
    dim3 grid(N / 128, M / 128, batch);
    tgemm3<<<grid, 512, TG_SMEM, st>>>(Ah, Bh, bias, Cf, Ch, M, N, K,
                                       loA, loB, loC, sA, sB, sC, sCp, alpha, epi);
}

// ---------------------------------------------------------------------------
// 1-term GEMM (hi planes only). epi: 0 = plain, 2 = QKV rope epilogue
// ---------------------------------------------------------------------------
#define T1STAGE 20480
#define T1_SMEM (4 * 20480)

__global__ void __launch_bounds__(512)
tgemm1(const __half* __restrict__ Ah0, const __half* __restrict__ Bh0,
       const float* __restrict__ bias, float* __restrict__ Cf,
       __half* __restrict__ Ch0, __half* __restrict__ Ch2,
       int M, int N, int K, long long loC,
       long long sA, long long sB, long long sC, long long sCp,
       float alpha, int epi)
{
    extern __shared__ char smem[];
    const uint32_t sbu = smem_u32(smem);
    const int t = threadIdx.x, w = t >> 5, lane = t & 31;
    const int wm = w & 3, wn = w >> 2;
    const int z = blockIdx.z;
    const int m0 = blockIdx.y * 128, n0 = blockIdx.x * 128;

    const __half* Ap = Ah0 + (size_t)z * sA + (size_t)(m0 + (t >> 2)) * K + (t & 3) * 8;
    const __half* Bp = Bh0 + (size_t)z * sB + (size_t)(n0 + (t >> 2)) * K + (t & 3) * 8;

    float acc[2][4][4];
#pragma unroll
    for (int i = 0; i < 2; i++)
#pragma unroll
        for (int j = 0; j < 4; j++)
#pragma unroll
            for (int e = 0; e < 4; e++) acc[i][j][e] = 0.0f;

    const int nch = K >> 5;
    const uint32_t sdbase = sbu + (uint32_t)((t >> 2) * 80 + (t & 3) * 16);

#define ISSUE1(ch) do {                                                     \
    uint32_t _sd = sdbase + (uint32_t)((ch) & 3) * T1STAGE;                 \
    const int _cb = (ch) * 32;                                              \
    cpasync16(_sd,         Ap + _cb);                                       \
    cpasync16(_sd + PLANE, Bp + _cb);                                       \
    CP_COMMIT();                                                            \
} while (0)

    ISSUE1(0);
    ISSUE1(1);
    if (nch > 2) ISSUE1(2);

    const uint32_t lmoff = (uint32_t)((lane & 15) * 80 + (lane >> 4) * 16);

    for (int ch = 0; ch < nch; ch++) {
        const int rem = nch - 1 - ch;
        if (rem >= 2)      { CP_WAIT(2); }
        else if (rem == 1) { CP_WAIT(1); }
        else               { CP_WAIT(0); }
        __syncthreads();
        if (ch + 3 < nch) ISSUE1(ch + 3);

        const uint32_t sAh = sbu + (uint32_t)(ch & 3) * T1STAGE;
        const uint32_t sBh = sAh + PLANE;
#pragma unroll
        for (int kk = 0; kk < 2; kk++) {
            uint32_t ah[2][4], bh[2][4];
#pragma unroll
            for (int mt = 0; mt < 2; mt++)
                ldsm4(ah[mt], sAh + (uint32_t)((wm * 32 + mt * 16) * 80 + kk * 32) + lmoff);
#pragma unroll
            for (int ng = 0; ng < 2; ng++)
                ldsm4(bh[ng], sBh + (uint32_t)((wn * 32 + ng * 16) * 80 + kk * 32) + lmoff);
#pragma unroll
            for (int ng = 0; ng < 2; ng++)
#pragma unroll
                for (int mt = 0; mt < 2; mt++)
#pragma unroll
                    for (int h2 = 0; h2 < 2; h2++)
                        mma_f16(acc[mt][ng * 2 + h2], ah[mt], bh[ng][h2], bh[ng][h2 + 2]);
        }
    }
#undef ISSUE1

    const int crow = m0 + wm * 32 + (lane >> 2);
    const int ccol = n0 + wn * 32 + (lane & 3) * 2;

    if (epi == 2) {
#pragma unroll
        for (int mt = 0; mt < 2; mt++) {
#pragma unroll
            for (int n8 = 0; n8 < 4; n8++) {
                const float* c = acc[mt][n8];
                const int col = ccol + n8 * 8;
                float b0 = bias[col], b1 = bias[col + 1];
#pragma unroll
                for (int h = 0; h < 2; h++) {
                    const int row = crow + mt * 16 + h * 8;
                    float x0 = c[h * 2 + 0] + b0;
                    float x1 = c[h * 2 + 1] + b1;
                    if (col < 1024) {
                        const int s = row & (SS - 1);
                        const int i = (col & 511) >> 1;
                        float sn = g_sin[s * 256 + i];
                        float cs = g_cos[s * 256 + i];
                        float y0 = x0 * cs - x1 * sn;
                        float y1 = x0 * sn + x1 * cs;
                        __half* dst = (col < 512) ? Ch0 : Ch2;
                        size_t off = (size_t)row * 512 + (col & 511);
                        *(__half2*)&dst[off] = __floats2half2_rn(y0, y1);
                    } else {
                        *(float2*)&Cf[(size_t)row * 512 + (col - 1024)] =
                            make_float2(x0, x1);
                    }
                }
            }
        }
        return;
    }

    float* Cfz = Cf ? Cf + (size_t)z * sC : (float*)0;
    __half* Chz = Ch0 ? Ch0 + (size_t)z * sCp : (__half*)0;
    __half* Clz = (Chz && loC) ? Chz + loC : (__half*)0;
#pragma unroll
    for (int mt = 0; mt < 2; mt++) {
#pragma unroll
        for (int n8 = 0; n8 < 4; n8++) {
            const float* c = acc[mt][n8];
            const int col = ccol + n8 * 8;
            float b0 = bias ? bias[col]     : 0.0f;
            float b1 = bias ? bias[col + 1] : 0.0f;
#pragma unroll
            for (int h = 0; h < 2; h++) {
                const int row = crow + mt * 16 + h * 8;
                float x0 = c[h * 2 + 0] * alpha + b0;
                float x1 = c[h * 2 + 1] * alpha + b1;
                if (Cfz)
                    *(float2*)&Cfz[(size_t)row * N + col] = make_float2(x0, x1);
                if (Chz) {
                    __half2 hh, ll;
                    split_pair(x0, x1, hh, ll);
                    *(__half2*)&Chz[(size_t)row * N + col] = hh;
                    if (Clz) *(__half2*)&Clz[(size_t)row * N + col] = ll;
                }
            }
        }
    }
}

static void tg1(const __half* Ah, long long sA, const __half* Bh, long long sB,
                const float* bias, float* Cf, long long sC,
                __half* Ch, __half* Ch2, long long loC, long long sCp,
                int M, int N, int K, int batch, float alpha, int epi,
                cudaStream_t st)
{
    dim3 grid(N / 128, M / 128, batch);
    tgemm1<<<grid, 512, T1_SMEM, st>>>(Ah, Bh, bias, Cf, Ch, Ch2, M, N, K, loC,
                                       sA, sB, sC, sCp, alpha, epi);
}

// 1-term, N-tile 64
#define B1STAGE 15360
#define T1N_SMEM (4 * 15360)

__global__ void __launch_bounds__(256)
tgemm1n64(const __half* __restrict__ Ah0, const __half* __restrict__ Bh0,
          float* __restrict__ Cf, int M, int N, int K, float alpha)
{
    extern __shared__ char smem[];
    const uint32_t sbu = smem_u32(smem);
    const int t = threadIdx.x, w = t >> 5, lane = t & 31;
    const int wm = w & 3, wn = w >> 2;
    const int m0 = blockIdx.y * 128, n0 = blockIdx.x * 64;

    const int arow = t >> 1, aseg = (t & 1) * 2;
    const int brow = t >> 2, bseg = t & 3;
    const __half* pa = Ah0 + (size_t)(m0 + arow) * K + aseg * 8;
    const __half* pb = Bh0 + (size_t)(n0 + brow) * K + bseg * 8;
    const uint32_t adst = sbu + (uint32_t)(arow * 80 + aseg * 16);
    const uint32_t bdst = sbu + 10240u + (uint32_t)(brow * 80 + bseg * 16);

    float acc[2][4][4];
#pragma unroll
    for (int i = 0; i < 2; i++)
#pragma unroll
        for (int j = 0; j < 4; j++)
#pragma unroll
            for (int e = 0; e < 4; e++) acc[i][j][e] = 0.0f;

    const int nch = K >> 5;

#define ISSUEN(ch) do {                                                     \
    uint32_t _st = (uint32_t)((ch) & 3) * B1STAGE;                          \
    const int _cb = (ch) * 32;                                              \
    cpasync16(adst + _st,      pa + _cb);                                   \
    cpasync16(adst + _st + 16, pa + _cb + 8);                               \
    cpasync16(bdst + _st,      pb + _cb);                                   \
    CP_COMMIT();                                                            \
} while (0)

    ISSUEN(0);
    ISSUEN(1);
    if (nch > 2) ISSUEN(2);

    const uint32_t lmoff = (uint32_t)((lane & 15) * 80 + (lane >> 4) * 16);

    for (int ch = 0; ch < nch; ch++) {
        const int rem = nch - 1 - ch;
        if (rem >= 2)      { CP_WAIT(2); }
        else if (rem == 1) { CP_WAIT(1); }
        else               { CP_WAIT(0); }
        __syncthreads();
        if (ch + 3 < nch) ISSUEN(ch + 3);

        const uint32_t sAh = sbu + (uint32_t)(ch & 3) * B1STAGE;
        const uint32_t sBh = sAh + 10240u;
#pragma unroll
        for (int kk = 0; kk < 2; kk++) {
            uint32_t ah[2][4], bh[2][4];
#pragma unroll
            for (int mt = 0; mt < 2; mt++)
                ldsm4(ah[mt], sAh + (uint32_t)((wm * 32 + mt * 16) * 80 + kk * 32) + lmoff);
#pragma unroll
            for (int ng = 0; ng < 2; ng++)
                ldsm4(bh[ng], sBh + (uint32_t)((wn * 32 + ng * 16) * 80 + kk * 32) + lmoff);
#pragma unroll
            for (int ng = 0; ng < 2; ng++)
#pragma unroll
                for (int mt = 0; mt < 2; mt++)
#pragma unroll
                    for (int h2 = 0; h2 < 2; h2++)
                        mma_f16(acc[mt][ng * 2 + h2], ah[mt], bh[ng][h2], bh[ng][h2 + 2]);
        }
    }
#undef ISSUEN

    const int crow = m0 + wm * 32 + (lane >> 2);
    const int ccol = n0 + wn * 32 + (lane & 3) * 2;
#pragma unroll
    for (int mt = 0; mt < 2; mt++)
#pragma unroll
        for (int n8 = 0; n8 < 4; n8++) {
            const float* c = acc[mt][n8];
            const int col = ccol + n8 * 8;
#pragma unroll
            for (int h = 0; h < 2; h++) {
                const int row = crow + mt * 16 + h * 8;
                *(float2*)&Cf[(size_t)row * N + col] =
                    make_float2(c[h * 2] * alpha, c[h * 2 + 1] * alpha);
            }
        }
}

// ---------------------------------------------------------------------------
__global__ void trans_conv(const float* __restrict__ in, __half* __restrict__ oh,
                           long long loOff, int R, int C,
                           long long sI, long long sO, const int* __restrict__ ids)
{
    __shared__ float tile[32][33];
    const int z = blockIdx.z;
    size_t ib = ids ? (size_t)ids[z] * sI : (size_t)z * sI;
    const float* ip = in + ib;
    __half* ohz = oh + (size_t)z * sO;
    __half* olz = loOff ? ohz + loOff : (__half*)0;
    const int c0 = blockIdx.x * 32, r0 = blockIdx.y * 32;
    const int tx = threadIdx.x, ty = threadIdx.y;
#pragma unroll
    for (int k = 0; k < 32; k += 8)
        tile[ty + k][tx] = ip[(size_t)(r0 + ty + k) * C + c0 + tx];
    __syncthreads();
    const int rr = (tx & 15) * 2, chf = tx >> 4;
#pragma unroll
    for (int k = 0; k < 2; k++) {
        int cc = ty + chf * 8 + k * 16;
        __half2 h, l;
        split_pair(tile[rr][cc], tile[rr + 1][cc], h, l);
        *(__half2*)&ohz[(size_t)(c0 + cc) * R + r0 + rr] = h;
        if (olz) *(__half2*)&olz[(size_t)(c0 + cc) * R + r0 + rr] = l;
    }
}

__global__ void conv_planes(const float* __restrict__ in, __half* __restrict__ oh,
                            long long lo)
{
    size_t idx = (size_t)blockIdx.x * 512 + (size_t)threadIdx.x * 2;
    float2 v = *(const float2*)&in[idx];
    __half2 h, l;
    split_pair(v.x, v.y, h, l);
    *(__half2*)&oh[idx] = h;
    if (lo) *(__half2*)&(oh + lo)[idx] = l;
}

__global__ void rope_table_kernel()
{
    int s = blockIdx.x;
    int i = threadIdx.x;
    float invf = 1.0f / powf(10000.0f, (float)i / 256.0f);
    float angf = (float)s * invf;
    double ang = (double)angf;
    g_sin[s * 256 + i] = (float)sin(ang);
    g_cos[s * 256 + i] = (float)cos(ang);
}

__global__ void bias_prep(const float* __restrict__ pos, float* __restrict__ out, int mode)
{
    int n = blockIdx.x, t = threadIdx.x;
    for (int c = t; c < 1024; c += 256) {
        float p = pos[n * 1024 + c];
        out[n * 1024 + c] = (mode == 1) ? logf(p) : (logf(p) - log1pf(-p));
    }
}

__global__ void softmax1024_planes(const __half* __restrict__ S, const float* __restrict__ bias,
                                   __half* __restrict__ oh)
{
    const int row = blockIdx.x, t = threadIdx.x;
    const __half* sr = S + (size_t)row * 1024;
    const float* pb = bias + (size_t)(row >> 10) * 1024;
    __half2 a  = *(const __half2*)&sr[2 * t];
    __half2 b2 = *(const __half2*)&sr[512 + 2 * t];
    float2 ba = *(const float2*)&pb[2 * t];
    float2 bb = *(const float2*)&pb[512 + 2 * t];
    float v0 = __low2float(a) + ba.x,  v1 = __high2float(a) + ba.y;
    float v2 = __low2float(b2) + bb.x, v3 = __high2float(b2) + bb.y;

    __shared__ float red[256];
    float mx = fmaxf(fmaxf(v0, v1), fmaxf(v2, v3));
    red[t] = mx; __syncthreads();
    for (int s = 128; s > 0; s >>= 1) { if (t < s) red[t] = fmaxf(red[t], red[t + s]); __syncthreads(); }
    mx = red[0]; __syncthreads();

    float e0 = expf(v0 - mx), e1 = expf(v1 - mx), e2 = expf(v2 - mx), e3 = expf(v3 - mx);
    red[t] = e0 + e1 + e2 + e3; __syncthreads();
    for (int s = 128; s > 0; s >>= 1) { if (t < s) red[t] += red[t + s]; __syncthreads(); }
    float inv = 1.0f / red[0];

    size_t o = (size_t)row * 1024 + 2 * t;
    *(__half2*)&oh[o]       = __floats2half2_rn(e0 * inv, e1 * inv);
    *(__half2*)&oh[o + 512] = __floats2half2_rn(e2 * inv, e3 * inv);
}

__global__ void softmax64_planes(const float* __restrict__ S, __half* __restrict__ oh)
{
    const int row = blockIdx.x * 8 + (threadIdx.x >> 5);
    const int lane = threadIdx.x & 31;
    const float* sr = S + (size_t)row * 64;
    float2 v = *(const float2*)&sr[lane * 2];
    float mx = fmaxf(v.x, v.y);
#pragma unroll
    for (int o = 16; o > 0; o >>= 1)
        mx = fmaxf(mx, __shfl_xor_sync(0xFFFFFFFF, mx, o));
    float e0 = expf(v.x - mx), e1 = expf(v.y - mx);
    float s = e0 + e1;
#pragma unroll
    for (int o = 16; o > 0; o >>= 1)
        s += __shfl_xor_sync(0xFFFFFFFF, s, o);
    float inv = 1.0f / s;
    *(__half2*)&oh[(size_t)row * 64 + lane * 2] = __floats2half2_rn(e0 * inv, e1 * inv);
}

__global__ void softmax_f32(float* __restrict__ S, const float* __restrict__ bias,
                            int cols, int rpb)
{
    int row = blockIdx.x;
    float* sr = S + (size_t)row * cols;
    const float* pb = bias + (size_t)(row / rpb) * cols;
    int t = threadIdx.x;
    __shared__ float red[256];

    float mx = -1e30f;
    for (int c = t; c < cols; c += 256) {
        float v = sr[c] + pb[c];
        sr[c] = v;
        mx = fmaxf(mx, v);
    }
    red[t] = mx; __syncthreads();
    for (int s = 128; s > 0; s >>= 1) { if (t < s) red[t] = fmaxf(red[t], red[t + s]); __syncthreads(); }
    mx = red[0]; __syncthreads();

    float sum = 0.0f;
    for (int c = t; c < cols; c += 256) {
        float e = expf(sr[c] - mx);
        sr[c] = e;
        sum += e;
    }
    red[t] = sum; __syncthreads();
    for (int s = 128; s > 0; s >>= 1) { if (t < s) red[t] += red[t + s]; __syncthreads(); }
    float inv = 1.0f / red[0];
    for (int c = t; c < cols; c += 256) sr[c] *= inv;
}

__global__ void ln_kernel(const float* __restrict__ Xin, const float* __restrict__ R,
                          const float* __restrict__ g, const float* __restrict__ b,
                          float* __restrict__ Xout,
                          __half* __restrict__ oh, long long lo)
{
    int row = blockIdx.x;
    int t   = threadIdx.x;
    const float* xr = Xin + (size_t)row * DD;
    const float* rr = R + (size_t)row * DD;

    float v0 = xr[2 * t] + rr[2 * t];
    float v1 = xr[2 * t + 1] + rr[2 * t + 1];

    __shared__ float red[256];
    red[t] = v0 + v1; __syncthreads();
    for (int s = 128; s > 0; s >>= 1) { if (t < s) red[t] += red[t + s]; __syncthreads(); }
    float m = red[0] * (1.0f / 512.0f);
    __syncthreads();

    float d0 = v0 - m, d1 = v1 - m;
    red[t] = d0 * d0 + d1 * d1; __syncthreads();
    for (int s = 128; s > 0; s >>= 1) { if (t < s) red[t] += red[t + s]; __syncthreads(); }
    float var = red[0] * (1.0f / 512.0f);
    float inv = rsqrtf(var + 1e-5f);

    float o0 = d0 * inv * g[2 * t]     + b[2 * t];
    float o1 = d1 * inv * g[2 * t + 1] + b[2 * t + 1];
    float* xo = Xout + (size_t)row * DD;
    xo[2 * t]     = o0;
    xo[2 * t + 1] = o1;

    __half2 h, l;
    split_pair(o0, o1, h, l);
    size_t o = (size_t)row * DD + 2 * t;
    *(__half2*)&oh[o] = h;
    *(__half2*)&(oh + lo)[o] = l;
}

__global__ void vgate_kernel(const float* __restrict__ F, const float* __restrict__ raw,
                             const float* __restrict__ Wig, const float* __restrict__ big,
                             float* __restrict__ V)
{
    int row = blockIdx.x;
    int t   = threadIdx.x;
    const float* fr = F + (size_t)row * DD;
    __shared__ float red[256];
    float s = fr[t] * Wig[t] + fr[t + 256] * Wig[t + 256];
    red[t] = s; __syncthreads();
    for (int k = 128; k > 0; k >>= 1) { if (t < k) red[t] += red[t + k]; __syncthreads(); }
    float gte = 1.0f / (1.0f + expf(-(red[0] + big[0])));
    const float* rr = raw + (size_t)row * DD;
    float* vr = V + (size_t)row * DD;
    vr[t]       = rr[t]       * gte;
    vr[t + 256] = rr[t + 256] * gte;
}

__global__ void out_kernel(const float* __restrict__ FU, const float* __restrict__ A2,
                           const float* __restrict__ PD,
                           const float* __restrict__ Wu1, const float* __restrict__ bu1,
                           const float* __restrict__ Wu2, const float* __restrict__ bu2,
                           const float* __restrict__ b1,
                           float* __restrict__ out, float* __restrict__ gate)
{
    int row = blockIdx.x;
    int t   = threadIdx.x;
    const float* fu = FU + (size_t)row * DD;
    const float* a2 = A2 + (size_t)row * DD;
    const float* pd = PD + (size_t)row * DD;

    __shared__ float red[256];
    float s = fu[t] * Wu1[t] + fu[t + 256] * Wu1[t + 256]
            + a2[t] * Wu2[t] + a2[t + 256] * Wu2[t + 256];
    red[t] = s; __syncthreads();
    for (int k = 128; k > 0; k >>= 1) { if (t < k) red[t] += red[t + k]; __syncthreads(); }
    float z = red[0] + bu1[0] + bu2[0] + b1[0] - 4.0f;
    float g = 1.0f / (1.0f + expf(-z));

    float* orow = out + (size_t)row * DD;
    orow[t]       = pd[t]       * (1.0f - g) + a2[t]       * g;
    orow[t + 256] = pd[t + 256] * (1.0f - g) + a2[t + 256] * g;
    if (t == 0) gate[row] = g;
}

#define BM 64
#define BN 64
#define BK 16

__global__ void gemm_kernel(const float* __restrict__ A,
                            const float* __restrict__ Bm,
                            const float* __restrict__ bias,
                            float* __restrict__ C,
                            int M, int N, int K,
                            long long sA, long long sB, long long sC,
                            float alpha, int transB, int epi)
{
    const int bz = blockIdx.z;
    A  += (size_t)bz * sA;
    Bm += (size_t)bz * sB;
    C  += (size_t)bz * sC;

    const int m0 = blockIdx.y * BM;
    const int n0 = blockIdx.x * BN;

    __shared__ float As[BK][BM + 4];
    __shared__ float Bs[BK][BN + 4];

    const int t  = threadIdx.x;
    const int tx = t & 15;
    const int ty = t >> 4;

    float acc[4][4] = {};

    const int arow = t >> 2;
    const int akc  = (t & 3) * 4;
    const int kb   = t >> 4;
    const int nb   = (t & 15) * 4;

    for (int k0 = 0; k0 < K; k0 += BK) {
        float4 av = *(const float4*)&A[(size_t)(m0 + arow) * K + k0 + akc];
        As[akc + 0][arow] = av.x;
        As[akc + 1][arow] = av.y;
        As[akc + 2][arow] = av.z;
        As[akc + 3][arow] = av.w;

        if (!transB) {
            float4 bv = *(const float4*)&Bm[(size_t)(k0 + kb) * N + n0 + nb];
            *(float4*)&Bs[kb][nb] = bv;
        } else {
            float4 bv = *(const float4*)&Bm[(size_t)(n0 + arow) * K + k0 + akc];
            Bs[akc + 0][arow] = bv.x;
            Bs[akc + 1][arow] = bv.y;
            Bs[akc + 2][arow] = bv.z;
            Bs[akc + 3][arow] = bv.w;
        }
        __syncthreads();

#pragma unroll
        for (int k = 0; k < BK; k++) {
            float4 a = *(const float4*)&As[k][ty * 4];
            float4 b = *(const float4*)&Bs[k][tx * 4];
            acc[0][0] += a.x * b.x; acc[0][1] += a.x * b.y;
            acc[0][2] += a.x * b.z; acc[0][3] += a.x * b.w;
            acc[1][0] += a.y * b.x; acc[1][1] += a.y * b.y;
            acc[1][2] += a.y * b.z; acc[1][3] += a.y * b.w;
            acc[2][0] += a.z * b.x; acc[2][1] += a.z * b.y;
            acc[2][2] += a.z * b.z; acc[2][3] += a.z * b.w;
            acc[3][0] += a.w * b.x; acc[3][1] += a.w * b.y;
            acc[3][2] += a.w * b.z; acc[3][3] += a.w * b.w;
        }
        __syncthreads();
    }

#pragma unroll
    for (int i = 0; i < 4; i++) {
        const int row = m0 + ty * 4 + i;
        float v[4];
#pragma unroll
        for (int j = 0; j < 4; j++) {
            float x = acc[i][j] * alpha;
            if (bias) x += bias[n0 + tx * 4 + j];
            v[j] = x;
        }
        *(float4*)&C[(size_t)row * N + n0 + tx * 4] = make_float4(v[0], v[1], v[2], v[3]);
    }
}

static void sgemm_launch(const float* A, const float* B, const float* bias, float* C,
                         int M, int N, int K, int batch,
                         long long sA, long long sB, long long sC,
                         float alpha, int transB, cudaStream_t st)
{
    dim3 grid(N / BN, M / BM, batch);
    gemm_kernel<<<grid, 256, 0, st>>>(A, B, bias, C, M, N, K, sA, sB, sC, alpha, transB, 0);
}

// ---------------------------------------------------------------------------
// Encoder (stream + buffer views). QKV 1-term; Wo/FF 3-term.
// ---------------------------------------------------------------------------
static void run_encoder(const float* Xin0, float* X, int nb,
                        const __half* initHi,
                        const float* biasRows, const __half* PW,
                        const float* bqkv, const float* bo,
                        const float* ln, const float* bff,
                        float* bV, float* bK, __half* Sh,
                        __half* Pq, __half* Pk, __half* Pvt,
                        __half* Pp, __half* Pbq, __half* Ph,
                        __half* Px, long long lo, cudaStream_t st)
{
    const int rows = nb * SS;
    const float sc = 1.0f / sqrtf((float)DD);
    for (int l = 0; l < 2; l++) {
        const __half* AP = (l == 0) ? initHi : Px;
        tg1(AP, 0, PW + (size_t)(l * 3) * 262144, 0,
            bqkv + (size_t)l * 1536, bV, 0, Pq, Pk, 0, 0,
            rows, 1536, 512, 1, 1.0f, 2, st);
        trans_conv<<<dim3(16, 32, nb), dim3(32, 8), 0, st>>>(bV, Pvt, 0, 1024, 512,
                                                             524288, 524288, nullptr);
        tg1(Pq, 524288, Pk, 524288, nullptr, nullptr, 0, Sh, nullptr, 0, 1048576,
            1024, 1024, 512, nb, sc, 0, st);
        softmax1024_planes<<<rows, 256, 0, st>>>(Sh, biasRows, Pp);
        tg1(Pp, 1048576, Pvt, 524288, nullptr, nullptr, 0, Pbq, nullptr, lo, 524288,
            1024, 512, 1024, nb, 1.0f, 0, st);
        tg3(Pbq, lo, 0, PW + (size_t)(6 + l) * 262144, WLO, 0, bo + l * 512,
            bK, 0, nullptr, 0, 0, rows, 512, 512, 1, 1.0f, 0, st);
        ln_kernel<<<rows, 256, 0, st>>>((l == 0) ? Xin0 : X, bK,
                                        ln + l * 2048, ln + l * 2048 + 512, X, Px, lo);
        tg3(Px, lo, 0, PW + (size_t)(8 + 2 * l) * 262144, WLO, 0, bff + l * 1024,
            nullptr, 0, Ph, lo, 0, rows, 512, 512, 1, 1.0f, 1, st);
        tg3(Ph, lo, 0, PW + (size_t)(9 + 2 * l) * 262144, WLO, 0, bff + l * 1024 + 512,
            bK, 0, nullptr, 0, 0, rows, 512, 512, 1, 1.0f, 0, st);
        ln_kernel<<<rows, 256, 0, st>>>(X, bK, ln + l * 2048 + 1024, ln + l * 2048 + 1536,
                                        X, Px, lo);
    }
}

extern "C" void kernel_launch(void* const* d_in, const int* in_sizes, int n_in,
                              void* d_out, int out_size)
{
    const float* raw_emb   = (const float*)d_in[0];
    const float* pos_w     = (const float*)d_in[1];
    const float* post_dec  = (const float*)d_in[2];
    const float* pos_r     = (const float*)d_in[3];
    const float* questions = (const float*)d_in[4];
    const float* W_k       = (const float*)d_in[5];
    const float* W_ig      = (const float*)d_in[6];
    const float* b_ig      = (const float*)d_in[7];
    const float* W_u1      = (const float*)d_in[8];
    const float* b_u1      = (const float*)d_in[9];
    const float* W_u2      = (const float*)d_in[10];
    const float* b_u2      = (const float*)d_in[11];
    const float* b1        = (const float*)d_in[12];
    const float* W_ok      = (const float*)d_in[13];
    const float* b_ok      = (const float*)d_in[14];
    const float* encw_Wqkv = (const float*)d_in[15];
    const float* encw_bqkv = (const float*)d_in[16];
    const float* encw_Wo   = (const float*)d_in[17];
    const float* encw_bo   = (const float*)d_in[18];
    const float* encw_ln   = (const float*)d_in[19];
    const float* encw_Wff  = (const float*)d_in[20];
    const float* encw_bff  = (const float*)d_in[21];
    const float* encr_Wqkv = (const float*)d_in[22];
    const float* encr_bqkv = (const float*)d_in[23];
    const float* encr_Wo   = (const float*)d_in[24];
    const float* encr_bo   = (const float*)d_in[25];
    const float* encr_ln   = (const float*)d_in[26];
    const float* encr_Wff  = (const float*)d_in[27];
    const float* encr_bff  = (const float*)d_in[28];
    const int*   lookup    = (const int*)d_in[29];

    float* out  = (float*)d_out;
    float* gate = out + (size_t)NBB * SS * DD;

    float *pX, *pV, *pK, *pXw, *pVw, *pKw, *pS1, *pKd, *pVd, *pA1, *pA2s, *pA2, *pBW, *pBR;
    __half *pPW, *pPraw, *pPpd, *pPx, *pPq, *pPk, *pPvt, *pPp, *pPbq, *pPh, *pSh;
    __half *pPxw, *pPqw, *pPkw, *pPvtw, *pPpw, *pPbqw, *pPhw, *pShw;
    __half *pPk2, *pPa2, *pPsel, *pPqst;
    cudaGetSymbolAddress((void**)&pX,    g_X);
    cudaGetSymbolAddress((void**)&pV,    g_V);
    cudaGetSymbolAddress((void**)&pK,    g_Kb);
    cudaGetSymbolAddress((void**)&pXw,   g_Xw);
    cudaGetSymbolAddress((void**)&pVw,   g_Vw);
    cudaGetSymbolAddress((void**)&pKw,   g_Kw);
    cudaGetSymbolAddress((void**)&pS1,   g_S1);
    cudaGetSymbolAddress((void**)&pKd,   g_Kdoc);
    cudaGetSymbolAddress((void**)&pVd,   g_Vdoc);
    cudaGetSymbolAddress((void**)&pA1,   g_A1S);
    cudaGetSymbolAddress((void**)&pA2s,  g_A2SC);
    cudaGetSymbolAddress((void**)&pA2,   g_A2);
    cudaGetSymbolAddress((void**)&pBW,   g_BIASW);
    cudaGetSymbolAddress((void**)&pBR,   g_BIASR);
    cudaGetSymbolAddress((void**)&pPW,   g_PW);
    cudaGetSymbolAddress((void**)&pPraw, g_Praw);
    cudaGetSymbolAddress((void**)&pPpd,  g_Ppd);
    cudaGetSymbolAddress((void**)&pPx,   g_Px);
    cudaGetSymbolAddress((void**)&pPq,   g_Pq);
    cudaGetSymbolAddress((void**)&pPk,   g_Pk);
    cudaGetSymbolAddress((void**)&pPvt,  g_Pvt);
    cudaGetSymbolAddress((void**)&pPp,   g_Pp);
    cudaGetSymbolAddress((void**)&pPbq,  g_Pbq);
    cudaGetSymbolAddress((void**)&pPh,   g_Ph);
    cudaGetSymbolAddress((void**)&pSh,   g_Sh);
    cudaGetSymbolAddress((void**)&pPxw,  g_Pxw);
    cudaGetSymbolAddress((void**)&pPqw,  g_Pqw);
    cudaGetSymbolAddress((void**)&pPkw,  g_Pkw);
    cudaGetSymbolAddress((void**)&pPvtw, g_Pvtw);
    cudaGetSymbolAddress((void**)&pPpw,  g_Ppw);
    cudaGetSymbolAddress((void**)&pPbqw, g_Pbqw);
    cudaGetSymbolAddress((void**)&pPhw,  g_Phw);
    cudaGetSymbolAddress((void**)&pShw,  g_Shw);
    cudaGetSymbolAddress((void**)&pPk2,  g_Pk2);
    cudaGetSymbolAddress((void**)&pPa2,  g_Pa2);
    cudaGetSymbolAddress((void**)&pPsel, g_Psel);
    cudaGetSymbolAddress((void**)&pPqst, g_Pqst);

    cudaFuncSetAttribute(tgemm3,    cudaFuncAttributeMaxDynamicSharedMemorySize, TG_SMEM);
    cudaFuncSetAttribute(tgemm1,    cudaFuncAttributeMaxDynamicSharedMemorySize, T1_SMEM);
    cudaFuncSetAttribute(tgemm1n64, cudaFuncAttributeMaxDynamicSharedMemorySize, T1N_SMEM);

    const float scD = 1.0f / sqrtf((float)DD);
    const long long HB = 4194304LL;   // half offset: 8192 rows x 512

    cudaStream_t s2;
    cudaStreamCreateWithFlags(&s2, cudaStreamNonBlocking);
    cudaEvent_t evF, evJ;
    cudaEventCreateWithFlags(&evF, cudaEventDisableTiming);
    cudaEventCreateWithFlags(&evJ, cudaEventDisableTiming);
    cudaStream_t s0 = 0;

    // ---- common prep on s0 (needed by both streams) ----
    rope_table_kernel<<<1024, 256, 0, s0>>>();
    conv_planes<<<NBB * SS, 256, 0, s0>>>(post_dec, pPpd, 0);
    trans_conv<<<dim3(16, 16, 6), dim3(32, 8), 0, s0>>>(encr_Wqkv, pPW + 12LL * 262144, WLO, 512, 512, 262144, 262144, nullptr);
    trans_conv<<<dim3(16, 16, 2), dim3(32, 8), 0, s0>>>(encr_Wo,   pPW + 18LL * 262144, WLO, 512, 512, 262144, 262144, nullptr);
    trans_conv<<<dim3(16, 16, 4), dim3(32, 8), 0, s0>>>(encr_Wff,  pPW + 20LL * 262144, WLO, 512, 512, 262144, 262144, nullptr);
    bias_prep<<<NBB, 256, 0, s0>>>(pos_r, pBR, 2);

    cudaEventRecord(evF, s0);
    cudaStreamWaitEvent(s2, evF, 0);

    // ================= s2: write side + k2/a2 + read half-2 ================
    trans_conv<<<dim3(16, 16, 6), dim3(32, 8), 0, s2>>>(encw_Wqkv, pPW + 0LL * 262144, WLO, 512, 512, 262144, 262144, nullptr);
    trans_conv<<<dim3(16, 16, 2), dim3(32, 8), 0, s2>>>(encw_Wo,   pPW + 6LL * 262144, WLO, 512, 512, 262144, 262144, nullptr);
    trans_conv<<<dim3(16, 16, 4), dim3(32, 8), 0, s2>>>(encw_Wff,  pPW + 8LL * 262144, WLO, 512, 512, 262144, 262144, nullptr);
    conv_planes<<<NDOC * SS, 256, 0, s2>>>(raw_emb, pPraw, 0);
    bias_prep<<<NDOC, 256, 0, s2>>>(pos_w, pBW, 1);

    run_encoder(raw_emb, pXw, NDOC, pPraw, pBW,
                pPW, encw_bqkv, encw_bo, encw_ln, encw_bff,
                pVw, pKw, pShw, pPqw, pPkw, pPvtw, pPpw, pPbqw, pPhw, pPxw,
                LOW, s2);

    vgate_kernel<<<NDOC * SS, 256, 0, s2>>>(pXw, raw_emb, W_ig, b_ig, pVd);
    trans_conv<<<dim3(16, 16, 1), dim3(32, 8), 0, s2>>>(W_k, pPW + 24LL * 262144, WLO, 512, 512, 262144, 262144, nullptr);
    tg1(pPraw, 0, pPW + 24LL * 262144, 0, nullptr, pKd, 0, nullptr, nullptr, 0, 0,
        NDOC * SS, 512, 512, 1, 1.0f, 0, s2);
    sgemm_launch(questions, pKd, nullptr, pS1, QQ, SS, DD, NDOC, 0, 524288, 65536, scD, 1, s2);
    softmax_f32<<<NDOC * QQ, 256, 0, s2>>>(pS1, pBW, SS, QQ);
    sgemm_launch(pS1, pVd, nullptr, pA1, QQ, DD, SS, NDOC, 65536, 524288, 32768, 1.0f, 0, s2);
    trans_conv<<<dim3(16, 2, 16), dim3(32, 8), 0, s2>>>(pA1, pPsel, 0, 64, 512, 32768, 32768, lookup);

    // independent k2/a2/A2 chain
    trans_conv<<<dim3(16, 16, 1), dim3(32, 8), 0, s2>>>(W_ok, pPW + 25LL * 262144, WLO, 512, 512, 262144, 262144, nullptr);
    conv_planes<<<QQ, 256, 0, s2>>>(questions, pPqst, 0);
    tg1(pPpd, 0, pPW + 25LL * 262144, 0, b_ok, nullptr, 0, pPk2, nullptr, 0, 0,
        NBB * SS, 512, 512, 1, 1.0f, 0, s2);
    {
        dim3 grid(1, (NBB * SS) / 128, 1);
        tgemm1n64<<<grid, 256, T1N_SMEM, s2>>>(pPk2, pPqst, pA2s, NBB * SS, QQ, DD, 0.125f);
    }
    softmax64_planes<<<NBB * SS / 8, 256, 0, s2>>>(pA2s, pPa2);
    tg1(pPa2, 65536, pPsel, 32768, nullptr, pA2, 524288, nullptr, nullptr, 0, 0,
        1024, 512, 64, NBB, 1.0f, 0, s2);

    // read-side encoder, batches 8..15 (offset views into read buffers)
    run_encoder(post_dec + HB, pX + HB, NBB / 2, pPpd + HB, pBR + 8 * 1024,
                pPW + 12LL * 262144, encr_bqkv, encr_bo, encr_ln, encr_bff,
                pV + HB, pK + HB, pSh + 8LL * 1048576,
                pPq + HB, pPk + HB, pPvt + HB,
                pPp + 8388608LL, pPbq + HB, pPh + HB, pPx + HB,
                LO, s2);

    cudaEventRecord(evJ, s2);

    // ================= s0: read-side encoder, batches 0..7 =================
    run_encoder(post_dec, pX, NBB / 2, pPpd, pBR,
                pPW + 12LL * 262144, encr_bqkv, encr_bo, encr_ln, encr_bff,
                pV, pK, pSh, pPq, pPk, pPvt, pPp, pPbq, pPh, pPx,
                LO, s0);

    // join + final
    cudaStreamWaitEvent(s0, evJ, 0);
    out_kernel<<<NBB * SS, 256, 0, s0>>>(pX, pA2, post_dec,
                                         W_u1, b_u1, W_u2, b_u2, b1,
                                         out, gate);

    (void)in_sizes; (void)n_in; (void)out_size;
}

// round 13
// speedup vs baseline: 1.0146x; 1.0146x over previous
#include <cuda_runtime.h>
#include <cuda_fp16.h>
#include <math.h>
#include <stdint.h>

#define DD     512
#define SS     1024
#define NBB    16
#define QQ     64
#define NDOC   8

// ---- read-side f32 scratch (full 16 batches; s2 uses +12-batch views) ----
__device__ float g_X   [16384 * 512];
__device__ float g_V   [16384 * 512];
__device__ float g_Kb  [16384 * 512];
// ---- write-side f32 scratch ----
__device__ float g_Xw  [8192 * 512];
__device__ float g_Vw  [8192 * 512];
__device__ float g_Kw  [8192 * 512];
__device__ float g_S1  [8 * 64 * 1024];
__device__ float g_Kdoc[8192 * 512];
__device__ float g_Vdoc[8192 * 512];
__device__ float g_A1S [8 * 64 * 512];
__device__ float g_A2SC[16384 * 64];
__device__ float g_A2  [16384 * 512];
__device__ float g_sin [1024 * 256];
__device__ float g_cos [1024 * 256];
__device__ float g_BIASW[8 * 1024];
__device__ float g_BIASR[16 * 1024];

#define WLO 6815744LL
#define LO  8388608LL
#define LOW 4194304LL
__device__ __align__(16) __half g_PW  [2 * 26 * 262144];
__device__ __align__(16) __half g_Praw[4194304];
__device__ __align__(16) __half g_Ppd [8388608];
// read-side planes
__device__ __align__(16) __half g_Px  [2 * 8388608];
__device__ __align__(16) __half g_Pq  [8388608];
__device__ __align__(16) __half g_Pk  [8388608];
__device__ __align__(16) __half g_Pvt [8388608];
__device__ __align__(16) __half g_Pp  [16777216];
__device__ __align__(16) __half g_Pbq [2 * 8388608];
__device__ __align__(16) __half g_Ph  [2 * 8388608];
__device__ __align__(16) __half g_Sh  [16 * 1048576];
// write-side planes
__device__ __align__(16) __half g_Pxw [2 * 4194304];
__device__ __align__(16) __half g_Pqw [4194304];
__device__ __align__(16) __half g_Pkw [4194304];
__device__ __align__(16) __half g_Pvtw[4194304];
__device__ __align__(16) __half g_Ppw [8388608];
__device__ __align__(16) __half g_Pbqw[2 * 4194304];
__device__ __align__(16) __half g_Phw [2 * 4194304];
__device__ __align__(16) __half g_Shw [8 * 1048576];
// misc planes
__device__ __align__(16) __half g_Pk2 [8388608];
__device__ __align__(16) __half g_Pa2 [1048576];
__device__ __align__(16) __half g_Psel[524288];
__device__ __align__(16) __half g_Pqst[32768];

__device__ __forceinline__ uint32_t smem_u32(const void* p) {
    uint32_t a;
    asm("{ .reg .u64 t; cvta.to.shared.u64 t, %1; cvt.u32.u64 %0, t; }"
        : "=r"(a) : "l"(p));
    return a;
}

__device__ __forceinline__ void ldsm4(uint32_t* r, uint32_t addr) {
    asm volatile("ldmatrix.sync.aligned.m8n8.x4.shared.b16 {%0,%1,%2,%3}, [%4];"
                 : "=r"(r[0]), "=r"(r[1]), "=r"(r[2]), "=r"(r[3]) : "r"(addr));
}

__device__ __forceinline__ void mma_f16(float* c, const uint32_t* a,
                                        uint32_t b0, uint32_t b1) {
    asm volatile(
        "mma.sync.aligned.m16n8k16.row.col.f32.f16.f16.f32 "
        "{%0,%1,%2,%3}, {%4,%5,%6,%7}, {%8,%9}, {%0,%1,%2,%3};"
        : "+f"(c[0]), "+f"(c[1]), "+f"(c[2]), "+f"(c[3])
        : "r"(a[0]), "r"(a[1]), "r"(a[2]), "r"(a[3]), "r"(b0), "r"(b1));
}

__device__ __forceinline__ void cpasync16(uint32_t dst, const void* src) {
    asm volatile("cp.async.cg.shared.global [%0], [%1], 16;" :: "r"(dst), "l"(src));
}
#define CP_COMMIT() asm volatile("cp.async.commit_group;" ::: "memory")
#define CP_WAIT(n)  asm volatile("cp.async.wait_group %0;" :: "n"(n) : "memory")

__device__ __forceinline__ void split_pair(float x0, float x1,
                                           __half2& h, __half2& l) {
    h = __floats2half2_rn(x0, x1);
    l = __floats2half2_rn(x0 - __low2float(h), x1 - __high2float(h));
}

// ---------------------------------------------------------------------------
// 3-term split GEMM (fp16 planes): residual-path GEMMs (Wo, FF)
// ---------------------------------------------------------------------------
#define PLANE  10240
#define TSTAGE 40960
#define TG_SMEM (4 * 40960)

__global__ void __launch_bounds__(512)
tgemm3(const __half* __restrict__ Ah0, const __half* __restrict__ Bh0,
       const float* __restrict__ bias, float* __restrict__ Cf,
       __half* __restrict__ Ch0,
       int M, int N, int K,
       long long loA, long long loB, long long loC,
       long long sA, long long sB, long long sC, long long sCp,
       float alpha, int epi)
{
    extern __shared__ char smem[];
    const uint32_t sbu = smem_u32(smem);
    const int t = threadIdx.x, w = t >> 5, lane = t & 31;
    const int wm = w & 3, wn = w >> 2;
    const int z = blockIdx.z;
    const int m0 = blockIdx.y * 128, n0 = blockIdx.x * 128;

    const __half* Ah = Ah0 + (size_t)z * sA;
    const __half* Bh = Bh0 + (size_t)z * sB;

    const int lrow = t >> 2, seg = t & 3;
    const __half* pr[4];
    pr[0] = Ah + (size_t)(m0 + lrow) * K + seg * 8;
    pr[1] = pr[0] + loA;
    pr[2] = Bh + (size_t)(n0 + lrow) * K + seg * 8;
    pr[3] = pr[2] + loB;

    float acc[2][4][4];
#pragma unroll
    for (int i = 0; i < 2; i++)
#pragma unroll
        for (int j = 0; j < 4; j++)
#pragma unroll
            for (int e = 0; e < 4; e++) acc[i][j][e] = 0.0f;

    const int nch = K >> 5;
    const uint32_t sdbase = sbu + (uint32_t)(lrow * 80 + seg * 16);

#define ISSUE(ch) do {                                                      \
    uint32_t _sd = sdbase + (uint32_t)((ch) & 3) * TSTAGE;                  \
    const int _cb = (ch) * 32;                                              \
    _Pragma("unroll")                                                       \
    for (int _p = 0; _p < 4; _p++)                                          \
        cpasync16(_sd + _p * PLANE, pr[_p] + _cb);                          \
    CP_COMMIT();                                                            \
} while (0)

    ISSUE(0);
    ISSUE(1);
    if (nch > 2) ISSUE(2);

    const uint32_t lmoff = (uint32_t)((lane & 15) * 80 + (lane >> 4) * 16);

    for (int ch = 0; ch < nch; ch++) {
        const int rem = nch - 1 - ch;
        if (rem >= 2)      { CP_WAIT(2); }
        else if (rem == 1) { CP_WAIT(1); }
        else               { CP_WAIT(0); }
        __syncthreads();
        if (ch + 3 < nch) ISSUE(ch + 3);

        const uint32_t sAh = sbu + (uint32_t)(ch & 3) * TSTAGE;
        const uint32_t sBh = sAh + 2 * PLANE;
#pragma unroll
        for (int kk = 0; kk < 2; kk++) {
            uint32_t ah[2][4], al[2][4], bh[2][4], bl[2][4];
#pragma unroll
            for (int mt = 0; mt < 2; mt++) {
                uint32_t aaddr = sAh + (uint32_t)((wm * 32 + mt * 16) * 80 + kk * 32) + lmoff;
                ldsm4(ah[mt], aaddr);
                ldsm4(al[mt], aaddr + PLANE);
            }
#pragma unroll
            for (int ng = 0; ng < 2; ng++) {
                uint32_t baddr = sBh + (uint32_t)((wn * 32 + ng * 16) * 80 + kk * 32) + lmoff;
                ldsm4(bh[ng], baddr);
                ldsm4(bl[ng], baddr + PLANE);
            }
#pragma unroll
            for (int ng = 0; ng < 2; ng++)
#pragma unroll
                for (int mt = 0; mt < 2; mt++)
#pragma unroll
                    for (int h2 = 0; h2 < 2; h2++)
                        mma_f16(acc[mt][ng * 2 + h2], ah[mt], bh[ng][h2], bh[ng][h2 + 2]);
#pragma unroll
            for (int ng = 0; ng < 2; ng++)
#pragma unroll
                for (int mt = 0; mt < 2; mt++)
#pragma unroll
                    for (int h2 = 0; h2 < 2; h2++)
                        mma_f16(acc[mt][ng * 2 + h2], ah[mt], bl[ng][h2], bl[ng][h2 + 2]);
#pragma unroll
            for (int ng = 0; ng < 2; ng++)
#pragma unroll
                for (int mt = 0; mt < 2; mt++)
#pragma unroll
                    for (int h2 = 0; h2 < 2; h2++)
                        mma_f16(acc[mt][ng * 2 + h2], al[mt], bh[ng][h2], bh[ng][h2 + 2]);
        }
    }
#undef ISSUE

    const float GC = 0.7978845608028654f;
    const int crow = m0 + wm * 32 + (lane >> 2);
    const int ccol = n0 + wn * 32 + (lane & 3) * 2;

    float* Cfz = Cf ? Cf + (size_t)z * sC : (float*)0;
    __half* Chz = Ch0 ? Ch0 + (size_t)z * sCp : (__half*)0;
    __half* Clz = Chz ? Chz + loC : (__half*)0;
#pragma unroll
    for (int mt = 0; mt < 2; mt++) {
#pragma unroll
        for (int n8 = 0; n8 < 4; n8++) {
            const float* c = acc[mt][n8];
            const int col = ccol + n8 * 8;
            float b0 = bias ? bias[col]     : 0.0f;
            float b1 = bias ? bias[col + 1] : 0.0f;
#pragma unroll
            for (int h = 0; h < 2; h++) {
                const int row = crow + mt * 16 + h * 8;
                float x0 = c[h * 2 + 0] * alpha + b0;
                float x1 = c[h * 2 + 1] * alpha + b1;
                if (epi == 1) {
                    x0 = 0.5f * x0 * (1.0f + tanhf(GC * (x0 + 0.044715f * x0 * x0 * x0)));
                    x1 = 0.5f * x1 * (1.0f + tanhf(GC * (x1 + 0.044715f * x1 * x1 * x1)));
                }
                if (Cfz)
                    *(float2*)&Cfz[(size_t)row * N + col] = make_float2(x0, x1);
                if (Chz) {
                    __half2 hh, ll;
                    split_pair(x0, x1, hh, ll);
                    *(__half2*)&Chz[(size_t)row * N + col] = hh;
                    *(__half2*)&Clz[(size_t)row * N + col] = ll;
                }
            }
        }
    }
}

static void tg3(const __half* Ah, long long loA, long long sA,
                const __half* Bh, long long loB, long long sB,
                const float* bias, float* Cf, long long sC,
                __half* Ch, long long loC, long long sCp,
                int M, int N, int K, int batch, float alpha, int epi,
                cudaStream_t st)
{
    dim3 grid(N / 128, M / 128, batch);
    tgemm3<<<grid, 512, TG_SMEM, st>>>(Ah, Bh, bias, Cf, Ch, M, N, K,
                                       loA, loB, loC, sA, sB, sC, sCp, alpha, epi);
}

// ---------------------------------------------------------------------------
// 1-term GEMM (hi planes only). epi: 0 = plain, 2 = QKV rope epilogue
// ---------------------------------------------------------------------------
#define T1STAGE 20480
#define T1_SMEM (4 * 20480)

__global__ void __launch_bounds__(512)
tgemm1(const __half* __restrict__ Ah0, const __half* __restrict__ Bh0,
       const float* __restrict__ bias, float* __restrict__ Cf,
       __half* __restrict__ Ch0, __half* __restrict__ Ch2,
       int M, int N, int K, long long loC,
       long long sA, long long sB, long long sC, long long sCp,
       float alpha, int epi)
{
    extern __shared__ char smem[];
    const uint32_t sbu = smem_u32(smem);
    const int t = threadIdx.x, w = t >> 5, lane = t & 31;
    const int wm = w & 3, wn = w >> 2;
    const int z = blockIdx.z;
    const int m0 = blockIdx.y * 128, n0 = blockIdx.x * 128;

    const __half* Ap = Ah0 + (size_t)z * sA + (size_t)(m0 + (t >> 2)) * K + (t & 3) * 8;
    const __half* Bp = Bh0 + (size_t)z * sB + (size_t)(n0 + (t >> 2)) * K + (t & 3) * 8;

    float acc[2][4][4];
#pragma unroll
    for (int i = 0; i < 2; i++)
#pragma unroll
        for (int j = 0; j < 4; j++)
#pragma unroll
            for (int e = 0; e < 4; e++) acc[i][j][e] = 0.0f;

    const int nch = K >> 5;
    const uint32_t sdbase = sbu + (uint32_t)((t >> 2) * 80 + (t & 3) * 16);

#define ISSUE1(ch) do {                                                     \
    uint32_t _sd = sdbase + (uint32_t)((ch) & 3) * T1STAGE;                 \
    const int _cb = (ch) * 32;                                              \
    cpasync16(_sd,         Ap + _cb);                                       \
    cpasync16(_sd + PLANE, Bp + _cb);                                       \
    CP_COMMIT();                                                            \
} while (0)

    ISSUE1(0);
    ISSUE1(1);
    if (nch > 2) ISSUE1(2);

    const uint32_t lmoff = (uint32_t)((lane & 15) * 80 + (lane >> 4) * 16);

    for (int ch = 0; ch < nch; ch++) {
        const int rem = nch - 1 - ch;
        if (rem >= 2)      { CP_WAIT(2); }
        else if (rem == 1) { CP_WAIT(1); }
        else               { CP_WAIT(0); }
        __syncthreads();
        if (ch + 3 < nch) ISSUE1(ch + 3);

        const uint32_t sAh = sbu + (uint32_t)(ch & 3) * T1STAGE;
        const uint32_t sBh = sAh + PLANE;
#pragma unroll
        for (int kk = 0; kk < 2; kk++) {
            uint32_t ah[2][4], bh[2][4];
#pragma unroll
            for (int mt = 0; mt < 2; mt++)
                ldsm4(ah[mt], sAh + (uint32_t)((wm * 32 + mt * 16) * 80 + kk * 32) + lmoff);
#pragma unroll
            for (int ng = 0; ng < 2; ng++)
                ldsm4(bh[ng], sBh + (uint32_t)((wn * 32 + ng * 16) * 80 + kk * 32) + lmoff);
#pragma unroll
            for (int ng = 0; ng < 2; ng++)
#pragma unroll
                for (int mt = 0; mt < 2; mt++)
#pragma unroll
                    for (int h2 = 0; h2 < 2; h2++)
                        mma_f16(acc[mt][ng * 2 + h2], ah[mt], bh[ng][h2], bh[ng][h2 + 2]);
        }
    }
#undef ISSUE1

    const int crow = m0 + wm * 32 + (lane >> 2);
    const int ccol = n0 + wn * 32 + (lane & 3) * 2;

    if (epi == 2) {
#pragma unroll
        for (int mt = 0; mt < 2; mt++) {
#pragma unroll
            for (int n8 = 0; n8 < 4; n8++) {
                const float* c = acc[mt][n8];
                const int col = ccol + n8 * 8;
                float b0 = bias[col], b1 = bias[col + 1];
#pragma unroll
                for (int h = 0; h < 2; h++) {
                    const int row = crow + mt * 16 + h * 8;
                    float x0 = c[h * 2 + 0] + b0;
                    float x1 = c[h * 2 + 1] + b1;
                    if (col < 1024) {
                        const int s = row & (SS - 1);
                        const int i = (col & 511) >> 1;
                        float sn = g_sin[s * 256 + i];
                        float cs = g_cos[s * 256 + i];
                        float y0 = x0 * cs - x1 * sn;
                        float y1 = x0 * sn + x1 * cs;
                        __half* dst = (col < 512) ? Ch0 : Ch2;
                        size_t off = (size_t)row * 512 + (col & 511);
                        *(__half2*)&dst[off] = __floats2half2_rn(y0, y1);
                    } else {
                        *(float2*)&Cf[(size_t)row * 512 + (col - 1024)] =
                            make_float2(x0, x1);
                    }
                }
            }
        }
        return;
    }

    float* Cfz = Cf ? Cf + (size_t)z * sC : (float*)0;
    __half* Chz = Ch0 ? Ch0 + (size_t)z * sCp : (__half*)0;
    __half* Clz = (Chz && loC) ? Chz + loC : (__half*)0;
#pragma unroll
    for (int mt = 0; mt < 2; mt++) {
#pragma unroll
        for (int n8 = 0; n8 < 4; n8++) {
            const float* c = acc[mt][n8];
            const int col = ccol + n8 * 8;
            float b0 = bias ? bias[col]     : 0.0f;
            float b1 = bias ? bias[col + 1] : 0.0f;
#pragma unroll
            for (int h = 0; h < 2; h++) {
                const int row = crow + mt * 16 + h * 8;
                float x0 = c[h * 2 + 0] * alpha + b0;
                float x1 = c[h * 2 + 1] * alpha + b1;
                if (Cfz)
                    *(float2*)&Cfz[(size_t)row * N + col] = make_float2(x0, x1);
                if (Chz) {
                    __half2 hh, ll;
                    split_pair(x0, x1, hh, ll);
                    *(__half2*)&Chz[(size_t)row * N + col] = hh;
                    if (Clz) *(__half2*)&Clz[(size_t)row * N + col] = ll;
                }
            }
        }
    }
}

static void tg1(const __half* Ah, long long sA, const __half* Bh, long long sB,
                const float* bias, float* Cf, long long sC,
                __half* Ch, __half* Ch2, long long loC, long long sCp,
                int M, int N, int K, int batch, float alpha, int epi,
                cudaStream_t st)
{
    dim3 grid(N / 128, M / 128, batch);
    tgemm1<<<grid, 512, T1_SMEM, st>>>(Ah, Bh, bias, Cf, Ch, Ch2, M, N, K, loC,
                                       sA, sB, sC, sCp, alpha, epi);
}

// 1-term, N-tile 64
#define B1STAGE 15360
#define T1N_SMEM (4 * 15360)

__global__ void __launch_bounds__(256)
tgemm1n64(const __half* __restrict__ Ah0, const __half* __restrict__ Bh0,
          float* __restrict__ Cf, int M, int N, int K, float alpha)
{
    extern __shared__ char smem[];
    const uint32_t sbu = smem_u32(smem);
    const int t = threadIdx.x, w = t >> 5, lane = t & 31;
    const int wm = w & 3, wn = w >> 2;
    const int m0 = blockIdx.y * 128, n0 = blockIdx.x * 64;

    const int arow = t >> 1, aseg = (t & 1) * 2;
    const int brow = t >> 2, bseg = t & 3;
    const __half* pa = Ah0 + (size_t)(m0 + arow) * K + aseg * 8;
    const __half* pb = Bh0 + (size_t)(n0 + brow) * K + bseg * 8;
    const uint32_t adst = sbu + (uint32_t)(arow * 80 + aseg * 16);
    const uint32_t bdst = sbu + 10240u + (uint32_t)(brow * 80 + bseg * 16);

    float acc[2][4][4];
#pragma unroll
    for (int i = 0; i < 2; i++)
#pragma unroll
        for (int j = 0; j < 4; j++)
#pragma unroll
            for (int e = 0; e < 4; e++) acc[i][j][e] = 0.0f;

    const int nch = K >> 5;

#define ISSUEN(ch) do {                                                     \
    uint32_t _st = (uint32_t)((ch) & 3) * B1STAGE;                          \
    const int _cb = (ch) * 32;                                              \
    cpasync16(adst + _st,      pa + _cb);                                   \
    cpasync16(adst + _st + 16, pa + _cb + 8);                               \
    cpasync16(bdst + _st,      pb + _cb);                                   \
    CP_COMMIT();                                                            \
} while (0)

    ISSUEN(0);
    ISSUEN(1);
    if (nch > 2) ISSUEN(2);

    const uint32_t lmoff = (uint32_t)((lane & 15) * 80 + (lane >> 4) * 16);

    for (int ch = 0; ch < nch; ch++) {
        const int rem = nch - 1 - ch;
        if (rem >= 2)      { CP_WAIT(2); }
        else if (rem == 1) { CP_WAIT(1); }
        else               { CP_WAIT(0); }
        __syncthreads();
        if (ch + 3 < nch) ISSUEN(ch + 3);

        const uint32_t sAh = sbu + (uint32_t)(ch & 3) * B1STAGE;
        const uint32_t sBh = sAh + 10240u;
#pragma unroll
        for (int kk = 0; kk < 2; kk++) {
            uint32_t ah[2][4], bh[2][4];
#pragma unroll
            for (int mt = 0; mt < 2; mt++)
                ldsm4(ah[mt], sAh + (uint32_t)((wm * 32 + mt * 16) * 80 + kk * 32) + lmoff);
#pragma unroll
            for (int ng = 0; ng < 2; ng++)
                ldsm4(bh[ng], sBh + (uint32_t)((wn * 32 + ng * 16) * 80 + kk * 32) + lmoff);
#pragma unroll
            for (int ng = 0; ng < 2; ng++)
#pragma unroll
                for (int mt = 0; mt < 2; mt++)
#pragma unroll
                    for (int h2 = 0; h2 < 2; h2++)
                        mma_f16(acc[mt][ng * 2 + h2], ah[mt], bh[ng][h2], bh[ng][h2 + 2]);
        }
    }
#undef ISSUEN

    const int crow = m0 + wm * 32 + (lane >> 2);
    const int ccol = n0 + wn * 32 + (lane & 3) * 2;
#pragma unroll
    for (int mt = 0; mt < 2; mt++)
#pragma unroll
        for (int n8 = 0; n8 < 4; n8++) {
            const float* c = acc[mt][n8];
            const int col = ccol + n8 * 8;
#pragma unroll
            for (int h = 0; h < 2; h++) {
                const int row = crow + mt * 16 + h * 8;
                *(float2*)&Cf[(size_t)row * N + col] =
                    make_float2(c[h * 2] * alpha, c[h * 2 + 1] * alpha);
            }
        }
}

// ---------------------------------------------------------------------------
__global__ void trans_conv(const float* __restrict__ in, __half* __restrict__ oh,
                           long long loOff, int R, int C,
                           long long sI, long long sO, const int* __restrict__ ids)
{
    __shared__ float tile[32][33];
    const int z = blockIdx.z;
    size_t ib = ids ? (size_t)ids[z] * sI : (size_t)z * sI;
    const float* ip = in + ib;
    __half* ohz = oh + (size_t)z * sO;
    __half* olz = loOff ? ohz + loOff : (__half*)0;
    const int c0 = blockIdx.x * 32, r0 = blockIdx.y * 32;
    const int tx = threadIdx.x, ty = threadIdx.y;
#pragma unroll
    for (int k = 0; k < 32; k += 8)
        tile[ty + k][tx] = ip[(size_t)(r0 + ty + k) * C + c0 + tx];
    __syncthreads();
    const int rr = (tx & 15) * 2, chf = tx >> 4;
#pragma unroll
    for (int k = 0; k < 2; k++) {
        int cc = ty + chf * 8 + k * 16;
        __half2 h, l;
        split_pair(tile[rr][cc], tile[rr + 1][cc], h, l);
        *(__half2*)&ohz[(size_t)(c0 + cc) * R + r0 + rr] = h;
        if (olz) *(__half2*)&olz[(size_t)(c0 + cc) * R + r0 + rr] = l;
    }
}

__global__ void conv_planes(const float* __restrict__ in, __half* __restrict__ oh,
                            long long lo)
{
    size_t idx = (size_t)blockIdx.x * 512 + (size_t)threadIdx.x * 2;
    float2 v = *(const float2*)&in[idx];
    __half2 h, l;
    split_pair(v.x, v.y, h, l);
    *(__half2*)&oh[idx] = h;
    if (lo) *(__half2*)&(oh + lo)[idx] = l;
}

__global__ void rope_table_kernel()
{
    int s = blockIdx.x;
    int i = threadIdx.x;
    float invf = 1.0f / powf(10000.0f, (float)i / 256.0f);
    float angf = (float)s * invf;
    double ang = (double)angf;
    g_sin[s * 256 + i] = (float)sin(ang);
    g_cos[s * 256 + i] = (float)cos(ang);
}

__global__ void bias_prep(const float* __restrict__ pos, float* __restrict__ out, int mode)
{
    int n = blockIdx.x, t = threadIdx.x;
    for (int c = t; c < 1024; c += 256) {
        float p = pos[n * 1024 + c];
        out[n * 1024 + c] = (mode == 1) ? logf(p) : (logf(p) - log1pf(-p));
    }
}

__global__ void softmax1024_planes(const __half* __restrict__ S, const float* __restrict__ bias,
                                   __half* __restrict__ oh)
{
    const int row = blockIdx.x, t = threadIdx.x;
    const __half* sr = S + (size_t)row * 1024;
    const float* pb = bias + (size_t)(row >> 10) * 1024;
    __half2 a  = *(const __half2*)&sr[2 * t];
    __half2 b2 = *(const __half2*)&sr[512 + 2 * t];
    float2 ba = *(const float2*)&pb[2 * t];
    float2 bb = *(const float2*)&pb[512 + 2 * t];
    float v0 = __low2float(a) + ba.x,  v1 = __high2float(a) + ba.y;
    float v2 = __low2float(b2) + bb.x, v3 = __high2float(b2) + bb.y;

    __shared__ float red[256];
    float mx = fmaxf(fmaxf(v0, v1), fmaxf(v2, v3));
    red[t] = mx; __syncthreads();
    for (int s = 128; s > 0; s >>= 1) { if (t < s) red[t] = fmaxf(red[t], red[t + s]); __syncthreads(); }
    mx = red[0]; __syncthreads();

    float e0 = expf(v0 - mx), e1 = expf(v1 - mx), e2 = expf(v2 - mx), e3 = expf(v3 - mx);
    red[t] = e0 + e1 + e2 + e3; __syncthreads();
    for (int s = 128; s > 0; s >>= 1) { if (t < s) red[t] += red[t + s]; __syncthreads(); }
    float inv = 1.0f / red[0];

    size_t o = (size_t)row * 1024 + 2 * t;
    *(__half2*)&oh[o]       = __floats2half2_rn(e0 * inv, e1 * inv);
    *(__half2*)&oh[o + 512] = __floats2half2_rn(e2 * inv, e3 * inv);
}

__global__ void softmax64_planes(const float* __restrict__ S, __half* __restrict__ oh)
{
    const int row = blockIdx.x * 8 + (threadIdx.x >> 5);
    const int lane = threadIdx.x & 31;
    const float* sr = S + (size_t)row * 64;
    float2 v = *(const float2*)&sr[lane * 2];
    float mx = fmaxf(v.x, v.y);
#pragma unroll
    for (int o = 16; o > 0; o >>= 1)
        mx = fmaxf(mx, __shfl_xor_sync(0xFFFFFFFF, mx, o));
    float e0 = expf(v.x - mx), e1 = expf(v.y - mx);
    float s = e0 + e1;
#pragma unroll
    for (int o = 16; o > 0; o >>= 1)
        s += __shfl_xor_sync(0xFFFFFFFF, s, o);
    float inv = 1.0f / s;
    *(__half2*)&oh[(size_t)row * 64 + lane * 2] = __floats2half2_rn(e0 * inv, e1 * inv);
}

__global__ void softmax_f32(float* __restrict__ S, const float* __restrict__ bias,
                            int cols, int rpb)
{
    int row = blockIdx.x;
    float* sr = S + (size_t)row * cols;
    const float* pb = bias + (size_t)(row / rpb) * cols;
    int t = threadIdx.x;
    __shared__ float red[256];

    float mx = -1e30f;
    for (int c = t; c < cols; c += 256) {
        float v = sr[c] + pb[c];
        sr[c] = v;
        mx = fmaxf(mx, v);
    }
    red[t] = mx; __syncthreads();
    for (int s = 128; s > 0; s >>= 1) { if (t < s) red[t] = fmaxf(red[t], red[t + s]); __syncthreads(); }
    mx = red[0]; __syncthreads();

    float sum = 0.0f;
    for (int c = t; c < cols; c += 256) {
        float e = expf(sr[c] - mx);
        sr[c] = e;
        sum += e;
    }
    red[t] = sum; __syncthreads();
    for (int s = 128; s > 0; s >>= 1) { if (t < s) red[t] += red[t + s]; __syncthreads(); }
    float inv = 1.0f / red[0];
    for (int c = t; c < cols; c += 256) sr[c] *= inv;
}

__global__ void ln_kernel(const float* __restrict__ Xin, const float* __restrict__ R,
                          const float* __restrict__ g, const float* __restrict__ b,
                          float* __restrict__ Xout,
                          __half* __restrict__ oh, long long lo)
{
    int row = blockIdx.x;
    int t   = threadIdx.x;
    const float* xr = Xin + (size_t)row * DD;
    const float* rr = R + (size_t)row * DD;

    float v0 = xr[2 * t] + rr[2 * t];
    float v1 = xr[2 * t + 1] + rr[2 * t + 1];

    __shared__ float red[256];
    red[t] = v0 + v1; __syncthreads();
    for (int s = 128; s > 0; s >>= 1) { if (t < s) red[t] += red[t + s]; __syncthreads(); }
    float m = red[0] * (1.0f / 512.0f);
    __syncthreads();

    float d0 = v0 - m, d1 = v1 - m;
    red[t] = d0 * d0 + d1 * d1; __syncthreads();
    for (int s = 128; s > 0; s >>= 1) { if (t < s) red[t] += red[t + s]; __syncthreads(); }
    float var = red[0] * (1.0f / 512.0f);
    float inv = rsqrtf(var + 1e-5f);

    float o0 = d0 * inv * g[2 * t]     + b[2 * t];
    float o1 = d1 * inv * g[2 * t + 1] + b[2 * t + 1];
    float* xo = Xout + (size_t)row * DD;
    xo[2 * t]     = o0;
    xo[2 * t + 1] = o1;

    __half2 h, l;
    split_pair(o0, o1, h, l);
    size_t o = (size_t)row * DD + 2 * t;
    *(__half2*)&oh[o] = h;
    *(__half2*)&(oh + lo)[o] = l;
}

__global__ void vgate_kernel(const float* __restrict__ F, const float* __restrict__ raw,
                             const float* __restrict__ Wig, const float* __restrict__ big,
                             float* __restrict__ V)
{
    int row = blockIdx.x;
    int t   = threadIdx.x;
    const float* fr = F + (size_t)row * DD;
    __shared__ float red[256];
    float s = fr[t] * Wig[t] + fr[t + 256] * Wig[t + 256];
    red[t] = s; __syncthreads();
    for (int k = 128; k > 0; k >>= 1) { if (t < k) red[t] += red[t + k]; __syncthreads(); }
    float gte = 1.0f / (1.0f + expf(-(red[0] + big[0])));
    const float* rr = raw + (size_t)row * DD;
    float* vr = V + (size_t)row * DD;
    vr[t]       = rr[t]       * gte;
    vr[t + 256] = rr[t + 256] * gte;
}

__global__ void out_kernel(const float* __restrict__ FU, const float* __restrict__ A2,
                           const float* __restrict__ PD,
                           const float* __restrict__ Wu1, const float* __restrict__ bu1,
                           const float* __restrict__ Wu2, const float* __restrict__ bu2,
                           const float* __restrict__ b1,
                           float* __restrict__ out, float* __restrict__ gate)
{
    int row = blockIdx.x;
    int t   = threadIdx.x;
    const float* fu = FU + (size_t)row * DD;
    const float* a2 = A2 + (size_t)row * DD;
    const float* pd = PD + (size_t)row * DD;

    __shared__ float red[256];
    float s = fu[t] * Wu1[t] + fu[t + 256] * Wu1[t + 256]
            + a2[t] * Wu2[t] + a2[t + 256] * Wu2[t + 256];
    red[t] = s; __syncthreads();
    for (int k = 128; k > 0; k >>= 1) { if (t < k) red[t] += red[t + k]; __syncthreads(); }
    float z = red[0] + bu1[0] + bu2[0] + b1[0] - 4.0f;
    float g = 1.0f / (1.0f + expf(-z));

    float* orow = out + (size_t)row * DD;
    orow[t]       = pd[t]       * (1.0f - g) + a2[t]       * g;
    orow[t + 256] = pd[t + 256] * (1.0f - g) + a2[t + 256] * g;
    if (t == 0) gate[row] = g;
}

#define BM 64
#define BN 64
#define BK 16

__global__ void gemm_kernel(const float* __restrict__ A,
                            const float* __restrict__ Bm,
                            const float* __restrict__ bias,
                            float* __restrict__ C,
                            int M, int N, int K,
                            long long sA, long long sB, long long sC,
                            float alpha, int transB, int epi)
{
    const int bz = blockIdx.z;
    A  += (size_t)bz * sA;
    Bm += (size_t)bz * sB;
    C  += (size_t)bz * sC;

    const int m0 = blockIdx.y * BM;
    const int n0 = blockIdx.x * BN;

    __shared__ float As[BK][BM + 4];
    __shared__ float Bs[BK][BN + 4];

    const int t  = threadIdx.x;
    const int tx = t & 15;
    const int ty = t >> 4;

    float acc[4][4] = {};

    const int arow = t >> 2;
    const int akc  = (t & 3) * 4;
    const int kb   = t >> 4;
    const int nb   = (t & 15) * 4;

    for (int k0 = 0; k0 < K; k0 += BK) {
        float4 av = *(const float4*)&A[(size_t)(m0 + arow) * K + k0 + akc];
        As[akc + 0][arow] = av.x;
        As[akc + 1][arow] = av.y;
        As[akc + 2][arow] = av.z;
        As[akc + 3][arow] = av.w;

        if (!transB) {
            float4 bv = *(const float4*)&Bm[(size_t)(k0 + kb) * N + n0 + nb];
            *(float4*)&Bs[kb][nb] = bv;
        } else {
            float4 bv = *(const float4*)&Bm[(size_t)(n0 + arow) * K + k0 + akc];
            Bs[akc + 0][arow] = bv.x;
            Bs[akc + 1][arow] = bv.y;
            Bs[akc + 2][arow] = bv.z;
            Bs[akc + 3][arow] = bv.w;
        }
        __syncthreads();

#pragma unroll
        for (int k = 0; k < BK; k++) {
            float4 a = *(const float4*)&As[k][ty * 4];
            float4 b = *(const float4*)&Bs[k][tx * 4];
            acc[0][0] += a.x * b.x; acc[0][1] += a.x * b.y;
            acc[0][2] += a.x * b.z; acc[0][3] += a.x * b.w;
            acc[1][0] += a.y * b.x; acc[1][1] += a.y * b.y;
            acc[1][2] += a.y * b.z; acc[1][3] += a.y * b.w;
            acc[2][0] += a.z * b.x; acc[2][1] += a.z * b.y;
            acc[2][2] += a.z * b.z; acc[2][3] += a.z * b.w;
            acc[3][0] += a.w * b.x; acc[3][1] += a.w * b.y;
            acc[3][2] += a.w * b.z; acc[3][3] += a.w * b.w;
        }
        __syncthreads();
    }

#pragma unroll
    for (int i = 0; i < 4; i++) {
        const int row = m0 + ty * 4 + i;
        float v[4];
#pragma unroll
        for (int j = 0; j < 4; j++) {
            float x = acc[i][j] * alpha;
            if (bias) x += bias[n0 + tx * 4 + j];
            v[j] = x;
        }
        *(float4*)&C[(size_t)row * N + n0 + tx * 4] = make_float4(v[0], v[1], v[2], v[3]);
    }
}

static void sgemm_launch(const float* A, const float* B, const float* bias, float* C,
                         int M, int N, int K, int batch,
                         long long sA, long long sB, long long sC,
                         float alpha, int transB, cudaStream_t st)
{
    dim3 grid(N / BN, M / BM, batch);
    gemm_kernel<<<grid, 256, 0, st>>>(A, B, bias, C, M, N, K, sA, sB, sC, alpha, transB, 0);
}

// ---------------------------------------------------------------------------
// Encoder (stream + buffer views). QKV 1-term; Wo/FF 3-term.
// ---------------------------------------------------------------------------
static void run_encoder(const float* Xin0, float* X, int nb,
                        const __half* initHi,
                        const float* biasRows, const __half* PW,
                        const float* bqkv, const float* bo,
                        const float* ln, const float* bff,
                        float* bV, float* bK, __half* Sh,
                        __half* Pq, __half* Pk, __half* Pvt,
                        __half* Pp, __half* Pbq, __half* Ph,
                        __half* Px, long long lo, cudaStream_t st)
{
    const int rows = nb * SS;
    const float sc = 1.0f / sqrtf((float)DD);
    for (int l = 0; l < 2; l++) {
        const __half* AP = (l == 0) ? initHi : Px;
        tg1(AP, 0, PW + (size_t)(l * 3) * 262144, 0,
            bqkv + (size_t)l * 1536, bV, 0, Pq, Pk, 0, 0,
            rows, 1536, 512, 1, 1.0f, 2, st);
        trans_conv<<<dim3(16, 32, nb), dim3(32, 8), 0, st>>>(bV, Pvt, 0, 1024, 512,
                                                             524288, 524288, nullptr);
        tg1(Pq, 524288, Pk, 524288, nullptr, nullptr, 0, Sh, nullptr, 0, 1048576,
            1024, 1024, 512, nb, sc, 0, st);
        softmax1024_planes<<<rows, 256, 0, st>>>(Sh, biasRows, Pp);
        tg1(Pp, 1048576, Pvt, 524288, nullptr, nullptr, 0, Pbq, nullptr, lo, 524288,
            1024, 512, 1024, nb, 1.0f, 0, st);
        tg3(Pbq, lo, 0, PW + (size_t)(6 + l) * 262144, WLO, 0, bo + l * 512,
            bK, 0, nullptr, 0, 0, rows, 512, 512, 1, 1.0f, 0, st);
        ln_kernel<<<rows, 256, 0, st>>>((l == 0) ? Xin0 : X, bK,
                                        ln + l * 2048, ln + l * 2048 + 512, X, Px, lo);
        tg3(Px, lo, 0, PW + (size_t)(8 + 2 * l) * 262144, WLO, 0, bff + l * 1024,
            nullptr, 0, Ph, lo, 0, rows, 512, 512, 1, 1.0f, 1, st);
        tg3(Ph, lo, 0, PW + (size_t)(9 + 2 * l) * 262144, WLO, 0, bff + l * 1024 + 512,
            bK, 0, nullptr, 0, 0, rows, 512, 512, 1, 1.0f, 0, st);
        ln_kernel<<<rows, 256, 0, st>>>(X, bK, ln + l * 2048 + 1024, ln + l * 2048 + 1536,
                                        X, Px, lo);
    }
}

extern "C" void kernel_launch(void* const* d_in, const int* in_sizes, int n_in,
                              void* d_out, int out_size)
{
    const float* raw_emb   = (const float*)d_in[0];
    const float* pos_w     = (const float*)d_in[1];
    const float* post_dec  = (const float*)d_in[2];
    const float* pos_r     = (const float*)d_in[3];
    const float* questions = (const float*)d_in[4];
    const float* W_k       = (const float*)d_in[5];
    const float* W_ig      = (const float*)d_in[6];
    const float* b_ig      = (const float*)d_in[7];
    const float* W_u1      = (const float*)d_in[8];
    const float* b_u1      = (const float*)d_in[9];
    const float* W_u2      = (const float*)d_in[10];
    const float* b_u2      = (const float*)d_in[11];
    const float* b1        = (const float*)d_in[12];
    const float* W_ok      = (const float*)d_in[13];
    const float* b_ok      = (const float*)d_in[14];
    const float* encw_Wqkv = (const float*)d_in[15];
    const float* encw_bqkv = (const float*)d_in[16];
    const float* encw_Wo   = (const float*)d_in[17];
    const float* encw_bo   = (const float*)d_in[18];
    const float* encw_ln   = (const float*)d_in[19];
    const float* encw_Wff  = (const float*)d_in[20];
    const float* encw_bff  = (const float*)d_in[21];
    const float* encr_Wqkv = (const float*)d_in[22];
    const float* encr_bqkv = (const float*)d_in[23];
    const float* encr_Wo   = (const float*)d_in[24];
    const float* encr_bo   = (const float*)d_in[25];
    const float* encr_ln   = (const float*)d_in[26];
    const float* encr_Wff  = (const float*)d_in[27];
    const float* encr_bff  = (const float*)d_in[28];
    const int*   lookup    = (const int*)d_in[29];

    float* out  = (float*)d_out;
    float* gate = out + (size_t)NBB * SS * DD;

    float *pX, *pV, *pK, *pXw, *pVw, *pKw, *pS1, *pKd, *pVd, *pA1, *pA2s, *pA2, *pBW, *pBR;
    __half *pPW, *pPraw, *pPpd, *pPx, *pPq, *pPk, *pPvt, *pPp, *pPbq, *pPh, *pSh;
    __half *pPxw, *pPqw, *pPkw, *pPvtw, *pPpw, *pPbqw, *pPhw, *pShw;
    __half *pPk2, *pPa2, *pPsel, *pPqst;
    cudaGetSymbolAddress((void**)&pX,    g_X);
    cudaGetSymbolAddress((void**)&pV,    g_V);
    cudaGetSymbolAddress((void**)&pK,    g_Kb);
    cudaGetSymbolAddress((void**)&pXw,   g_Xw);
    cudaGetSymbolAddress((void**)&pVw,   g_Vw);
    cudaGetSymbolAddress((void**)&pKw,   g_Kw);
    cudaGetSymbolAddress((void**)&pS1,   g_S1);
    cudaGetSymbolAddress((void**)&pKd,   g_Kdoc);
    cudaGetSymbolAddress((void**)&pVd,   g_Vdoc);
    cudaGetSymbolAddress((void**)&pA1,   g_A1S);
    cudaGetSymbolAddress((void**)&pA2s,  g_A2SC);
    cudaGetSymbolAddress((void**)&pA2,   g_A2);
    cudaGetSymbolAddress((void**)&pBW,   g_BIASW);
    cudaGetSymbolAddress((void**)&pBR,   g_BIASR);
    cudaGetSymbolAddress((void**)&pPW,   g_PW);
    cudaGetSymbolAddress((void**)&pPraw, g_Praw);
    cudaGetSymbolAddress((void**)&pPpd,  g_Ppd);
    cudaGetSymbolAddress((void**)&pPx,   g_Px);
    cudaGetSymbolAddress((void**)&pPq,   g_Pq);
    cudaGetSymbolAddress((void**)&pPk,   g_Pk);
    cudaGetSymbolAddress((void**)&pPvt,  g_Pvt);
    cudaGetSymbolAddress((void**)&pPp,   g_Pp);
    cudaGetSymbolAddress((void**)&pPbq,  g_Pbq);
    cudaGetSymbolAddress((void**)&pPh,   g_Ph);
    cudaGetSymbolAddress((void**)&pSh,   g_Sh);
    cudaGetSymbolAddress((void**)&pPxw,  g_Pxw);
    cudaGetSymbolAddress((void**)&pPqw,  g_Pqw);
    cudaGetSymbolAddress((void**)&pPkw,  g_Pkw);
    cudaGetSymbolAddress((void**)&pPvtw, g_Pvtw);
    cudaGetSymbolAddress((void**)&pPpw,  g_Ppw);
    cudaGetSymbolAddress((void**)&pPbqw, g_Pbqw);
    cudaGetSymbolAddress((void**)&pPhw,  g_Phw);
    cudaGetSymbolAddress((void**)&pShw,  g_Shw);
    cudaGetSymbolAddress((void**)&pPk2,  g_Pk2);
    cudaGetSymbolAddress((void**)&pPa2,  g_Pa2);
    cudaGetSymbolAddress((void**)&pPsel, g_Psel);
    cudaGetSymbolAddress((void**)&pPqst, g_Pqst);

    cudaFuncSetAttribute(tgemm3,    cudaFuncAttributeMaxDynamicSharedMemorySize, TG_SMEM);
    cudaFuncSetAttribute(tgemm1,    cudaFuncAttributeMaxDynamicSharedMemorySize, T1_SMEM);
    cudaFuncSetAttribute(tgemm1n64, cudaFuncAttributeMaxDynamicSharedMemorySize, T1N_SMEM);

    const float scD = 1.0f / sqrtf((float)DD);
    // split point: 12 batches on s0, 4 on s2
    const long long HB = 12LL * 1024 * 512;      // 6291456 elements
    const long long HP = 12LL * 1048576;         // Pp / Sh offset

    cudaStream_t s2;
    cudaStreamCreateWithFlags(&s2, cudaStreamNonBlocking);
    cudaEvent_t evF, evJ;
    cudaEventCreateWithFlags(&evF, cudaEventDisableTiming);
    cudaEventCreateWithFlags(&evJ, cudaEventDisableTiming);
    cudaStream_t s0 = 0;

    // ---- common prep on s0 (needed by both streams) ----
    rope_table_kernel<<<1024, 256, 0, s0>>>();
    conv_planes<<<NBB * SS, 256, 0, s0>>>(post_dec, pPpd, 0);
    trans_conv<<<dim3(16, 16, 6), dim3(32, 8), 0, s0>>>(encr_Wqkv, pPW + 12LL * 262144, WLO, 512, 512, 262144, 262144, nullptr);
    trans_conv<<<dim3(16, 16, 2), dim3(32, 8), 0, s0>>>(encr_Wo,   pPW + 18LL * 262144, WLO, 512, 512, 262144, 262144, nullptr);
    trans_conv<<<dim3(16, 16, 4), dim3(32, 8), 0, s0>>>(encr_Wff,  pPW + 20LL * 262144, WLO, 512, 512, 262144, 262144, nullptr);
    bias_prep<<<NBB, 256, 0, s0>>>(pos_r, pBR, 2);

    cudaEventRecord(evF, s0);
    cudaStreamWaitEvent(s2, evF, 0);

    // ================= s2: write side + k2/a2 + read batches 12..15 ========
    trans_conv<<<dim3(16, 16, 6), dim3(32, 8), 0, s2>>>(encw_Wqkv, pPW + 0LL * 262144, WLO, 512, 512, 262144, 262144, nullptr);
    trans_conv<<<dim3(16, 16, 2), dim3(32, 8), 0, s2>>>(encw_Wo,   pPW + 6LL * 262144, WLO, 512, 512, 262144, 262144, nullptr);
    trans_conv<<<dim3(16, 16, 4), dim3(32, 8), 0, s2>>>(encw_Wff,  pPW + 8LL * 262144, WLO, 512, 512, 262144, 262144, nullptr);
    conv_planes<<<NDOC * SS, 256, 0, s2>>>(raw_emb, pPraw, 0);
    bias_prep<<<NDOC, 256, 0, s2>>>(pos_w, pBW, 1);

    run_encoder(raw_emb, pXw, NDOC, pPraw, pBW,
                pPW, encw_bqkv, encw_bo, encw_ln, encw_bff,
                pVw, pKw, pShw, pPqw, pPkw, pPvtw, pPpw, pPbqw, pPhw, pPxw,
                LOW, s2);

    vgate_kernel<<<NDOC * SS, 256, 0, s2>>>(pXw, raw_emb, W_ig, b_ig, pVd);
    trans_conv<<<dim3(16, 16, 1), dim3(32, 8), 0, s2>>>(W_k, pPW + 24LL * 262144, WLO, 512, 512, 262144, 262144, nullptr);
    tg1(pPraw, 0, pPW + 24LL * 262144, 0, nullptr, pKd, 0, nullptr, nullptr, 0, 0,
        NDOC * SS, 512, 512, 1, 1.0f, 0, s2);
    sgemm_launch(questions, pKd, nullptr, pS1, QQ, SS, DD, NDOC, 0, 524288, 65536, scD, 1, s2);
    softmax_f32<<<NDOC * QQ, 256, 0, s2>>>(pS1, pBW, SS, QQ);
    sgemm_launch(pS1, pVd, nullptr, pA1, QQ, DD, SS, NDOC, 65536, 524288, 32768, 1.0f, 0, s2);
    trans_conv<<<dim3(16, 2, 16), dim3(32, 8), 0, s2>>>(pA1, pPsel, 0, 64, 512, 32768, 32768, lookup);

    // independent k2/a2/A2 chain
    trans_conv<<<dim3(16, 16, 1), dim3(32, 8), 0, s2>>>(W_ok, pPW + 25LL * 262144, WLO, 512, 512, 262144, 262144, nullptr);
    conv_planes<<<QQ, 256, 0, s2>>>(questions, pPqst, 0);
    tg1(pPpd, 0, pPW + 25LL * 262144, 0, b_ok, nullptr, 0, pPk2, nullptr, 0, 0,
        NBB * SS, 512, 512, 1, 1.0f, 0, s2);
    {
        dim3 grid(1, (NBB * SS) / 128, 1);
        tgemm1n64<<<grid, 256, T1N_SMEM, s2>>>(pPk2, pPqst, pA2s, NBB * SS, QQ, DD, 0.125f);
    }
    softmax64_planes<<<NBB * SS / 8, 256, 0, s2>>>(pA2s, pPa2);
    tg1(pPa2, 65536, pPsel, 32768, nullptr, pA2, 524288, nullptr, nullptr, 0, 0,
        1024, 512, 64, NBB, 1.0f, 0, s2);

    // read-side encoder, batches 12..15 (offset views into read buffers)
    run_encoder(post_dec + HB, pX + HB, 4, pPpd + HB, pBR + 12 * 1024,
                pPW + 12LL * 262144, encr_bqkv, encr_bo, encr_ln, encr_bff,
                pV + HB, pK + HB, pSh + HP,
                pPq + HB, pPk + HB, pPvt + HB,
                pPp + HP, pPbq + HB, pPh + HB, pPx + HB,
                LO, s2);

    cudaEventRecord(evJ, s2);

    // ================= s0: read-side encoder, batches 0..11 ================
    run_encoder(post_dec, pX, 12, pPpd, pBR,
                pPW + 12LL * 262144, encr_bqkv, encr_bo, encr_ln, encr_bff,
                pV, pK, pSh, pPq, pPk, pPvt, pPp, pPbq, pPh, pPx,
                LO, s0);

    // join + final
    cudaStreamWaitEvent(s0, evJ, 0);
    out_kernel<<<NBB * SS, 256, 0, s0>>>(pX, pA2, post_dec,
                                         W_u1, b_u1, W_u2, b_u2, b1,
                                         out, gate);

    (void)in_sizes; (void)n_in; (void)out_size;
}

// round 14
// speedup vs baseline: 1.0627x; 1.0474x over previous
#include <cuda_runtime.h>
#include <cuda_fp16.h>
#include <math.h>
#include <stdint.h>

#define DD     512
#define SS     1024
#define NBB    16
#define QQ     64
#define NDOC   8

// ---- read-side f32 scratch ----
__device__ float g_X   [16384 * 512];
__device__ float g_Kb  [16384 * 512];
// ---- write-side f32 scratch ----
__device__ float g_Xw  [8192 * 512];
__device__ float g_Kw  [8192 * 512];
__device__ float g_S1  [8 * 64 * 1024];
__device__ float g_Kdoc[8192 * 512];
__device__ float g_Vdoc[8192 * 512];
__device__ float g_A1S [8 * 64 * 512];
__device__ float g_A2SC[16384 * 64];
__device__ float g_A2  [16384 * 512];
__device__ float g_sin [1024 * 256];
__device__ float g_cos [1024 * 256];
__device__ float g_BIASW[8 * 1024];
__device__ float g_BIASR[16 * 1024];

#define WLO 6815744LL
#define LO  8388608LL
#define LOW 4194304LL
__device__ __align__(16) __half g_PW  [2 * 26 * 262144];
__device__ __align__(16) __half g_Praw[4194304];
__device__ __align__(16) __half g_Ppd [8388608];
// read-side planes
__device__ __align__(16) __half g_Px  [2 * 8388608];
__device__ __align__(16) __half g_Pq  [8388608];
__device__ __align__(16) __half g_Pk  [8388608];
__device__ __align__(16) __half g_Vh  [8388608];      // V fp16 (row-major)
__device__ __align__(16) __half g_Pvt [8388608];
__device__ __align__(16) __half g_Pp  [16777216];
__device__ __align__(16) __half g_Pbq [2 * 8388608];
__device__ __align__(16) __half g_Ph  [2 * 8388608];
__device__ __align__(16) __half g_Sh  [16 * 1048576];
// write-side planes
__device__ __align__(16) __half g_Pxw [2 * 4194304];
__device__ __align__(16) __half g_Pqw [4194304];
__device__ __align__(16) __half g_Pkw [4194304];
__device__ __align__(16) __half g_Vhw [4194304];
__device__ __align__(16) __half g_Pvtw[4194304];
__device__ __align__(16) __half g_Ppw [8388608];
__device__ __align__(16) __half g_Pbqw[2 * 4194304];
__device__ __align__(16) __half g_Phw [2 * 4194304];
__device__ __align__(16) __half g_Shw [8 * 1048576];
// misc planes
__device__ __align__(16) __half g_Pk2 [8388608];
__device__ __align__(16) __half g_Pa2 [1048576];
__device__ __align__(16) __half g_Psel[524288];
__device__ __align__(16) __half g_Pqst[32768];

__device__ __forceinline__ uint32_t smem_u32(const void* p) {
    uint32_t a;
    asm("{ .reg .u64 t; cvta.to.shared.u64 t, %1; cvt.u32.u64 %0, t; }"
        : "=r"(a) : "l"(p));
    return a;
}

__device__ __forceinline__ void ldsm4(uint32_t* r, uint32_t addr) {
    asm volatile("ldmatrix.sync.aligned.m8n8.x4.shared.b16 {%0,%1,%2,%3}, [%4];"
                 : "=r"(r[0]), "=r"(r[1]), "=r"(r[2]), "=r"(r[3]) : "r"(addr));
}

__device__ __forceinline__ void mma_f16(float* c, const uint32_t* a,
                                        uint32_t b0, uint32_t b1) {
    asm volatile(
        "mma.sync.aligned.m16n8k16.row.col.f32.f16.f16.f32 "
        "{%0,%1,%2,%3}, {%4,%5,%6,%7}, {%8,%9}, {%0,%1,%2,%3};"
        : "+f"(c[0]), "+f"(c[1]), "+f"(c[2]), "+f"(c[3])
        : "r"(a[0]), "r"(a[1]), "r"(a[2]), "r"(a[3]), "r"(b0), "r"(b1));
}

__device__ __forceinline__ void cpasync16(uint32_t dst, const void* src) {
    asm volatile("cp.async.cg.shared.global [%0], [%1], 16;" :: "r"(dst), "l"(src));
}
#define CP_COMMIT() asm volatile("cp.async.commit_group;" ::: "memory")
#define CP_WAIT(n)  asm volatile("cp.async.wait_group %0;" :: "n"(n) : "memory")

__device__ __forceinline__ void split_pair(float x0, float x1,
                                           __half2& h, __half2& l) {
    h = __floats2half2_rn(x0, x1);
    l = __floats2half2_rn(x0 - __low2float(h), x1 - __high2float(h));
}

// ---------------------------------------------------------------------------
// 3-term split GEMM (fp16 planes): residual-path GEMMs (Wo, FF)
// ---------------------------------------------------------------------------
#define PLANE  10240
#define TSTAGE 40960
#define TG_SMEM (4 * 40960)

__global__ void __launch_bounds__(512)
tgemm3(const __half* __restrict__ Ah0, const __half* __restrict__ Bh0,
       const float* __restrict__ bias, float* __restrict__ Cf,
       __half* __restrict__ Ch0,
       int M, int N, int K,
       long long loA, long long loB, long long loC,
       long long sA, long long sB, long long sC, long long sCp,
       float alpha, int epi)
{
    extern __shared__ char smem[];
    const uint32_t sbu = smem_u32(smem);
    const int t = threadIdx.x, w = t >> 5, lane = t & 31;
    const int wm = w & 3, wn = w >> 2;
    const int z = blockIdx.z;
    const int m0 = blockIdx.y * 128, n0 = blockIdx.x * 128;

    const __half* Ah = Ah0 + (size_t)z * sA;
    const __half* Bh = Bh0 + (size_t)z * sB;

    const int lrow = t >> 2, seg = t & 3;
    const __half* pr[4];
    pr[0] = Ah + (size_t)(m0 + lrow) * K + seg * 8;
    pr[1] = pr[0] + loA;
    pr[2] = Bh + (size_t)(n0 + lrow) * K + seg * 8;
    pr[3] = pr[2] + loB;

    float acc[2][4][4];
#pragma unroll
    for (int i = 0; i < 2; i++)
#pragma unroll
        for (int j = 0; j < 4; j++)
#pragma unroll
            for (int e = 0; e < 4; e++) acc[i][j][e] = 0.0f;

    const int nch = K >> 5;
    const uint32_t sdbase = sbu + (uint32_t)(lrow * 80 + seg * 16);

#define ISSUE(ch) do {                                                      \
    uint32_t _sd = sdbase + (uint32_t)((ch) & 3) * TSTAGE;                  \
    const int _cb = (ch) * 32;                                              \
    _Pragma("unroll")                                                       \
    for (int _p = 0; _p < 4; _p++)                                          \
        cpasync16(_sd + _p * PLANE, pr[_p] + _cb);                          \
    CP_COMMIT();                                                            \
} while (0)

    ISSUE(0);
    ISSUE(1);
    if (nch > 2) ISSUE(2);

    const uint32_t lmoff = (uint32_t)((lane & 15) * 80 + (lane >> 4) * 16);

    for (int ch = 0; ch < nch; ch++) {
        const int rem = nch - 1 - ch;
        if (rem >= 2)      { CP_WAIT(2); }
        else if (rem == 1) { CP_WAIT(1); }
        else               { CP_WAIT(0); }
        __syncthreads();
        if (ch + 3 < nch) ISSUE(ch + 3);

        const uint32_t sAh = sbu + (uint32_t)(ch & 3) * TSTAGE;
        const uint32_t sBh = sAh + 2 * PLANE;
#pragma unroll
        for (int kk = 0; kk < 2; kk++) {
            uint32_t ah[2][4], al[2][4], bh[2][4], bl[2][4];
#pragma unroll
            for (int mt = 0; mt < 2; mt++) {
                uint32_t aaddr = sAh + (uint32_t)((wm * 32 + mt * 16) * 80 + kk * 32) + lmoff;
                ldsm4(ah[mt], aaddr);
                ldsm4(al[mt], aaddr + PLANE);
            }
#pragma unroll
            for (int ng = 0; ng < 2; ng++) {
                uint32_t baddr = sBh + (uint32_t)((wn * 32 + ng * 16) * 80 + kk * 32) + lmoff;
                ldsm4(bh[ng], baddr);
                ldsm4(bl[ng], baddr + PLANE);
            }
#pragma unroll
            for (int ng = 0; ng < 2; ng++)
#pragma unroll
                for (int mt = 0; mt < 2; mt++)
#pragma unroll
                    for (int h2 = 0; h2 < 2; h2++)
                        mma_f16(acc[mt][ng * 2 + h2], ah[mt], bh[ng][h2], bh[ng][h2 + 2]);
#pragma unroll
            for (int ng = 0; ng < 2; ng++)
#pragma unroll
                for (int mt = 0; mt < 2; mt++)
#pragma unroll
                    for (int h2 = 0; h2 < 2; h2++)
                        mma_f16(acc[mt][ng * 2 + h2], ah[mt], bl[ng][h2], bl[ng][h2 + 2]);
#pragma unroll
            for (int ng = 0; ng < 2; ng++)
#pragma unroll
                for (int mt = 0; mt < 2; mt++)
#pragma unroll
                    for (int h2 = 0; h2 < 2; h2++)
                        mma_f16(acc[mt][ng * 2 + h2], al[mt], bh[ng][h2], bh[ng][h2 + 2]);
        }
    }
#undef ISSUE

    const float GC = 0.7978845608028654f;
    const int crow = m0 + wm * 32 + (lane >> 2);
    const int ccol = n0 + wn * 32 + (lane & 3) * 2;

    float* Cfz = Cf ? Cf + (size_t)z * sC : (float*)0;
    __half* Chz = Ch0 ? Ch0 + (size_t)z * sCp : (__half*)0;
    __half* Clz = Chz ? Chz + loC : (__half*)0;
#pragma unroll
    for (int mt = 0; mt < 2; mt++) {
#pragma unroll
        for (int n8 = 0; n8 < 4; n8++) {
            const float* c = acc[mt][n8];
            const int col = ccol + n8 * 8;
            float b0 = bias ? bias[col]     : 0.0f;
            float b1 = bias ? bias[col + 1] : 0.0f;
#pragma unroll
            for (int h = 0; h < 2; h++) {
                const int row = crow + mt * 16 + h * 8;
                float x0 = c[h * 2 + 0] * alpha + b0;
                float x1 = c[h * 2 + 1] * alpha + b1;
                if (epi == 1) {
                    x0 = 0.5f * x0 * (1.0f + tanhf(GC * (x0 + 0.044715f * x0 * x0 * x0)));
                    x1 = 0.5f * x1 * (1.0f + tanhf(GC * (x1 + 0.044715f * x1 * x1 * x1)));
                }
                if (Cfz)
                    *(float2*)&Cfz[(size_t)row * N + col] = make_float2(x0, x1);
                if (Chz) {
                    __half2 hh, ll;
                    split_pair(x0, x1, hh, ll);
                    *(__half2*)&Chz[(size_t)row * N + col] = hh;
                    *(__half2*)&Clz[(size_t)row * N + col] = ll;
                }
            }
        }
    }
}

static void tg3(const __half* Ah, long long loA, long long sA,
                const __half* Bh, long long loB, long long sB,
                const float* bias, float* Cf, long long sC,
                __half* Ch, long long loC, long long sCp,
                int M, int N, int K, int batch, float alpha, int epi,
                cudaStream_t st)
{
    dim3 grid(N / 128, M / 128, batch);
    tgemm3<<<grid, 512, TG_SMEM, st>>>(Ah, Bh, bias, Cf, Ch, M, N, K,
                                       loA, loB, loC, sA, sB, sC, sCp, alpha, epi);
}

// ---------------------------------------------------------------------------
// 1-term GEMM (hi planes only). epi: 0 = plain, 2 = QKV rope epilogue
//   epi=2: cols<1024 rope -> Ch0/Ch2 hi planes; cols>=1024 -> V fp16 via Cf
// ---------------------------------------------------------------------------
#define T1STAGE 20480
#define T1_SMEM (4 * 20480)

__global__ void __launch_bounds__(512)
tgemm1(const __half* __restrict__ Ah0, const __half* __restrict__ Bh0,
       const float* __restrict__ bias, float* __restrict__ Cf,
       __half* __restrict__ Ch0, __half* __restrict__ Ch2,
       int M, int N, int K, long long loC,
       long long sA, long long sB, long long sC, long long sCp,
       float alpha, int epi)
{
    extern __shared__ char smem[];
    const uint32_t sbu = smem_u32(smem);
    const int t = threadIdx.x, w = t >> 5, lane = t & 31;
    const int wm = w & 3, wn = w >> 2;
    const int z = blockIdx.z;
    const int m0 = blockIdx.y * 128, n0 = blockIdx.x * 128;

    const __half* Ap = Ah0 + (size_t)z * sA + (size_t)(m0 + (t >> 2)) * K + (t & 3) * 8;
    const __half* Bp = Bh0 + (size_t)z * sB + (size_t)(n0 + (t >> 2)) * K + (t & 3) * 8;

    float acc[2][4][4];
#pragma unroll
    for (int i = 0; i < 2; i++)
#pragma unroll
        for (int j = 0; j < 4; j++)
#pragma unroll
            for (int e = 0; e < 4; e++) acc[i][j][e] = 0.0f;

    const int nch = K >> 5;
    const uint32_t sdbase = sbu + (uint32_t)((t >> 2) * 80 + (t & 3) * 16);

#define ISSUE1(ch) do {                                                     \
    uint32_t _sd = sdbase + (uint32_t)((ch) & 3) * T1STAGE;                 \
    const int _cb = (ch) * 32;                                              \
    cpasync16(_sd,         Ap + _cb);                                       \
    cpasync16(_sd + PLANE, Bp + _cb);                                       \
    CP_COMMIT();                                                            \
} while (0)

    ISSUE1(0);
    ISSUE1(1);
    if (nch > 2) ISSUE1(2);

    const uint32_t lmoff = (uint32_t)((lane & 15) * 80 + (lane >> 4) * 16);

    for (int ch = 0; ch < nch; ch++) {
        const int rem = nch - 1 - ch;
        if (rem >= 2)      { CP_WAIT(2); }
        else if (rem == 1) { CP_WAIT(1); }
        else               { CP_WAIT(0); }
        __syncthreads();
        if (ch + 3 < nch) ISSUE1(ch + 3);

        const uint32_t sAh = sbu + (uint32_t)(ch & 3) * T1STAGE;
        const uint32_t sBh = sAh + PLANE;
#pragma unroll
        for (int kk = 0; kk < 2; kk++) {
            uint32_t ah[2][4], bh[2][4];
#pragma unroll
            for (int mt = 0; mt < 2; mt++)
                ldsm4(ah[mt], sAh + (uint32_t)((wm * 32 + mt * 16) * 80 + kk * 32) + lmoff);
#pragma unroll
            for (int ng = 0; ng < 2; ng++)
                ldsm4(bh[ng], sBh + (uint32_t)((wn * 32 + ng * 16) * 80 + kk * 32) + lmoff);
#pragma unroll
            for (int ng = 0; ng < 2; ng++)
#pragma unroll
                for (int mt = 0; mt < 2; mt++)
#pragma unroll
                    for (int h2 = 0; h2 < 2; h2++)
                        mma_f16(acc[mt][ng * 2 + h2], ah[mt], bh[ng][h2], bh[ng][h2 + 2]);
        }
    }
#undef ISSUE1

    const int crow = m0 + wm * 32 + (lane >> 2);
    const int ccol = n0 + wn * 32 + (lane & 3) * 2;

    if (epi == 2) {
        __half* Vh = (__half*)Cf;
#pragma unroll
        for (int mt = 0; mt < 2; mt++) {
#pragma unroll
            for (int n8 = 0; n8 < 4; n8++) {
                const float* c = acc[mt][n8];
                const int col = ccol + n8 * 8;
                float b0 = bias[col], b1 = bias[col + 1];
#pragma unroll
                for (int h = 0; h < 2; h++) {
                    const int row = crow + mt * 16 + h * 8;
                    float x0 = c[h * 2 + 0] + b0;
                    float x1 = c[h * 2 + 1] + b1;
                    if (col < 1024) {
                        const int s = row & (SS - 1);
                        const int i = (col & 511) >> 1;
                        float sn = g_sin[s * 256 + i];
                        float cs = g_cos[s * 256 + i];
                        float y0 = x0 * cs - x1 * sn;
                        float y1 = x0 * sn + x1 * cs;
                        __half* dst = (col < 512) ? Ch0 : Ch2;
                        size_t off = (size_t)row * 512 + (col & 511);
                        *(__half2*)&dst[off] = __floats2half2_rn(y0, y1);
                    } else {
                        *(__half2*)&Vh[(size_t)row * 512 + (col - 1024)] =
                            __floats2half2_rn(x0, x1);
                    }
                }
            }
        }
        return;
    }

    float* Cfz = Cf ? Cf + (size_t)z * sC : (float*)0;
    __half* Chz = Ch0 ? Ch0 + (size_t)z * sCp : (__half*)0;
    __half* Clz = (Chz && loC) ? Chz + loC : (__half*)0;
#pragma unroll
    for (int mt = 0; mt < 2; mt++) {
#pragma unroll
        for (int n8 = 0; n8 < 4; n8++) {
            const float* c = acc[mt][n8];
            const int col = ccol + n8 * 8;
            float b0 = bias ? bias[col]     : 0.0f;
            float b1 = bias ? bias[col + 1] : 0.0f;
#pragma unroll
            for (int h = 0; h < 2; h++) {
                const int row = crow + mt * 16 + h * 8;
                float x0 = c[h * 2 + 0] * alpha + b0;
                float x1 = c[h * 2 + 1] * alpha + b1;
                if (Cfz)
                    *(float2*)&Cfz[(size_t)row * N + col] = make_float2(x0, x1);
                if (Chz) {
                    __half2 hh, ll;
                    split_pair(x0, x1, hh, ll);
                    *(__half2*)&Chz[(size_t)row * N + col] = hh;
                    if (Clz) *(__half2*)&Clz[(size_t)row * N + col] = ll;
                }
            }
        }
    }
}

static void tg1(const __half* Ah, long long sA, const __half* Bh, long long sB,
                const float* bias, float* Cf, long long sC,
                __half* Ch, __half* Ch2, long long loC, long long sCp,
                int M, int N, int K, int batch, float alpha, int epi,
                cudaStream_t st)
{
    dim3 grid(N / 128, M / 128, batch);
    tgemm1<<<grid, 512, T1_SMEM, st>>>(Ah, Bh, bias, Cf, Ch, Ch2, M, N, K, loC,
                                       sA, sB, sC, sCp, alpha, epi);
}

// 1-term, N-tile 64
#define B1STAGE 15360
#define T1N_SMEM (4 * 15360)

__global__ void __launch_bounds__(256)
tgemm1n64(const __half* __restrict__ Ah0, const __half* __restrict__ Bh0,
          float* __restrict__ Cf, int M, int N, int K, float alpha)
{
    extern __shared__ char smem[];
    const uint32_t sbu = smem_u32(smem);
    const int t = threadIdx.x, w = t >> 5, lane = t & 31;
    const int wm = w & 3, wn = w >> 2;
    const int m0 = blockIdx.y * 128, n0 = blockIdx.x * 64;

    const int arow = t >> 1, aseg = (t & 1) * 2;
    const int brow = t >> 2, bseg = t & 3;
    const __half* pa = Ah0 + (size_t)(m0 + arow) * K + aseg * 8;
    const __half* pb = Bh0 + (size_t)(n0 + brow) * K + bseg * 8;
    const uint32_t adst = sbu + (uint32_t)(arow * 80 + aseg * 16);
    const uint32_t bdst = sbu + 10240u + (uint32_t)(brow * 80 + bseg * 16);

    float acc[2][4][4];
#pragma unroll
    for (int i = 0; i < 2; i++)
#pragma unroll
        for (int j = 0; j < 4; j++)
#pragma unroll
            for (int e = 0; e < 4; e++) acc[i][j][e] = 0.0f;

    const int nch = K >> 5;

#define ISSUEN(ch) do {                                                     \
    uint32_t _st = (uint32_t)((ch) & 3) * B1STAGE;                          \
    const int _cb = (ch) * 32;                                              \
    cpasync16(adst + _st,      pa + _cb);                                   \
    cpasync16(adst + _st + 16, pa + _cb + 8);                               \
    cpasync16(bdst + _st,      pb + _cb);                                   \
    CP_COMMIT();                                                            \
} while (0)

    ISSUEN(0);
    ISSUEN(1);
    if (nch > 2) ISSUEN(2);

    const uint32_t lmoff = (uint32_t)((lane & 15) * 80 + (lane >> 4) * 16);

    for (int ch = 0; ch < nch; ch++) {
        const int rem = nch - 1 - ch;
        if (rem >= 2)      { CP_WAIT(2); }
        else if (rem == 1) { CP_WAIT(1); }
        else               { CP_WAIT(0); }
        __syncthreads();
        if (ch + 3 < nch) ISSUEN(ch + 3);

        const uint32_t sAh = sbu + (uint32_t)(ch & 3) * B1STAGE;
        const uint32_t sBh = sAh + 10240u;
#pragma unroll
        for (int kk = 0; kk < 2; kk++) {
            uint32_t ah[2][4], bh[2][4];
#pragma unroll
            for (int mt = 0; mt < 2; mt++)
                ldsm4(ah[mt], sAh + (uint32_t)((wm * 32 + mt * 16) * 80 + kk * 32) + lmoff);
#pragma unroll
            for (int ng = 0; ng < 2; ng++)
                ldsm4(bh[ng], sBh + (uint32_t)((wn * 32 + ng * 16) * 80 + kk * 32) + lmoff);
#pragma unroll
            for (int ng = 0; ng < 2; ng++)
#pragma unroll
                for (int mt = 0; mt < 2; mt++)
#pragma unroll
                    for (int h2 = 0; h2 < 2; h2++)
                        mma_f16(acc[mt][ng * 2 + h2], ah[mt], bh[ng][h2], bh[ng][h2 + 2]);
        }
    }
#undef ISSUEN

    const int crow = m0 + wm * 32 + (lane >> 2);
    const int ccol = n0 + wn * 32 + (lane & 3) * 2;
#pragma unroll
    for (int mt = 0; mt < 2; mt++)
#pragma unroll
        for (int n8 = 0; n8 < 4; n8++) {
            const float* c = acc[mt][n8];
            const int col = ccol + n8 * 8;
#pragma unroll
            for (int h = 0; h < 2; h++) {
                const int row = crow + mt * 16 + h * 8;
                *(float2*)&Cf[(size_t)row * N + col] =
                    make_float2(c[h * 2] * alpha, c[h * 2 + 1] * alpha);
            }
        }
}

// ---------------------------------------------------------------------------
// Transpose + convert to planes (f32 input)
// ---------------------------------------------------------------------------
__global__ void trans_conv(const float* __restrict__ in, __half* __restrict__ oh,
                           long long loOff, int R, int C,
                           long long sI, long long sO, const int* __restrict__ ids)
{
    __shared__ float tile[32][33];
    const int z = blockIdx.z;
    size_t ib = ids ? (size_t)ids[z] * sI : (size_t)z * sI;
    const float* ip = in + ib;
    __half* ohz = oh + (size_t)z * sO;
    __half* olz = loOff ? ohz + loOff : (__half*)0;
    const int c0 = blockIdx.x * 32, r0 = blockIdx.y * 32;
    const int tx = threadIdx.x, ty = threadIdx.y;
#pragma unroll
    for (int k = 0; k < 32; k += 8)
        tile[ty + k][tx] = ip[(size_t)(r0 + ty + k) * C + c0 + tx];
    __syncthreads();
    const int rr = (tx & 15) * 2, chf = tx >> 4;
#pragma unroll
    for (int k = 0; k < 2; k++) {
        int cc = ty + chf * 8 + k * 16;
        __half2 h, l;
        split_pair(tile[rr][cc], tile[rr + 1][cc], h, l);
        *(__half2*)&ohz[(size_t)(c0 + cc) * R + r0 + rr] = h;
        if (olz) *(__half2*)&olz[(size_t)(c0 + cc) * R + r0 + rr] = l;
    }
}

// Transpose fp16 -> fp16 hi-only (for V)
__global__ void trans_conv_h(const __half* __restrict__ in, __half* __restrict__ oh,
                             int R, int C, long long sI, long long sO)
{
    __shared__ float tile[32][33];
    const int z = blockIdx.z;
    const __half* ip = in + (size_t)z * sI;
    __half* ohz = oh + (size_t)z * sO;
    const int c0 = blockIdx.x * 32, r0 = blockIdx.y * 32;
    const int tx = threadIdx.x, ty = threadIdx.y;
#pragma unroll
    for (int k = 0; k < 32; k += 8)
        tile[ty + k][tx] = __half2float(ip[(size_t)(r0 + ty + k) * C + c0 + tx]);
    __syncthreads();
    const int rr = (tx & 15) * 2, chf = tx >> 4;
#pragma unroll
    for (int k = 0; k < 2; k++) {
        int cc = ty + chf * 8 + k * 16;
        *(__half2*)&ohz[(size_t)(c0 + cc) * R + r0 + rr] =
            __floats2half2_rn(tile[rr][cc], tile[rr + 1][cc]);
    }
}

__global__ void conv_planes(const float* __restrict__ in, __half* __restrict__ oh,
                            long long lo)
{
    size_t idx = (size_t)blockIdx.x * 512 + (size_t)threadIdx.x * 2;
    float2 v = *(const float2*)&in[idx];
    __half2 h, l;
    split_pair(v.x, v.y, h, l);
    *(__half2*)&oh[idx] = h;
    if (lo) *(__half2*)&(oh + lo)[idx] = l;
}

__global__ void rope_table_kernel()
{
    int s = blockIdx.x;
    int i = threadIdx.x;
    float invf = 1.0f / powf(10000.0f, (float)i / 256.0f);
    float angf = (float)s * invf;
    double ang = (double)angf;
    g_sin[s * 256 + i] = (float)sin(ang);
    g_cos[s * 256 + i] = (float)cos(ang);
}

__global__ void bias_prep(const float* __restrict__ pos, float* __restrict__ out, int mode)
{
    int n = blockIdx.x, t = threadIdx.x;
    for (int c = t; c < 1024; c += 256) {
        float p = pos[n * 1024 + c];
        out[n * 1024 + c] = (mode == 1) ? logf(p) : (logf(p) - log1pf(-p));
    }
}

__global__ void softmax1024_planes(const __half* __restrict__ S, const float* __restrict__ bias,
                                   __half* __restrict__ oh)
{
    const int row = blockIdx.x, t = threadIdx.x;
    const __half* sr = S + (size_t)row * 1024;
    const float* pb = bias + (size_t)(row >> 10) * 1024;
    __half2 a  = *(const __half2*)&sr[2 * t];
    __half2 b2 = *(const __half2*)&sr[512 + 2 * t];
    float2 ba = *(const float2*)&pb[2 * t];
    float2 bb = *(const float2*)&pb[512 + 2 * t];
    float v0 = __low2float(a) + ba.x,  v1 = __high2float(a) + ba.y;
    float v2 = __low2float(b2) + bb.x, v3 = __high2float(b2) + bb.y;

    __shared__ float red[256];
    float mx = fmaxf(fmaxf(v0, v1), fmaxf(v2, v3));
    red[t] = mx; __syncthreads();
    for (int s = 128; s > 0; s >>= 1) { if (t < s) red[t] = fmaxf(red[t], red[t + s]); __syncthreads(); }
    mx = red[0]; __syncthreads();

    float e0 = expf(v0 - mx), e1 = expf(v1 - mx), e2 = expf(v2 - mx), e3 = expf(v3 - mx);
    red[t] = e0 + e1 + e2 + e3; __syncthreads();
    for (int s = 128; s > 0; s >>= 1) { if (t < s) red[t] += red[t + s]; __syncthreads(); }
    float inv = 1.0f / red[0];

    size_t o = (size_t)row * 1024 + 2 * t;
    *(__half2*)&oh[o]       = __floats2half2_rn(e0 * inv, e1 * inv);
    *(__half2*)&oh[o + 512] = __floats2half2_rn(e2 * inv, e3 * inv);
}

__global__ void softmax64_planes(const float* __restrict__ S, __half* __restrict__ oh)
{
    const int row = blockIdx.x * 8 + (threadIdx.x >> 5);
    const int lane = threadIdx.x & 31;
    const float* sr = S + (size_t)row * 64;
    float2 v = *(const float2*)&sr[lane * 2];
    float mx = fmaxf(v.x, v.y);
#pragma unroll
    for (int o = 16; o > 0; o >>= 1)
        mx = fmaxf(mx, __shfl_xor_sync(0xFFFFFFFF, mx, o));
    float e0 = expf(v.x - mx), e1 = expf(v.y - mx);
    float s = e0 + e1;
#pragma unroll
    for (int o = 16; o > 0; o >>= 1)
        s += __shfl_xor_sync(0xFFFFFFFF, s, o);
    float inv = 1.0f / s;
    *(__half2*)&oh[(size_t)row * 64 + lane * 2] = __floats2half2_rn(e0 * inv, e1 * inv);
}

__global__ void softmax_f32(float* __restrict__ S, const float* __restrict__ bias,
                            int cols, int rpb)
{
    int row = blockIdx.x;
    float* sr = S + (size_t)row * cols;
    const float* pb = bias + (size_t)(row / rpb) * cols;
    int t = threadIdx.x;
    __shared__ float red[256];

    float mx = -1e30f;
    for (int c = t; c < cols; c += 256) {
        float v = sr[c] + pb[c];
        sr[c] = v;
        mx = fmaxf(mx, v);
    }
    red[t] = mx; __syncthreads();
    for (int s = 128; s > 0; s >>= 1) { if (t < s) red[t] = fmaxf(red[t], red[t + s]); __syncthreads(); }
    mx = red[0]; __syncthreads();

    float sum = 0.0f;
    for (int c = t; c < cols; c += 256) {
        float e = expf(sr[c] - mx);
        sr[c] = e;
        sum += e;
    }
    red[t] = sum; __syncthreads();
    for (int s = 128; s > 0; s >>= 1) { if (t < s) red[t] += red[t + s]; __syncthreads(); }
    float inv = 1.0f / red[0];
    for (int c = t; c < cols; c += 256) sr[c] *= inv;
}

__global__ void ln_kernel(const float* __restrict__ Xin, const float* __restrict__ R,
                          const float* __restrict__ g, const float* __restrict__ b,
                          float* __restrict__ Xout,
                          __half* __restrict__ oh, long long lo)
{
    int row = blockIdx.x;
    int t   = threadIdx.x;
    const float* xr = Xin + (size_t)row * DD;
    const float* rr = R + (size_t)row * DD;

    float v0 = xr[2 * t] + rr[2 * t];
    float v1 = xr[2 * t + 1] + rr[2 * t + 1];

    __shared__ float red[256];
    red[t] = v0 + v1; __syncthreads();
    for (int s = 128; s > 0; s >>= 1) { if (t < s) red[t] += red[t + s]; __syncthreads(); }
    float m = red[0] * (1.0f / 512.0f);
    __syncthreads();

    float d0 = v0 - m, d1 = v1 - m;
    red[t] = d0 * d0 + d1 * d1; __syncthreads();
    for (int s = 128; s > 0; s >>= 1) { if (t < s) red[t] += red[t + s]; __syncthreads(); }
    float var = red[0] * (1.0f / 512.0f);
    float inv = rsqrtf(var + 1e-5f);

    float o0 = d0 * inv * g[2 * t]     + b[2 * t];
    float o1 = d1 * inv * g[2 * t + 1] + b[2 * t + 1];
    float* xo = Xout + (size_t)row * DD;
    xo[2 * t]     = o0;
    xo[2 * t + 1] = o1;

    __half2 h, l;
    split_pair(o0, o1, h, l);
    size_t o = (size_t)row * DD + 2 * t;
    *(__half2*)&oh[o] = h;
    *(__half2*)&(oh + lo)[o] = l;
}

__global__ void vgate_kernel(const float* __restrict__ F, const float* __restrict__ raw,
                             const float* __restrict__ Wig, const float* __restrict__ big,
                             float* __restrict__ V)
{
    int row = blockIdx.x;
    int t   = threadIdx.x;
    const float* fr = F + (size_t)row * DD;
    __shared__ float red[256];
    float s = fr[t] * Wig[t] + fr[t + 256] * Wig[t + 256];
    red[t] = s; __syncthreads();
    for (int k = 128; k > 0; k >>= 1) { if (t < k) red[t] += red[t + k]; __syncthreads(); }
    float gte = 1.0f / (1.0f + expf(-(red[0] + big[0])));
    const float* rr = raw + (size_t)row * DD;
    float* vr = V + (size_t)row * DD;
    vr[t]       = rr[t]       * gte;
    vr[t + 256] = rr[t + 256] * gte;
}

__global__ void out_kernel(const float* __restrict__ FU, const float* __restrict__ A2,
                           const float* __restrict__ PD,
                           const float* __restrict__ Wu1, const float* __restrict__ bu1,
                           const float* __restrict__ Wu2, const float* __restrict__ bu2,
                           const float* __restrict__ b1,
                           float* __restrict__ out, float* __restrict__ gate)
{
    int row = blockIdx.x;
    int t   = threadIdx.x;
    const float* fu = FU + (size_t)row * DD;
    const float* a2 = A2 + (size_t)row * DD;
    const float* pd = PD + (size_t)row * DD;

    __shared__ float red[256];
    float s = fu[t] * Wu1[t] + fu[t + 256] * Wu1[t + 256]
            + a2[t] * Wu2[t] + a2[t + 256] * Wu2[t + 256];
    red[t] = s; __syncthreads();
    for (int k = 128; k > 0; k >>= 1) { if (t < k) red[t] += red[t + k]; __syncthreads(); }
    float z = red[0] + bu1[0] + bu2[0] + b1[0] - 4.0f;
    float g = 1.0f / (1.0f + expf(-z));

    float* orow = out + (size_t)row * DD;
    orow[t]       = pd[t]       * (1.0f - g) + a2[t]       * g;
    orow[t + 256] = pd[t + 256] * (1.0f - g) + a2[t + 256] * g;
    if (t == 0) gate[row] = g;
}

#define BM 64
#define BN 64
#define BK 16

__global__ void gemm_kernel(const float* __restrict__ A,
                            const float* __restrict__ Bm,
                            const float* __restrict__ bias,
                            float* __restrict__ C,
                            int M, int N, int K,
                            long long sA, long long sB, long long sC,
                            float alpha, int transB, int epi)
{
    const int bz = blockIdx.z;
    A  += (size_t)bz * sA;
    Bm += (size_t)bz * sB;
    C  += (size_t)bz * sC;

    const int m0 = blockIdx.y * BM;
    const int n0 = blockIdx.x * BN;

    __shared__ float As[BK][BM + 4];
    __shared__ float Bs[BK][BN + 4];

    const int t  = threadIdx.x;
    const int tx = t & 15;
    const int ty = t >> 4;

    float acc[4][4] = {};

    const int arow = t >> 2;
    const int akc  = (t & 3) * 4;
    const int kb   = t >> 4;
    const int nb   = (t & 15) * 4;

    for (int k0 = 0; k0 < K; k0 += BK) {
        float4 av = *(const float4*)&A[(size_t)(m0 + arow) * K + k0 + akc];
        As[akc + 0][arow] = av.x;
        As[akc + 1][arow] = av.y;
        As[akc + 2][arow] = av.z;
        As[akc + 3][arow] = av.w;

        if (!transB) {
            float4 bv = *(const float4*)&Bm[(size_t)(k0 + kb) * N + n0 + nb];
            *(float4*)&Bs[kb][nb] = bv;
        } else {
            float4 bv = *(const float4*)&Bm[(size_t)(n0 + arow) * K + k0 + akc];
            Bs[akc + 0][arow] = bv.x;
            Bs[akc + 1][arow] = bv.y;
            Bs[akc + 2][arow] = bv.z;
            Bs[akc + 3][arow] = bv.w;
        }
        __syncthreads();

#pragma unroll
        for (int k = 0; k < BK; k++) {
            float4 a = *(const float4*)&As[k][ty * 4];
            float4 b = *(const float4*)&Bs[k][tx * 4];
            acc[0][0] += a.x * b.x; acc[0][1] += a.x * b.y;
            acc[0][2] += a.x * b.z; acc[0][3] += a.x * b.w;
            acc[1][0] += a.y * b.x; acc[1][1] += a.y * b.y;
            acc[1][2] += a.y * b.z; acc[1][3] += a.y * b.w;
            acc[2][0] += a.z * b.x; acc[2][1] += a.z * b.y;
            acc[2][2] += a.z * b.z; acc[2][3] += a.z * b.w;
            acc[3][0] += a.w * b.x; acc[3][1] += a.w * b.y;
            acc[3][2] += a.w * b.z; acc[3][3] += a.w * b.w;
        }
        __syncthreads();
    }

#pragma unroll
    for (int i = 0; i < 4; i++) {
        const int row = m0 + ty * 4 + i;
        float v[4];
#pragma unroll
        for (int j = 0; j < 4; j++) {
            float x = acc[i][j] * alpha;
            if (bias) x += bias[n0 + tx * 4 + j];
            v[j] = x;
        }
        *(float4*)&C[(size_t)row * N + n0 + tx * 4] = make_float4(v[0], v[1], v[2], v[3]);
    }
}

static void sgemm_launch(const float* A, const float* B, const float* bias, float* C,
                         int M, int N, int K, int batch,
                         long long sA, long long sB, long long sC,
                         float alpha, int transB, cudaStream_t st)
{
    dim3 grid(N / BN, M / BM, batch);
    gemm_kernel<<<grid, 256, 0, st>>>(A, B, bias, C, M, N, K, sA, sB, sC, alpha, transB, 0);
}

// ---------------------------------------------------------------------------
// Encoder (stream + private buffers). QKV 1-term (V emitted fp16); Wo/FF 3-term.
// ---------------------------------------------------------------------------
static void run_encoder(const float* Xin0, float* X, int nb,
                        const __half* initHi,
                        const float* biasRows, const __half* PW,
                        const float* bqkv, const float* bo,
                        const float* ln, const float* bff,
                        __half* bVh, float* bK, __half* Sh,
                        __half* Pq, __half* Pk, __half* Pvt,
                        __half* Pp, __half* Pbq, __half* Ph,
                        __half* Px, long long lo, cudaStream_t st)
{
    const int rows = nb * SS;
    const float sc = 1.0f / sqrtf((float)DD);
    for (int l = 0; l < 2; l++) {
        const __half* AP = (l == 0) ? initHi : Px;
        // QKV (1-term, rope epilogue, V -> fp16 row-major)
        tg1(AP, 0, PW + (size_t)(l * 3) * 262144, 0,
            bqkv + (size_t)l * 1536, (float*)bVh, 0, Pq, Pk, 0, 0,
            rows, 1536, 512, 1, 1.0f, 2, st);
        // V transpose fp16 -> fp16 hi plane
        trans_conv_h<<<dim3(16, 32, nb), dim3(32, 8), 0, st>>>(bVh, Pvt, 1024, 512,
                                                               524288, 524288);
        // scores = Q @ K^T * sc -> fp16 raw
        tg1(Pq, 524288, Pk, 524288, nullptr, nullptr, 0, Sh, nullptr, 0, 1048576,
            1024, 1024, 512, nb, sc, 0, st);
        softmax1024_planes<<<rows, 256, 0, st>>>(Sh, biasRows, Pp);
        // T = A @ V (1-term) -> hi+lo planes
        tg1(Pp, 1048576, Pvt, 524288, nullptr, nullptr, 0, Pbq, nullptr, lo, 524288,
            1024, 512, 1024, nb, 1.0f, 0, st);
        // O = T @ Wo + bo (3-term)
        tg3(Pbq, lo, 0, PW + (size_t)(6 + l) * 262144, WLO, 0, bo + l * 512,
            bK, 0, nullptr, 0, 0, rows, 512, 512, 1, 1.0f, 0, st);
        ln_kernel<<<rows, 256, 0, st>>>((l == 0) ? Xin0 : X, bK,
                                        ln + l * 2048, ln + l * 2048 + 512, X, Px, lo);
        tg3(Px, lo, 0, PW + (size_t)(8 + 2 * l) * 262144, WLO, 0, bff + l * 1024,
            nullptr, 0, Ph, lo, 0, rows, 512, 512, 1, 1.0f, 1, st);
        tg3(Ph, lo, 0, PW + (size_t)(9 + 2 * l) * 262144, WLO, 0, bff + l * 1024 + 512,
            bK, 0, nullptr, 0, 0, rows, 512, 512, 1, 1.0f, 0, st);
        ln_kernel<<<rows, 256, 0, st>>>(X, bK, ln + l * 2048 + 1024, ln + l * 2048 + 1536,
                                        X, Px, lo);
    }
}

extern "C" void kernel_launch(void* const* d_in, const int* in_sizes, int n_in,
                              void* d_out, int out_size)
{
    const float* raw_emb   = (const float*)d_in[0];
    const float* pos_w     = (const float*)d_in[1];
    const float* post_dec  = (const float*)d_in[2];
    const float* pos_r     = (const float*)d_in[3];
    const float* questions = (const float*)d_in[4];
    const float* W_k       = (const float*)d_in[5];
    const float* W_ig      = (const float*)d_in[6];
    const float* b_ig      = (const float*)d_in[7];
    const float* W_u1      = (const float*)d_in[8];
    const float* b_u1      = (const float*)d_in[9];
    const float* W_u2      = (const float*)d_in[10];
    const float* b_u2      = (const float*)d_in[11];
    const float* b1        = (const float*)d_in[12];
    const float* W_ok      = (const float*)d_in[13];
    const float* b_ok      = (const float*)d_in[14];
    const float* encw_Wqkv = (const float*)d_in[15];
    const float* encw_bqkv = (const float*)d_in[16];
    const float* encw_Wo   = (const float*)d_in[17];
    const float* encw_bo   = (const float*)d_in[18];
    const float* encw_ln   = (const float*)d_in[19];
    const float* encw_Wff  = (const float*)d_in[20];
    const float* encw_bff  = (const float*)d_in[21];
    const float* encr_Wqkv = (const float*)d_in[22];
    const float* encr_bqkv = (const float*)d_in[23];
    const float* encr_Wo   = (const float*)d_in[24];
    const float* encr_bo   = (const float*)d_in[25];
    const float* encr_ln   = (const float*)d_in[26];
    const float* encr_Wff  = (const float*)d_in[27];
    const float* encr_bff  = (const float*)d_in[28];
    const int*   lookup    = (const int*)d_in[29];

    float* out  = (float*)d_out;
    float* gate = out + (size_t)NBB * SS * DD;

    float *pX, *pK, *pXw, *pKw, *pS1, *pKd, *pVd, *pA1, *pA2s, *pA2, *pBW, *pBR;
    __half *pPW, *pPraw, *pPpd, *pPx, *pPq, *pPk, *pVh, *pPvt, *pPp, *pPbq, *pPh, *pSh;
    __half *pPxw, *pPqw, *pPkw, *pVhw, *pPvtw, *pPpw, *pPbqw, *pPhw, *pShw;
    __half *pPk2, *pPa2, *pPsel, *pPqst;
    cudaGetSymbolAddress((void**)&pX,    g_X);
    cudaGetSymbolAddress((void**)&pK,    g_Kb);
    cudaGetSymbolAddress((void**)&pXw,   g_Xw);
    cudaGetSymbolAddress((void**)&pKw,   g_Kw);
    cudaGetSymbolAddress((void**)&pS1,   g_S1);
    cudaGetSymbolAddress((void**)&pKd,   g_Kdoc);
    cudaGetSymbolAddress((void**)&pVd,   g_Vdoc);
    cudaGetSymbolAddress((void**)&pA1,   g_A1S);
    cudaGetSymbolAddress((void**)&pA2s,  g_A2SC);
    cudaGetSymbolAddress((void**)&pA2,   g_A2);
    cudaGetSymbolAddress((void**)&pBW,   g_BIASW);
    cudaGetSymbolAddress((void**)&pBR,   g_BIASR);
    cudaGetSymbolAddress((void**)&pPW,   g_PW);
    cudaGetSymbolAddress((void**)&pPraw, g_Praw);
    cudaGetSymbolAddress((void**)&pPpd,  g_Ppd);
    cudaGetSymbolAddress((void**)&pPx,   g_Px);
    cudaGetSymbolAddress((void**)&pPq,   g_Pq);
    cudaGetSymbolAddress((void**)&pPk,   g_Pk);
    cudaGetSymbolAddress((void**)&pVh,   g_Vh);
    cudaGetSymbolAddress((void**)&pPvt,  g_Pvt);
    cudaGetSymbolAddress((void**)&pPp,   g_Pp);
    cudaGetSymbolAddress((void**)&pPbq,  g_Pbq);
    cudaGetSymbolAddress((void**)&pPh,   g_Ph);
    cudaGetSymbolAddress((void**)&pSh,   g_Sh);
    cudaGetSymbolAddress((void**)&pPxw,  g_Pxw);
    cudaGetSymbolAddress((void**)&pPqw,  g_Pqw);
    cudaGetSymbolAddress((void**)&pPkw,  g_Pkw);
    cudaGetSymbolAddress((void**)&pVhw,  g_Vhw);
    cudaGetSymbolAddress((void**)&pPvtw, g_Pvtw);
    cudaGetSymbolAddress((void**)&pPpw,  g_Ppw);
    cudaGetSymbolAddress((void**)&pPbqw, g_Pbqw);
    cudaGetSymbolAddress((void**)&pPhw,  g_Phw);
    cudaGetSymbolAddress((void**)&pShw,  g_Shw);
    cudaGetSymbolAddress((void**)&pPk2,  g_Pk2);
    cudaGetSymbolAddress((void**)&pPa2,  g_Pa2);
    cudaGetSymbolAddress((void**)&pPsel, g_Psel);
    cudaGetSymbolAddress((void**)&pPqst, g_Pqst);

    cudaFuncSetAttribute(tgemm3,    cudaFuncAttributeMaxDynamicSharedMemorySize, TG_SMEM);
    cudaFuncSetAttribute(tgemm1,    cudaFuncAttributeMaxDynamicSharedMemorySize, T1_SMEM);
    cudaFuncSetAttribute(tgemm1n64, cudaFuncAttributeMaxDynamicSharedMemorySize, T1N_SMEM);

    const float scD = 1.0f / sqrtf((float)DD);

    cudaStream_t s2;
    cudaStreamCreateWithFlags(&s2, cudaStreamNonBlocking);
    cudaEvent_t evF, evJ;
    cudaEventCreateWithFlags(&evF, cudaEventDisableTiming);
    cudaEventCreateWithFlags(&evJ, cudaEventDisableTiming);
    cudaStream_t s0 = 0;

    // ---- common prep on s0 ----
    rope_table_kernel<<<1024, 256, 0, s0>>>();
    conv_planes<<<NBB * SS, 256, 0, s0>>>(post_dec, pPpd, 0);

    cudaEventRecord(evF, s0);
    cudaStreamWaitEvent(s2, evF, 0);

    // ================= s2: write side + independent k2/a2 path =============
    trans_conv<<<dim3(16, 16, 6), dim3(32, 8), 0, s2>>>(encw_Wqkv, pPW + 0LL * 262144, WLO, 512, 512, 262144, 262144, nullptr);
    trans_conv<<<dim3(16, 16, 2), dim3(32, 8), 0, s2>>>(encw_Wo,   pPW + 6LL * 262144, WLO, 512, 512, 262144, 262144, nullptr);
    trans_conv<<<dim3(16, 16, 4), dim3(32, 8), 0, s2>>>(encw_Wff,  pPW + 8LL * 262144, WLO, 512, 512, 262144, 262144, nullptr);
    conv_planes<<<NDOC * SS, 256, 0, s2>>>(raw_emb, pPraw, 0);
    bias_prep<<<NDOC, 256, 0, s2>>>(pos_w, pBW, 1);

    run_encoder(raw_emb, pXw, NDOC, pPraw, pBW,
                pPW, encw_bqkv, encw_bo, encw_ln, encw_bff,
                pVhw, pKw, pShw, pPqw, pPkw, pPvtw, pPpw, pPbqw, pPhw, pPxw,
                LOW, s2);

    vgate_kernel<<<NDOC * SS, 256, 0, s2>>>(pXw, raw_emb, W_ig, b_ig, pVd);
    trans_conv<<<dim3(16, 16, 1), dim3(32, 8), 0, s2>>>(W_k, pPW + 24LL * 262144, WLO, 512, 512, 262144, 262144, nullptr);
    tg1(pPraw, 0, pPW + 24LL * 262144, 0, nullptr, pKd, 0, nullptr, nullptr, 0, 0,
        NDOC * SS, 512, 512, 1, 1.0f, 0, s2);
    sgemm_launch(questions, pKd, nullptr, pS1, QQ, SS, DD, NDOC, 0, 524288, 65536, scD, 1, s2);
    softmax_f32<<<NDOC * QQ, 256, 0, s2>>>(pS1, pBW, SS, QQ);
    sgemm_launch(pS1, pVd, nullptr, pA1, QQ, DD, SS, NDOC, 65536, 524288, 32768, 1.0f, 0, s2);
    trans_conv<<<dim3(16, 2, 16), dim3(32, 8), 0, s2>>>(pA1, pPsel, 0, 64, 512, 32768, 32768, lookup);

    // independent k2/a2/A2 chain
    trans_conv<<<dim3(16, 16, 1), dim3(32, 8), 0, s2>>>(W_ok, pPW + 25LL * 262144, WLO, 512, 512, 262144, 262144, nullptr);
    conv_planes<<<QQ, 256, 0, s2>>>(questions, pPqst, 0);
    tg1(pPpd, 0, pPW + 25LL * 262144, 0, b_ok, nullptr, 0, pPk2, nullptr, 0, 0,
        NBB * SS, 512, 512, 1, 1.0f, 0, s2);
    {
        dim3 grid(1, (NBB * SS) / 128, 1);
        tgemm1n64<<<grid, 256, T1N_SMEM, s2>>>(pPk2, pPqst, pA2s, NBB * SS, QQ, DD, 0.125f);
    }
    softmax64_planes<<<NBB * SS / 8, 256, 0, s2>>>(pA2s, pPa2);
    tg1(pPa2, 65536, pPsel, 32768, nullptr, pA2, 524288, nullptr, nullptr, 0, 0,
        1024, 512, 64, NBB, 1.0f, 0, s2);

    cudaEventRecord(evJ, s2);

    // ================= s0: read-side encoder (long pole) ====================
    trans_conv<<<dim3(16, 16, 6), dim3(32, 8), 0, s0>>>(encr_Wqkv, pPW + 12LL * 262144, WLO, 512, 512, 262144, 262144, nullptr);
    trans_conv<<<dim3(16, 16, 2), dim3(32, 8), 0, s0>>>(encr_Wo,   pPW + 18LL * 262144, WLO, 512, 512, 262144, 262144, nullptr);
    trans_conv<<<dim3(16, 16, 4), dim3(32, 8), 0, s0>>>(encr_Wff,  pPW + 20LL * 262144, WLO, 512, 512, 262144, 262144, nullptr);
    bias_prep<<<NBB, 256, 0, s0>>>(pos_r, pBR, 2);

    run_encoder(post_dec, pX, NBB, pPpd, pBR,
                pPW + 12LL * 262144, encr_bqkv, encr_bo, encr_ln, encr_bff,
                pVh, pK, pSh, pPq, pPk, pPvt, pPp, pPbq, pPh, pPx,
                LO, s0);

    // join + final
    cudaStreamWaitEvent(s0, evJ, 0);
    out_kernel<<<NBB * SS, 256, 0, s0>>>(pX, pA2, post_dec,
                                         W_u1, b_u1, W_u2, b_u2, b1,
                                         out, gate);

    (void)in_sizes; (void)n_in; (void)out_size;
}

// round 15
// speedup vs baseline: 1.0718x; 1.0086x over previous
#include <cuda_runtime.h>
#include <cuda_fp16.h>
#include <math.h>
#include <stdint.h>

#define DD     512
#define SS     1024
#define NBB    16
#define QQ     64
#define NDOC   8

// ---- read-side f32 scratch ----
__device__ float g_X   [16384 * 512];
__device__ float g_Kb  [16384 * 512];
// ---- write-side f32 scratch ----
__device__ float g_Xw  [8192 * 512];
__device__ float g_Kw  [8192 * 512];
__device__ float g_S1  [8 * 64 * 1024];
__device__ float g_Kdoc[8192 * 512];
__device__ float g_Vdoc[8192 * 512];
__device__ float g_A1S [8 * 64 * 512];
__device__ float g_A2SC[16384 * 64];
__device__ float g_A2  [16384 * 512];
__device__ float g_sin [1024 * 256];
__device__ float g_cos [1024 * 256];
__device__ float g_BIASW[8 * 1024];
__device__ float g_BIASR[16 * 1024];

#define WLO 6815744LL
#define LO  8388608LL
#define LOW 4194304LL
__device__ __align__(16) __half g_PW  [2 * 26 * 262144];
__device__ __align__(16) __half g_Praw[4194304];
__device__ __align__(16) __half g_Ppd [8388608];
// read-side planes
__device__ __align__(16) __half g_Px  [2 * 8388608];
__device__ __align__(16) __half g_Pq  [8388608];
__device__ __align__(16) __half g_Pk  [8388608];
__device__ __align__(16) __half g_Pvt [8388608];
__device__ __align__(16) __half g_Pp  [16777216];
__device__ __align__(16) __half g_Pbq [2 * 8388608];
__device__ __align__(16) __half g_Ph  [2 * 8388608];
__device__ __align__(16) __half g_Sh  [16 * 1048576];
// write-side planes
__device__ __align__(16) __half g_Pxw [2 * 4194304];
__device__ __align__(16) __half g_Pqw [4194304];
__device__ __align__(16) __half g_Pkw [4194304];
__device__ __align__(16) __half g_Pvtw[4194304];
__device__ __align__(16) __half g_Ppw [8388608];
__device__ __align__(16) __half g_Pbqw[2 * 4194304];
__device__ __align__(16) __half g_Phw [2 * 4194304];
__device__ __align__(16) __half g_Shw [8 * 1048576];
// misc planes
__device__ __align__(16) __half g_Pk2 [8388608];
__device__ __align__(16) __half g_Pa2 [1048576];
__device__ __align__(16) __half g_Psel[524288];
__device__ __align__(16) __half g_Pqst[32768];

__device__ __forceinline__ uint32_t smem_u32(const void* p) {
    uint32_t a;
    asm("{ .reg .u64 t; cvta.to.shared.u64 t, %1; cvt.u32.u64 %0, t; }"
        : "=r"(a) : "l"(p));
    return a;
}

__device__ __forceinline__ void ldsm4(uint32_t* r, uint32_t addr) {
    asm volatile("ldmatrix.sync.aligned.m8n8.x4.shared.b16 {%0,%1,%2,%3}, [%4];"
                 : "=r"(r[0]), "=r"(r[1]), "=r"(r[2]), "=r"(r[3]) : "r"(addr));
}

__device__ __forceinline__ void mma_f16(float* c, const uint32_t* a,
                                        uint32_t b0, uint32_t b1) {
    asm volatile(
        "mma.sync.aligned.m16n8k16.row.col.f32.f16.f16.f32 "
        "{%0,%1,%2,%3}, {%4,%5,%6,%7}, {%8,%9}, {%0,%1,%2,%3};"
        : "+f"(c[0]), "+f"(c[1]), "+f"(c[2]), "+f"(c[3])
        : "r"(a[0]), "r"(a[1]), "r"(a[2]), "r"(a[3]), "r"(b0), "r"(b1));
}

__device__ __forceinline__ void cpasync16(uint32_t dst, const void* src) {
    asm volatile("cp.async.cg.shared.global [%0], [%1], 16;" :: "r"(dst), "l"(src));
}
#define CP_COMMIT() asm volatile("cp.async.commit_group;" ::: "memory")
#define CP_WAIT(n)  asm volatile("cp.async.wait_group %0;" :: "n"(n) : "memory")

__device__ __forceinline__ void split_pair(float x0, float x1,
                                           __half2& h, __half2& l) {
    h = __floats2half2_rn(x0, x1);
    l = __floats2half2_rn(x0 - __low2float(h), x1 - __high2float(h));
}

// ---------------------------------------------------------------------------
// 3-term split GEMM (fp16 planes): residual-path GEMMs (Wo, FF)
// ---------------------------------------------------------------------------
#define PLANE  10240
#define TSTAGE 40960
#define TG_SMEM (4 * 40960)

__global__ void __launch_bounds__(512)
tgemm3(const __half* __restrict__ Ah0, const __half* __restrict__ Bh0,
       const float* __restrict__ bias, float* __restrict__ Cf,
       __half* __restrict__ Ch0,
       int M, int N, int K,
       long long loA, long long loB, long long loC,
       long long sA, long long sB, long long sC, long long sCp,
       float alpha, int epi)
{
    extern __shared__ char smem[];
    const uint32_t sbu = smem_u32(smem);
    const int t = threadIdx.x, w = t >> 5, lane = t & 31;
    const int wm = w & 3, wn = w >> 2;
    const int z = blockIdx.z;
    const int m0 = blockIdx.y * 128, n0 = blockIdx.x * 128;

    const __half* Ah = Ah0 + (size_t)z * sA;
    const __half* Bh = Bh0 + (size_t)z * sB;

    const int lrow = t >> 2, seg = t & 3;
    const __half* pr[4];
    pr[0] = Ah + (size_t)(m0 + lrow) * K + seg * 8;
    pr[1] = pr[0] + loA;
    pr[2] = Bh + (size_t)(n0 + lrow) * K + seg * 8;
    pr[3] = pr[2] + loB;

    float acc[2][4][4];
#pragma unroll
    for (int i = 0; i < 2; i++)
#pragma unroll
        for (int j = 0; j < 4; j++)
#pragma unroll
            for (int e = 0; e < 4; e++) acc[i][j][e] = 0.0f;

    const int nch = K >> 5;
    const uint32_t sdbase = sbu + (uint32_t)(lrow * 80 + seg * 16);

#define ISSUE(ch) do {                                                      \
    uint32_t _sd = sdbase + (uint32_t)((ch) & 3) * TSTAGE;                  \
    const int _cb = (ch) * 32;                                              \
    _Pragma("unroll")                                                       \
    for (int _p = 0; _p < 4; _p++)                                          \
        cpasync16(_sd + _p * PLANE, pr[_p] + _cb);                          \
    CP_COMMIT();                                                            \
} while (0)

    ISSUE(0);
    ISSUE(1);
    if (nch > 2) ISSUE(2);

    const uint32_t lmoff = (uint32_t)((lane & 15) * 80 + (lane >> 4) * 16);

    for (int ch = 0; ch < nch; ch++) {
        const int rem = nch - 1 - ch;
        if (rem >= 2)      { CP_WAIT(2); }
        else if (rem == 1) { CP_WAIT(1); }
        else               { CP_WAIT(0); }
        __syncthreads();
        if (ch + 3 < nch) ISSUE(ch + 3);

        const uint32_t sAh = sbu + (uint32_t)(ch & 3) * TSTAGE;
        const uint32_t sBh = sAh + 2 * PLANE;
#pragma unroll
        for (int kk = 0; kk < 2; kk++) {
            uint32_t ah[2][4], al[2][4], bh[2][4], bl[2][4];
#pragma unroll
            for (int mt = 0; mt < 2; mt++) {
                uint32_t aaddr = sAh + (uint32_t)((wm * 32 + mt * 16) * 80 + kk * 32) + lmoff;
                ldsm4(ah[mt], aaddr);
                ldsm4(al[mt], aaddr + PLANE);
            }
#pragma unroll
            for (int ng = 0; ng < 2; ng++) {
                uint32_t baddr = sBh + (uint32_t)((wn * 32 + ng * 16) * 80 + kk * 32) + lmoff;
                ldsm4(bh[ng], baddr);
                ldsm4(bl[ng], baddr + PLANE);
            }
#pragma unroll
            for (int ng = 0; ng < 2; ng++)
#pragma unroll
                for (int mt = 0; mt < 2; mt++)
#pragma unroll
                    for (int h2 = 0; h2 < 2; h2++)
                        mma_f16(acc[mt][ng * 2 + h2], ah[mt], bh[ng][h2], bh[ng][h2 + 2]);
#pragma unroll
            for (int ng = 0; ng < 2; ng++)
#pragma unroll
                for (int mt = 0; mt < 2; mt++)
#pragma unroll
                    for (int h2 = 0; h2 < 2; h2++)
                        mma_f16(acc[mt][ng * 2 + h2], ah[mt], bl[ng][h2], bl[ng][h2 + 2]);
#pragma unroll
            for (int ng = 0; ng < 2; ng++)
#pragma unroll
                for (int mt = 0; mt < 2; mt++)
#pragma unroll
                    for (int h2 = 0; h2 < 2; h2++)
                        mma_f16(acc[mt][ng * 2 + h2], al[mt], bh[ng][h2], bh[ng][h2 + 2]);
        }
    }
#undef ISSUE

    const float GC = 0.7978845608028654f;
    const int crow = m0 + wm * 32 + (lane >> 2);
    const int ccol = n0 + wn * 32 + (lane & 3) * 2;

    float* Cfz = Cf ? Cf + (size_t)z * sC : (float*)0;
    __half* Chz = Ch0 ? Ch0 + (size_t)z * sCp : (__half*)0;
    __half* Clz = Chz ? Chz + loC : (__half*)0;
#pragma unroll
    for (int mt = 0; mt < 2; mt++) {
#pragma unroll
        for (int n8 = 0; n8 < 4; n8++) {
            const float* c = acc[mt][n8];
            const int col = ccol + n8 * 8;
            float b0 = bias ? bias[col]     : 0.0f;
            float b1 = bias ? bias[col + 1] : 0.0f;
#pragma unroll
            for (int h = 0; h < 2; h++) {
                const int row = crow + mt * 16 + h * 8;
                float x0 = c[h * 2 + 0] * alpha + b0;
                float x1 = c[h * 2 + 1] * alpha + b1;
                if (epi == 1) {
                    x0 = 0.5f * x0 * (1.0f + tanhf(GC * (x0 + 0.044715f * x0 * x0 * x0)));
                    x1 = 0.5f * x1 * (1.0f + tanhf(GC * (x1 + 0.044715f * x1 * x1 * x1)));
                }
                if (Cfz)
                    *(float2*)&Cfz[(size_t)row * N + col] = make_float2(x0, x1);
                if (Chz) {
                    __half2 hh, ll;
                    split_pair(x0, x1, hh, ll);
                    *(__half2*)&Chz[(size_t)row * N + col] = hh;
                    *(__half2*)&Clz[(size_t)row * N + col] = ll;
                }
            }
        }
    }
}

static void tg3(const __half* Ah, long long loA, long long sA,
                const __half* Bh, long long loB, long long sB,
                const float* bias, float* Cf, long long sC,
                __half* Ch, long long loC, long long sCp,
                int M, int N, int K, int batch, float alpha, int epi,
                cudaStream_t st)
{
    dim3 grid(N / 128, M / 128, batch);
    tgemm3<<<grid, 512, TG_SMEM, st>>>(Ah, Bh, bias, Cf, Ch, M, N, K,
                                       loA, loB, loC, sA, sB, sC, sCp, alpha, epi);
}

// ---------------------------------------------------------------------------
// 1-term GEMM (hi planes only). epi: 0 = plain, 2 = QKV rope epilogue
//   epi=2: cols<1024 rope -> Ch0/Ch2 hi planes;
//          cols>=1024 -> V fp16 TRANSPOSED to Cf (as __half*, [D,S] per batch)
// ---------------------------------------------------------------------------
#define T1STAGE 20480
#define T1_SMEM (4 * 20480)

__global__ void __launch_bounds__(512)
tgemm1(const __half* __restrict__ Ah0, const __half* __restrict__ Bh0,
       const float* __restrict__ bias, float* __restrict__ Cf,
       __half* __restrict__ Ch0, __half* __restrict__ Ch2,
       int M, int N, int K, long long loC,
       long long sA, long long sB, long long sC, long long sCp,
       float alpha, int epi)
{
    extern __shared__ char smem[];
    const uint32_t sbu = smem_u32(smem);
    const int t = threadIdx.x, w = t >> 5, lane = t & 31;
    const int wm = w & 3, wn = w >> 2;
    const int z = blockIdx.z;
    const int m0 = blockIdx.y * 128, n0 = blockIdx.x * 128;

    const __half* Ap = Ah0 + (size_t)z * sA + (size_t)(m0 + (t >> 2)) * K + (t & 3) * 8;
    const __half* Bp = Bh0 + (size_t)z * sB + (size_t)(n0 + (t >> 2)) * K + (t & 3) * 8;

    float acc[2][4][4];
#pragma unroll
    for (int i = 0; i < 2; i++)
#pragma unroll
        for (int j = 0; j < 4; j++)
#pragma unroll
            for (int e = 0; e < 4; e++) acc[i][j][e] = 0.0f;

    const int nch = K >> 5;
    const uint32_t sdbase = sbu + (uint32_t)((t >> 2) * 80 + (t & 3) * 16);

#define ISSUE1(ch) do {                                                     \
    uint32_t _sd = sdbase + (uint32_t)((ch) & 3) * T1STAGE;                 \
    const int _cb = (ch) * 32;                                              \
    cpasync16(_sd,         Ap + _cb);                                       \
    cpasync16(_sd + PLANE, Bp + _cb);                                       \
    CP_COMMIT();                                                            \
} while (0)

    ISSUE1(0);
    ISSUE1(1);
    if (nch > 2) ISSUE1(2);

    const uint32_t lmoff = (uint32_t)((lane & 15) * 80 + (lane >> 4) * 16);

    for (int ch = 0; ch < nch; ch++) {
        const int rem = nch - 1 - ch;
        if (rem >= 2)      { CP_WAIT(2); }
        else if (rem == 1) { CP_WAIT(1); }
        else               { CP_WAIT(0); }
        __syncthreads();
        if (ch + 3 < nch) ISSUE1(ch + 3);

        const uint32_t sAh = sbu + (uint32_t)(ch & 3) * T1STAGE;
        const uint32_t sBh = sAh + PLANE;
#pragma unroll
        for (int kk = 0; kk < 2; kk++) {
            uint32_t ah[2][4], bh[2][4];
#pragma unroll
            for (int mt = 0; mt < 2; mt++)
                ldsm4(ah[mt], sAh + (uint32_t)((wm * 32 + mt * 16) * 80 + kk * 32) + lmoff);
#pragma unroll
            for (int ng = 0; ng < 2; ng++)
                ldsm4(bh[ng], sBh + (uint32_t)((wn * 32 + ng * 16) * 80 + kk * 32) + lmoff);
#pragma unroll
            for (int ng = 0; ng < 2; ng++)
#pragma unroll
                for (int mt = 0; mt < 2; mt++)
#pragma unroll
                    for (int h2 = 0; h2 < 2; h2++)
                        mma_f16(acc[mt][ng * 2 + h2], ah[mt], bh[ng][h2], bh[ng][h2 + 2]);
        }
    }
#undef ISSUE1

    const int crow = m0 + wm * 32 + (lane >> 2);
    const int ccol = n0 + wn * 32 + (lane & 3) * 2;

    if (epi == 2) {
        __half* Vt = (__half*)Cf;
#pragma unroll
        for (int mt = 0; mt < 2; mt++) {
#pragma unroll
            for (int n8 = 0; n8 < 4; n8++) {
                const float* c = acc[mt][n8];
                const int col = ccol + n8 * 8;
                float b0 = bias[col], b1 = bias[col + 1];
#pragma unroll
                for (int h = 0; h < 2; h++) {
                    const int row = crow + mt * 16 + h * 8;
                    float x0 = c[h * 2 + 0] + b0;
                    float x1 = c[h * 2 + 1] + b1;
                    if (col < 1024) {
                        const int s = row & (SS - 1);
                        const int i = (col & 511) >> 1;
                        float sn = g_sin[s * 256 + i];
                        float cs = g_cos[s * 256 + i];
                        float y0 = x0 * cs - x1 * sn;
                        float y1 = x0 * sn + x1 * cs;
                        __half* dst = (col < 512) ? Ch0 : Ch2;
                        size_t off = (size_t)row * 512 + (col & 511);
                        *(__half2*)&dst[off] = __floats2half2_rn(y0, y1);
                    } else {
                        // V transposed: [D, S] per batch, stride 524288
                        const int b = row >> 10, srow = row & 1023;
                        size_t base = (size_t)b * 524288 +
                                      (size_t)(col - 1024) * 1024 + srow;
                        Vt[base]        = __float2half_rn(x0);
                        Vt[base + 1024] = __float2half_rn(x1);
                    }
                }
            }
        }
        return;
    }

    float* Cfz = Cf ? Cf + (size_t)z * sC : (float*)0;
    __half* Chz = Ch0 ? Ch0 + (size_t)z * sCp : (__half*)0;
    __half* Clz = (Chz && loC) ? Chz + loC : (__half*)0;
#pragma unroll
    for (int mt = 0; mt < 2; mt++) {
#pragma unroll
        for (int n8 = 0; n8 < 4; n8++) {
            const float* c = acc[mt][n8];
            const int col = ccol + n8 * 8;
            float b0 = bias ? bias[col]     : 0.0f;
            float b1 = bias ? bias[col + 1] : 0.0f;
#pragma unroll
            for (int h = 0; h < 2; h++) {
                const int row = crow + mt * 16 + h * 8;
                float x0 = c[h * 2 + 0] * alpha + b0;
                float x1 = c[h * 2 + 1] * alpha + b1;
                if (Cfz)
                    *(float2*)&Cfz[(size_t)row * N + col] = make_float2(x0, x1);
                if (Chz) {
                    __half2 hh, ll;
                    split_pair(x0, x1, hh, ll);
                    *(__half2*)&Chz[(size_t)row * N + col] = hh;
                    if (Clz) *(__half2*)&Clz[(size_t)row * N + col] = ll;
                }
            }
        }
    }
}

static void tg1(const __half* Ah, long long sA, const __half* Bh, long long sB,
                const float* bias, float* Cf, long long sC,
                __half* Ch, __half* Ch2, long long loC, long long sCp,
                int M, int N, int K, int batch, float alpha, int epi,
                cudaStream_t st)
{
    dim3 grid(N / 128, M / 128, batch);
    tgemm1<<<grid, 512, T1_SMEM, st>>>(Ah, Bh, bias, Cf, Ch, Ch2, M, N, K, loC,
                                       sA, sB, sC, sCp, alpha, epi);
}

// 1-term, N-tile 64
#define B1STAGE 15360
#define T1N_SMEM (4 * 15360)

__global__ void __launch_bounds__(256)
tgemm1n64(const __half* __restrict__ Ah0, const __half* __restrict__ Bh0,
          float* __restrict__ Cf, int M, int N, int K, float alpha)
{
    extern __shared__ char smem[];
    const uint32_t sbu = smem_u32(smem);
    const int t = threadIdx.x, w = t >> 5, lane = t & 31;
    const int wm = w & 3, wn = w >> 2;
    const int m0 = blockIdx.y * 128, n0 = blockIdx.x * 64;

    const int arow = t >> 1, aseg = (t & 1) * 2;
    const int brow = t >> 2, bseg = t & 3;
    const __half* pa = Ah0 + (size_t)(m0 + arow) * K + aseg * 8;
    const __half* pb = Bh0 + (size_t)(n0 + brow) * K + bseg * 8;
    const uint32_t adst = sbu + (uint32_t)(arow * 80 + aseg * 16);
    const uint32_t bdst = sbu + 10240u + (uint32_t)(brow * 80 + bseg * 16);

    float acc[2][4][4];
#pragma unroll
    for (int i = 0; i < 2; i++)
#pragma unroll
        for (int j = 0; j < 4; j++)
#pragma unroll
            for (int e = 0; e < 4; e++) acc[i][j][e] = 0.0f;

    const int nch = K >> 5;

#define ISSUEN(ch) do {                                                     \
    uint32_t _st = (uint32_t)((ch) & 3) * B1STAGE;                          \
    const int _cb = (ch) * 32;                                              \
    cpasync16(adst + _st,      pa + _cb);                                   \
    cpasync16(adst + _st + 16, pa + _cb + 8);                               \
    cpasync16(bdst + _st,      pb + _cb);                                   \
    CP_COMMIT();                                                            \
} while (0)

    ISSUEN(0);
    ISSUEN(1);
    if (nch > 2) ISSUEN(2);

    const uint32_t lmoff = (uint32_t)((lane & 15) * 80 + (lane >> 4) * 16);

    for (int ch = 0; ch < nch; ch++) {
        const int rem = nch - 1 - ch;
        if (rem >= 2)      { CP_WAIT(2); }
        else if (rem == 1) { CP_WAIT(1); }
        else               { CP_WAIT(0); }
        __syncthreads();
        if (ch + 3 < nch) ISSUEN(ch + 3);

        const uint32_t sAh = sbu + (uint32_t)(ch & 3) * B1STAGE;
        const uint32_t sBh = sAh + 10240u;
#pragma unroll
        for (int kk = 0; kk < 2; kk++) {
            uint32_t ah[2][4], bh[2][4];
#pragma unroll
            for (int mt = 0; mt < 2; mt++)
                ldsm4(ah[mt], sAh + (uint32_t)((wm * 32 + mt * 16) * 80 + kk * 32) + lmoff);
#pragma unroll
            for (int ng = 0; ng < 2; ng++)
                ldsm4(bh[ng], sBh + (uint32_t)((wn * 32 + ng * 16) * 80 + kk * 32) + lmoff);
#pragma unroll
            for (int ng = 0; ng < 2; ng++)
#pragma unroll
                for (int mt = 0; mt < 2; mt++)
#pragma unroll
                    for (int h2 = 0; h2 < 2; h2++)
                        mma_f16(acc[mt][ng * 2 + h2], ah[mt], bh[ng][h2], bh[ng][h2 + 2]);
        }
    }
#undef ISSUEN

    const int crow = m0 + wm * 32 + (lane >> 2);
    const int ccol = n0 + wn * 32 + (lane & 3) * 2;
#pragma unroll
    for (int mt = 0; mt < 2; mt++)
#pragma unroll
        for (int n8 = 0; n8 < 4; n8++) {
            const float* c = acc[mt][n8];
            const int col = ccol + n8 * 8;
#pragma unroll
            for (int h = 0; h < 2; h++) {
                const int row = crow + mt * 16 + h * 8;
                *(float2*)&Cf[(size_t)row * N + col] =
                    make_float2(c[h * 2] * alpha, c[h * 2 + 1] * alpha);
            }
        }
}

// ---------------------------------------------------------------------------
__global__ void trans_conv(const float* __restrict__ in, __half* __restrict__ oh,
                           long long loOff, int R, int C,
                           long long sI, long long sO, const int* __restrict__ ids)
{
    __shared__ float tile[32][33];
    const int z = blockIdx.z;
    size_t ib = ids ? (size_t)ids[z] * sI : (size_t)z * sI;
    const float* ip = in + ib;
    __half* ohz = oh + (size_t)z * sO;
    __half* olz = loOff ? ohz + loOff : (__half*)0;
    const int c0 = blockIdx.x * 32, r0 = blockIdx.y * 32;
    const int tx = threadIdx.x, ty = threadIdx.y;
#pragma unroll
    for (int k = 0; k < 32; k += 8)
        tile[ty + k][tx] = ip[(size_t)(r0 + ty + k) * C + c0 + tx];
    __syncthreads();
    const int rr = (tx & 15) * 2, chf = tx >> 4;
#pragma unroll
    for (int k = 0; k < 2; k++) {
        int cc = ty + chf * 8 + k * 16;
        __half2 h, l;
        split_pair(tile[rr][cc], tile[rr + 1][cc], h, l);
        *(__half2*)&ohz[(size_t)(c0 + cc) * R + r0 + rr] = h;
        if (olz) *(__half2*)&olz[(size_t)(c0 + cc) * R + r0 + rr] = l;
    }
}

__global__ void conv_planes(const float* __restrict__ in, __half* __restrict__ oh,
                            long long lo)
{
    size_t idx = (size_t)blockIdx.x * 512 + (size_t)threadIdx.x * 2;
    float2 v = *(const float2*)&in[idx];
    __half2 h, l;
    split_pair(v.x, v.y, h, l);
    *(__half2*)&oh[idx] = h;
    if (lo) *(__half2*)&(oh + lo)[idx] = l;
}

__global__ void rope_table_kernel()
{
    int s = blockIdx.x;
    int i = threadIdx.x;
    float invf = 1.0f / powf(10000.0f, (float)i / 256.0f);
    float angf = (float)s * invf;
    double ang = (double)angf;
    g_sin[s * 256 + i] = (float)sin(ang);
    g_cos[s * 256 + i] = (float)cos(ang);
}

__global__ void bias_prep(const float* __restrict__ pos, float* __restrict__ out, int mode)
{
    int n = blockIdx.x, t = threadIdx.x;
    for (int c = t; c < 1024; c += 256) {
        float p = pos[n * 1024 + c];
        out[n * 1024 + c] = (mode == 1) ? logf(p) : (logf(p) - log1pf(-p));
    }
}

__global__ void softmax1024_planes(const __half* __restrict__ S, const float* __restrict__ bias,
                                   __half* __restrict__ oh)
{
    const int row = blockIdx.x, t = threadIdx.x;
    const __half* sr = S + (size_t)row * 1024;
    const float* pb = bias + (size_t)(row >> 10) * 1024;
    __half2 a  = *(const __half2*)&sr[2 * t];
    __half2 b2 = *(const __half2*)&sr[512 + 2 * t];
    float2 ba = *(const float2*)&pb[2 * t];
    float2 bb = *(const float2*)&pb[512 + 2 * t];
    float v0 = __low2float(a) + ba.x,  v1 = __high2float(a) + ba.y;
    float v2 = __low2float(b2) + bb.x, v3 = __high2float(b2) + bb.y;

    __shared__ float red[256];
    float mx = fmaxf(fmaxf(v0, v1), fmaxf(v2, v3));
    red[t] = mx; __syncthreads();
    for (int s = 128; s > 0; s >>= 1) { if (t < s) red[t] = fmaxf(red[t], red[t + s]); __syncthreads(); }
    mx = red[0]; __syncthreads();

    float e0 = expf(v0 - mx), e1 = expf(v1 - mx), e2 = expf(v2 - mx), e3 = expf(v3 - mx);
    red[t] = e0 + e1 + e2 + e3; __syncthreads();
    for (int s = 128; s > 0; s >>= 1) { if (t < s) red[t] += red[t + s]; __syncthreads(); }
    float inv = 1.0f / red[0];

    size_t o = (size_t)row * 1024 + 2 * t;
    *(__half2*)&oh[o]       = __floats2half2_rn(e0 * inv, e1 * inv);
    *(__half2*)&oh[o + 512] = __floats2half2_rn(e2 * inv, e3 * inv);
}

__global__ void softmax64_planes(const float* __restrict__ S, __half* __restrict__ oh)
{
    const int row = blockIdx.x * 8 + (threadIdx.x >> 5);
    const int lane = threadIdx.x & 31;
    const float* sr = S + (size_t)row * 64;
    float2 v = *(const float2*)&sr[lane * 2];
    float mx = fmaxf(v.x, v.y);
#pragma unroll
    for (int o = 16; o > 0; o >>= 1)
        mx = fmaxf(mx, __shfl_xor_sync(0xFFFFFFFF, mx, o));
    float e0 = expf(v.x - mx), e1 = expf(v.y - mx);
    float s = e0 + e1;
#pragma unroll
    for (int o = 16; o > 0; o >>= 1)
        s += __shfl_xor_sync(0xFFFFFFFF, s, o);
    float inv = 1.0f / s;
    *(__half2*)&oh[(size_t)row * 64 + lane * 2] = __floats2half2_rn(e0 * inv, e1 * inv);
}

__global__ void softmax_f32(float* __restrict__ S, const float* __restrict__ bias,
                            int cols, int rpb)
{
    int row = blockIdx.x;
    float* sr = S + (size_t)row * cols;
    const float* pb = bias + (size_t)(row / rpb) * cols;
    int t = threadIdx.x;
    __shared__ float red[256];

    float mx = -1e30f;
    for (int c = t; c < cols; c += 256) {
        float v = sr[c] + pb[c];
        sr[c] = v;
        mx = fmaxf(mx, v);
    }
    red[t] = mx; __syncthreads();
    for (int s = 128; s > 0; s >>= 1) { if (t < s) red[t] = fmaxf(red[t], red[t + s]); __syncthreads(); }
    mx = red[0]; __syncthreads();

    float sum = 0.0f;
    for (int c = t; c < cols; c += 256) {
        float e = expf(sr[c] - mx);
        sr[c] = e;
        sum += e;
    }
    red[t] = sum; __syncthreads();
    for (int s = 128; s > 0; s >>= 1) { if (t < s) red[t] += red[t + s]; __syncthreads(); }
    float inv = 1.0f / red[0];
    for (int c = t; c < cols; c += 256) sr[c] *= inv;
}

__global__ void ln_kernel(const float* __restrict__ Xin, const float* __restrict__ R,
                          const float* __restrict__ g, const float* __restrict__ b,
                          float* __restrict__ Xout,
                          __half* __restrict__ oh, long long lo)
{
    int row = blockIdx.x;
    int t   = threadIdx.x;
    const float* xr = Xin + (size_t)row * DD;
    const float* rr = R + (size_t)row * DD;

    float v0 = xr[2 * t] + rr[2 * t];
    float v1 = xr[2 * t + 1] + rr[2 * t + 1];

    __shared__ float red[256];
    red[t] = v0 + v1; __syncthreads();
    for (int s = 128; s > 0; s >>= 1) { if (t < s) red[t] += red[t + s]; __syncthreads(); }
    float m = red[0] * (1.0f / 512.0f);
    __syncthreads();

    float d0 = v0 - m, d1 = v1 - m;
    red[t] = d0 * d0 + d1 * d1; __syncthreads();
    for (int s = 128; s > 0; s >>= 1) { if (t < s) red[t] += red[t + s]; __syncthreads(); }
    float var = red[0] * (1.0f / 512.0f);
    float inv = rsqrtf(var + 1e-5f);

    float o0 = d0 * inv * g[2 * t]     + b[2 * t];
    float o1 = d1 * inv * g[2 * t + 1] + b[2 * t + 1];
    float* xo = Xout + (size_t)row * DD;
    xo[2 * t]     = o0;
    xo[2 * t + 1] = o1;

    __half2 h, l;
    split_pair(o0, o1, h, l);
    size_t o = (size_t)row * DD + 2 * t;
    *(__half2*)&oh[o] = h;
    *(__half2*)&(oh + lo)[o] = l;
}

__global__ void vgate_kernel(const float* __restrict__ F, const float* __restrict__ raw,
                             const float* __restrict__ Wig, const float* __restrict__ big,
                             float* __restrict__ V)
{
    int row = blockIdx.x;
    int t   = threadIdx.x;
    const float* fr = F + (size_t)row * DD;
    __shared__ float red[256];
    float s = fr[t] * Wig[t] + fr[t + 256] * Wig[t + 256];
    red[t] = s; __syncthreads();
    for (int k = 128; k > 0; k >>= 1) { if (t < k) red[t] += red[t + k]; __syncthreads(); }
    float gte = 1.0f / (1.0f + expf(-(red[0] + big[0])));
    const float* rr = raw + (size_t)row * DD;
    float* vr = V + (size_t)row * DD;
    vr[t]       = rr[t]       * gte;
    vr[t + 256] = rr[t + 256] * gte;
}

__global__ void out_kernel(const float* __restrict__ FU, const float* __restrict__ A2,
                           const float* __restrict__ PD,
                           const float* __restrict__ Wu1, const float* __restrict__ bu1,
                           const float* __restrict__ Wu2, const float* __restrict__ bu2,
                           const float* __restrict__ b1,
                           float* __restrict__ out, float* __restrict__ gate)
{
    int row = blockIdx.x;
    int t   = threadIdx.x;
    const float* fu = FU + (size_t)row * DD;
    const float* a2 = A2 + (size_t)row * DD;
    const float* pd = PD + (size_t)row * DD;

    __shared__ float red[256];
    float s = fu[t] * Wu1[t] + fu[t + 256] * Wu1[t + 256]
            + a2[t] * Wu2[t] + a2[t + 256] * Wu2[t + 256];
    red[t] = s; __syncthreads();
    for (int k = 128; k > 0; k >>= 1) { if (t < k) red[t] += red[t + k]; __syncthreads(); }
    float z = red[0] + bu1[0] + bu2[0] + b1[0] - 4.0f;
    float g = 1.0f / (1.0f + expf(-z));

    float* orow = out + (size_t)row * DD;
    orow[t]       = pd[t]       * (1.0f - g) + a2[t]       * g;
    orow[t + 256] = pd[t + 256] * (1.0f - g) + a2[t + 256] * g;
    if (t == 0) gate[row] = g;
}

#define BM 64
#define BN 64
#define BK 16

__global__ void gemm_kernel(const float* __restrict__ A,
                            const float* __restrict__ Bm,
                            const float* __restrict__ bias,
                            float* __restrict__ C,
                            int M, int N, int K,
                            long long sA, long long sB, long long sC,
                            float alpha, int transB, int epi)
{
    const int bz = blockIdx.z;
    A  += (size_t)bz * sA;
    Bm += (size_t)bz * sB;
    C  += (size_t)bz * sC;

    const int m0 = blockIdx.y * BM;
    const int n0 = blockIdx.x * BN;

    __shared__ float As[BK][BM + 4];
    __shared__ float Bs[BK][BN + 4];

    const int t  = threadIdx.x;
    const int tx = t & 15;
    const int ty = t >> 4;

    float acc[4][4] = {};

    const int arow = t >> 2;
    const int akc  = (t & 3) * 4;
    const int kb   = t >> 4;
    const int nb   = (t & 15) * 4;

    for (int k0 = 0; k0 < K; k0 += BK) {
        float4 av = *(const float4*)&A[(size_t)(m0 + arow) * K + k0 + akc];
        As[akc + 0][arow] = av.x;
        As[akc + 1][arow] = av.y;
        As[akc + 2][arow] = av.z;
        As[akc + 3][arow] = av.w;

        if (!transB) {
            float4 bv = *(const float4*)&Bm[(size_t)(k0 + kb) * N + n0 + nb];
            *(float4*)&Bs[kb][nb] = bv;
        } else {
            float4 bv = *(const float4*)&Bm[(size_t)(n0 + arow) * K + k0 + akc];
            Bs[akc + 0][arow] = bv.x;
            Bs[akc + 1][arow] = bv.y;
            Bs[akc + 2][arow] = bv.z;
            Bs[akc + 3][arow] = bv.w;
        }
        __syncthreads();

#pragma unroll
        for (int k = 0; k < BK; k++) {
            float4 a = *(const float4*)&As[k][ty * 4];
            float4 b = *(const float4*)&Bs[k][tx * 4];
            acc[0][0] += a.x * b.x; acc[0][1] += a.x * b.y;
            acc[0][2] += a.x * b.z; acc[0][3] += a.x * b.w;
            acc[1][0] += a.y * b.x; acc[1][1] += a.y * b.y;
            acc[1][2] += a.y * b.z; acc[1][3] += a.y * b.w;
            acc[2][0] += a.z * b.x; acc[2][1] += a.z * b.y;
            acc[2][2] += a.z * b.z; acc[2][3] += a.z * b.w;
            acc[3][0] += a.w * b.x; acc[3][1] += a.w * b.y;
            acc[3][2] += a.w * b.z; acc[3][3] += a.w * b.w;
        }
        __syncthreads();
    }

#pragma unroll
    for (int i = 0; i < 4; i++) {
        const int row = m0 + ty * 4 + i;
        float v[4];
#pragma unroll
        for (int j = 0; j < 4; j++) {
            float x = acc[i][j] * alpha;
            if (bias) x += bias[n0 + tx * 4 + j];
            v[j] = x;
        }
        *(float4*)&C[(size_t)row * N + n0 + tx * 4] = make_float4(v[0], v[1], v[2], v[3]);
    }
}

static void sgemm_launch(const float* A, const float* B, const float* bias, float* C,
                         int M, int N, int K, int batch,
                         long long sA, long long sB, long long sC,
                         float alpha, int transB, cudaStream_t st)
{
    dim3 grid(N / BN, M / BM, batch);
    gemm_kernel<<<grid, 256, 0, st>>>(A, B, bias, C, M, N, K, sA, sB, sC, alpha, transB, 0);
}

// ---------------------------------------------------------------------------
// Encoder. QKV 1-term with fused rope + transposed-V epilogue; Wo/FF 3-term.
// ---------------------------------------------------------------------------
static void run_encoder(const float* Xin0, float* X, int nb,
                        const __half* initHi,
                        const float* biasRows, const __half* PW,
                        const float* bqkv, const float* bo,
                        const float* ln, const float* bff,
                        float* bK, __half* Sh,
                        __half* Pq, __half* Pk, __half* Pvt,
                        __half* Pp, __half* Pbq, __half* Ph,
                        __half* Px, long long lo, cudaStream_t st)
{
    const int rows = nb * SS;
    const float sc = 1.0f / sqrtf((float)DD);
    for (int l = 0; l < 2; l++) {
        const __half* AP = (l == 0) ? initHi : Px;
        // QKV (1-term, rope epilogue, V -> fp16 transposed directly into Pvt)
        tg1(AP, 0, PW + (size_t)(l * 3) * 262144, 0,
            bqkv + (size_t)l * 1536, (float*)Pvt, 0, Pq, Pk, 0, 0,
            rows, 1536, 512, 1, 1.0f, 2, st);
        // scores = Q @ K^T * sc -> fp16 raw
        tg1(Pq, 524288, Pk, 524288, nullptr, nullptr, 0, Sh, nullptr, 0, 1048576,
            1024, 1024, 512, nb, sc, 0, st);
        softmax1024_planes<<<rows, 256, 0, st>>>(Sh, biasRows, Pp);
        // T = A @ V (1-term) -> hi+lo planes
        tg1(Pp, 1048576, Pvt, 524288, nullptr, nullptr, 0, Pbq, nullptr, lo, 524288,
            1024, 512, 1024, nb, 1.0f, 0, st);
        // O = T @ Wo + bo (3-term)
        tg3(Pbq, lo, 0, PW + (size_t)(6 + l) * 262144, WLO, 0, bo + l * 512,
            bK, 0, nullptr, 0, 0, rows, 512, 512, 1, 1.0f, 0, st);
        ln_kernel<<<rows, 256, 0, st>>>((l == 0) ? Xin0 : X, bK,
                                        ln + l * 2048, ln + l * 2048 + 512, X, Px, lo);
        tg3(Px, lo, 0, PW + (size_t)(8 + 2 * l) * 262144, WLO, 0, bff + l * 1024,
            nullptr, 0, Ph, lo, 0, rows, 512, 512, 1, 1.0f, 1, st);
        tg3(Ph, lo, 0, PW + (size_t)(9 + 2 * l) * 262144, WLO, 0, bff + l * 1024 + 512,
            bK, 0, nullptr, 0, 0, rows, 512, 512, 1, 1.0f, 0, st);
        ln_kernel<<<rows, 256, 0, st>>>(X, bK, ln + l * 2048 + 1024, ln + l * 2048 + 1536,
                                        X, Px, lo);
    }
}

extern "C" void kernel_launch(void* const* d_in, const int* in_sizes, int n_in,
                              void* d_out, int out_size)
{
    const float* raw_emb   = (const float*)d_in[0];
    const float* pos_w     = (const float*)d_in[1];
    const float* post_dec  = (const float*)d_in[2];
    const float* pos_r     = (const float*)d_in[3];
    const float* questions = (const float*)d_in[4];
    const float* W_k       = (const float*)d_in[5];
    const float* W_ig      = (const float*)d_in[6];
    const float* b_ig      = (const float*)d_in[7];
    const float* W_u1      = (const float*)d_in[8];
    const float* b_u1      = (const float*)d_in[9];
    const float* W_u2      = (const float*)d_in[10];
    const float* b_u2      = (const float*)d_in[11];
    const float* b1        = (const float*)d_in[12];
    const float* W_ok      = (const float*)d_in[13];
    const float* b_ok      = (const float*)d_in[14];
    const float* encw_Wqkv = (const float*)d_in[15];
    const float* encw_bqkv = (const float*)d_in[16];
    const float* encw_Wo   = (const float*)d_in[17];
    const float* encw_bo   = (const float*)d_in[18];
    const float* encw_ln   = (const float*)d_in[19];
    const float* encw_Wff  = (const float*)d_in[20];
    const float* encw_bff  = (const float*)d_in[21];
    const float* encr_Wqkv = (const float*)d_in[22];
    const float* encr_bqkv = (const float*)d_in[23];
    const float* encr_Wo   = (const float*)d_in[24];
    const float* encr_bo   = (const float*)d_in[25];
    const float* encr_ln   = (const float*)d_in[26];
    const float* encr_Wff  = (const float*)d_in[27];
    const float* encr_bff  = (const float*)d_in[28];
    const int*   lookup    = (const int*)d_in[29];

    float* out  = (float*)d_out;
    float* gate = out + (size_t)NBB * SS * DD;

    float *pX, *pK, *pXw, *pKw, *pS1, *pKd, *pVd, *pA1, *pA2s, *pA2, *pBW, *pBR;
    __half *pPW, *pPraw, *pPpd, *pPx, *pPq, *pPk, *pPvt, *pPp, *pPbq, *pPh, *pSh;
    __half *pPxw, *pPqw, *pPkw, *pPvtw, *pPpw, *pPbqw, *pPhw, *pShw;
    __half *pPk2, *pPa2, *pPsel, *pPqst;
    cudaGetSymbolAddress((void**)&pX,    g_X);
    cudaGetSymbolAddress((void**)&pK,    g_Kb);
    cudaGetSymbolAddress((void**)&pXw,   g_Xw);
    cudaGetSymbolAddress((void**)&pKw,   g_Kw);
    cudaGetSymbolAddress((void**)&pS1,   g_S1);
    cudaGetSymbolAddress((void**)&pKd,   g_Kdoc);
    cudaGetSymbolAddress((void**)&pVd,   g_Vdoc);
    cudaGetSymbolAddress((void**)&pA1,   g_A1S);
    cudaGetSymbolAddress((void**)&pA2s,  g_A2SC);
    cudaGetSymbolAddress((void**)&pA2,   g_A2);
    cudaGetSymbolAddress((void**)&pBW,   g_BIASW);
    cudaGetSymbolAddress((void**)&pBR,   g_BIASR);
    cudaGetSymbolAddress((void**)&pPW,   g_PW);
    cudaGetSymbolAddress((void**)&pPraw, g_Praw);
    cudaGetSymbolAddress((void**)&pPpd,  g_Ppd);
    cudaGetSymbolAddress((void**)&pPx,   g_Px);
    cudaGetSymbolAddress((void**)&pPq,   g_Pq);
    cudaGetSymbolAddress((void**)&pPk,   g_Pk);
    cudaGetSymbolAddress((void**)&pPvt,  g_Pvt);
    cudaGetSymbolAddress((void**)&pPp,   g_Pp);
    cudaGetSymbolAddress((void**)&pPbq,  g_Pbq);
    cudaGetSymbolAddress((void**)&pPh,   g_Ph);
    cudaGetSymbolAddress((void**)&pSh,   g_Sh);
    cudaGetSymbolAddress((void**)&pPxw,  g_Pxw);
    cudaGetSymbolAddress((void**)&pPqw,  g_Pqw);
    cudaGetSymbolAddress((void**)&pPkw,  g_Pkw);
    cudaGetSymbolAddress((void**)&pPvtw, g_Pvtw);
    cudaGetSymbolAddress((void**)&pPpw,  g_Ppw);
    cudaGetSymbolAddress((void**)&pPbqw, g_Pbqw);
    cudaGetSymbolAddress((void**)&pPhw,  g_Phw);
    cudaGetSymbolAddress((void**)&pShw,  g_Shw);
    cudaGetSymbolAddress((void**)&pPk2,  g_Pk2);
    cudaGetSymbolAddress((void**)&pPa2,  g_Pa2);
    cudaGetSymbolAddress((void**)&pPsel, g_Psel);
    cudaGetSymbolAddress((void**)&pPqst, g_Pqst);

    cudaFuncSetAttribute(tgemm3,    cudaFuncAttributeMaxDynamicSharedMemorySize, TG_SMEM);
    cudaFuncSetAttribute(tgemm1,    cudaFuncAttributeMaxDynamicSharedMemorySize, T1_SMEM);
    cudaFuncSetAttribute(tgemm1n64, cudaFuncAttributeMaxDynamicSharedMemorySize, T1N_SMEM);

    const float scD = 1.0f / sqrtf((float)DD);

    cudaStream_t s2;
    cudaStreamCreateWithFlags(&s2, cudaStreamNonBlocking);
    cudaEvent_t evF, evJ;
    cudaEventCreateWithFlags(&evF, cudaEventDisableTiming);
    cudaEventCreateWithFlags(&evJ, cudaEventDisableTiming);
    cudaStream_t s0 = 0;

    // ---- common prep on s0 ----
    rope_table_kernel<<<1024, 256, 0, s0>>>();
    conv_planes<<<NBB * SS, 256, 0, s0>>>(post_dec, pPpd, 0);

    cudaEventRecord(evF, s0);
    cudaStreamWaitEvent(s2, evF, 0);

    // ================= s2: write side + independent k2/a2 path =============
    trans_conv<<<dim3(16, 16, 6), dim3(32, 8), 0, s2>>>(encw_Wqkv, pPW + 0LL * 262144, WLO, 512, 512, 262144, 262144, nullptr);
    trans_conv<<<dim3(16, 16, 2), dim3(32, 8), 0, s2>>>(encw_Wo,   pPW + 6LL * 262144, WLO, 512, 512, 262144, 262144, nullptr);
    trans_conv<<<dim3(16, 16, 4), dim3(32, 8), 0, s2>>>(encw_Wff,  pPW + 8LL * 262144, WLO, 512, 512, 262144, 262144, nullptr);
    conv_planes<<<NDOC * SS, 256, 0, s2>>>(raw_emb, pPraw, 0);
    bias_prep<<<NDOC, 256, 0, s2>>>(pos_w, pBW, 1);

    run_encoder(raw_emb, pXw, NDOC, pPraw, pBW,
                pPW, encw_bqkv, encw_bo, encw_ln, encw_bff,
                pKw, pShw, pPqw, pPkw, pPvtw, pPpw, pPbqw, pPhw, pPxw,
                LOW, s2);

    vgate_kernel<<<NDOC * SS, 256, 0, s2>>>(pXw, raw_emb, W_ig, b_ig, pVd);
    trans_conv<<<dim3(16, 16, 1), dim3(32, 8), 0, s2>>>(W_k, pPW + 24LL * 262144, WLO, 512, 512, 262144, 262144, nullptr);
    tg1(pPraw, 0, pPW + 24LL * 262144, 0, nullptr, pKd, 0, nullptr, nullptr, 0, 0,
        NDOC * SS, 512, 512, 1, 1.0f, 0, s2);
    sgemm_launch(questions, pKd, nullptr, pS1, QQ, SS, DD, NDOC, 0, 524288, 65536, scD, 1, s2);
    softmax_f32<<<NDOC * QQ, 256, 0, s2>>>(pS1, pBW, SS, QQ);
    sgemm_launch(pS1, pVd, nullptr, pA1, QQ, DD, SS, NDOC, 65536, 524288, 32768, 1.0f, 0, s2);
    trans_conv<<<dim3(16, 2, 16), dim3(32, 8), 0, s2>>>(pA1, pPsel, 0, 64, 512, 32768, 32768, lookup);

    // independent k2/a2/A2 chain
    trans_conv<<<dim3(16, 16, 1), dim3(32, 8), 0, s2>>>(W_ok, pPW + 25LL * 262144, WLO, 512, 512, 262144, 262144, nullptr);
    conv_planes<<<QQ, 256, 0, s2>>>(questions, pPqst, 0);
    tg1(pPpd, 0, pPW + 25LL * 262144, 0, b_ok, nullptr, 0, pPk2, nullptr, 0, 0,
        NBB * SS, 512, 512, 1, 1.0f, 0, s2);
    {
        dim3 grid(1, (NBB * SS) / 128, 1);
        tgemm1n64<<<grid, 256, T1N_SMEM, s2>>>(pPk2, pPqst, pA2s, NBB * SS, QQ, DD, 0.125f);
    }
    softmax64_planes<<<NBB * SS / 8, 256, 0, s2>>>(pA2s, pPa2);
    tg1(pPa2, 65536, pPsel, 32768, nullptr, pA2, 524288, nullptr, nullptr, 0, 0,
        1024, 512, 64, NBB, 1.0f, 0, s2);

    cudaEventRecord(evJ, s2);

    // ================= s0: read-side encoder (long pole) ====================
    trans_conv<<<dim3(16, 16, 6), dim3(32, 8), 0, s0>>>(encr_Wqkv, pPW + 12LL * 262144, WLO, 512, 512, 262144, 262144, nullptr);
    trans_conv<<<dim3(16, 16, 2), dim3(32, 8), 0, s0>>>(encr_Wo,   pPW + 18LL * 262144, WLO, 512, 512, 262144, 262144, nullptr);
    trans_conv<<<dim3(16, 16, 4), dim3(32, 8), 0, s0>>>(encr_Wff,  pPW + 20LL * 262144, WLO, 512, 512, 262144, 262144, nullptr);
    bias_prep<<<NBB, 256, 0, s0>>>(pos_r, pBR, 2);

    run_encoder(post_dec, pX, NBB, pPpd, pBR,
                pPW + 12LL * 262144, encr_bqkv, encr_bo, encr_ln, encr_bff,
                pK, pSh, pPq, pPk, pPvt, pPp, pPbq, pPh, pPx,
                LO, s0);

    // join + final
    cudaStreamWaitEvent(s0, evJ, 0);
    out_kernel<<<NBB * SS, 256, 0, s0>>>(pX, pA2, post_dec,
                                         W_u1, b_u1, W_u2, b_u2, b1,
                                         out, gate);

    (void)in_sizes; (void)n_in; (void)out_size;
}

// round 16
// speedup vs baseline: 1.1611x; 1.0832x over previous
#include <cuda_runtime.h>
#include <cuda_fp16.h>
#include <math.h>
#include <stdint.h>

#define DD     512
#define SS     1024
#define NBB    16
#define QQ     64
#define NDOC   8

// ---- f32 scratch ----
__device__ float g_Kb  [16384 * 512];
__device__ float g_Kw  [8192 * 512];
__device__ float g_S1  [8 * 64 * 1024];
__device__ float g_Kdoc[8192 * 512];
__device__ float g_Vdoc[8192 * 512];
__device__ float g_A1S [8 * 64 * 512];
__device__ float g_A2SC[16384 * 64];
__device__ float g_A2  [16384 * 512];
__device__ float g_sin [1024 * 256];
__device__ float g_cos [1024 * 256];
__device__ float g_BIASW[8 * 1024];
__device__ float g_BIASR[16 * 1024];

#define WLO 6815744LL
#define LO  8388608LL
#define LOW 4194304LL
__device__ __align__(16) __half g_PW  [2 * 26 * 262144];
__device__ __align__(16) __half g_Praw[4194304];
__device__ __align__(16) __half g_Ppd [8388608];
// read-side planes
__device__ __align__(16) __half g_Px  [2 * 8388608];
__device__ __align__(16) __half g_Pq  [8388608];
__device__ __align__(16) __half g_Pk  [8388608];
__device__ __align__(16) __half g_Pvt [8388608];
__device__ __align__(16) __half g_Pp  [16777216];
__device__ __align__(16) __half g_Pbq [2 * 8388608];
__device__ __align__(16) __half g_Ph  [2 * 8388608];
__device__ __align__(16) __half g_Sh  [16 * 1048576];
// write-side planes
__device__ __align__(16) __half g_Pxw [2 * 4194304];
__device__ __align__(16) __half g_Pqw [4194304];
__device__ __align__(16) __half g_Pkw [4194304];
__device__ __align__(16) __half g_Pvtw[4194304];
__device__ __align__(16) __half g_Ppw [8388608];
__device__ __align__(16) __half g_Pbqw[2 * 4194304];
__device__ __align__(16) __half g_Phw [2 * 4194304];
__device__ __align__(16) __half g_Shw [8 * 1048576];
// misc planes
__device__ __align__(16) __half g_Pk2 [8388608];
__device__ __align__(16) __half g_Pa2 [1048576];
__device__ __align__(16) __half g_Psel[524288];
__device__ __align__(16) __half g_Pqst[32768];

__device__ __forceinline__ uint32_t smem_u32(const void* p) {
    uint32_t a;
    asm("{ .reg .u64 t; cvta.to.shared.u64 t, %1; cvt.u32.u64 %0, t; }"
        : "=r"(a) : "l"(p));
    return a;
}

__device__ __forceinline__ void ldsm4(uint32_t* r, uint32_t addr) {
    asm volatile("ldmatrix.sync.aligned.m8n8.x4.shared.b16 {%0,%1,%2,%3}, [%4];"
                 : "=r"(r[0]), "=r"(r[1]), "=r"(r[2]), "=r"(r[3]) : "r"(addr));
}

__device__ __forceinline__ void mma_f16(float* c, const uint32_t* a,
                                        uint32_t b0, uint32_t b1) {
    asm volatile(
        "mma.sync.aligned.m16n8k16.row.col.f32.f16.f16.f32 "
        "{%0,%1,%2,%3}, {%4,%5,%6,%7}, {%8,%9}, {%0,%1,%2,%3};"
        : "+f"(c[0]), "+f"(c[1]), "+f"(c[2]), "+f"(c[3])
        : "r"(a[0]), "r"(a[1]), "r"(a[2]), "r"(a[3]), "r"(b0), "r"(b1));
}

__device__ __forceinline__ void cpasync16(uint32_t dst, const void* src) {
    asm volatile("cp.async.cg.shared.global [%0], [%1], 16;" :: "r"(dst), "l"(src));
}
#define CP_COMMIT() asm volatile("cp.async.commit_group;" ::: "memory")
#define CP_WAIT(n)  asm volatile("cp.async.wait_group %0;" :: "n"(n) : "memory")

__device__ __forceinline__ void split_pair(float x0, float x1,
                                           __half2& h, __half2& l) {
    h = __floats2half2_rn(x0, x1);
    l = __floats2half2_rn(x0 - __low2float(h), x1 - __high2float(h));
}

// ---------------------------------------------------------------------------
// 3-term split GEMM (fp16 planes): residual-path GEMMs (Wo, FF)
// ---------------------------------------------------------------------------
#define PLANE  10240
#define TSTAGE 40960
#define TG_SMEM (4 * 40960)

__global__ void __launch_bounds__(512)
tgemm3(const __half* __restrict__ Ah0, const __half* __restrict__ Bh0,
       const float* __restrict__ bias, float* __restrict__ Cf,
       __half* __restrict__ Ch0,
       int M, int N, int K,
       long long loA, long long loB, long long loC,
       long long sA, long long sB, long long sC, long long sCp,
       float alpha, int epi)
{
    extern __shared__ char smem[];
    const uint32_t sbu = smem_u32(smem);
    const int t = threadIdx.x, w = t >> 5, lane = t & 31;
    const int wm = w & 3, wn = w >> 2;
    const int z = blockIdx.z;
    const int m0 = blockIdx.y * 128, n0 = blockIdx.x * 128;

    const __half* Ah = Ah0 + (size_t)z * sA;
    const __half* Bh = Bh0 + (size_t)z * sB;

    const int lrow = t >> 2, seg = t & 3;
    const __half* pr[4];
    pr[0] = Ah + (size_t)(m0 + lrow) * K + seg * 8;
    pr[1] = pr[0] + loA;
    pr[2] = Bh + (size_t)(n0 + lrow) * K + seg * 8;
    pr[3] = pr[2] + loB;

    float acc[2][4][4];
#pragma unroll
    for (int i = 0; i < 2; i++)
#pragma unroll
        for (int j = 0; j < 4; j++)
#pragma unroll
            for (int e = 0; e < 4; e++) acc[i][j][e] = 0.0f;

    const int nch = K >> 5;
    const uint32_t sdbase = sbu + (uint32_t)(lrow * 80 + seg * 16);

#define ISSUE(ch) do {                                                      \
    uint32_t _sd = sdbase + (uint32_t)((ch) & 3) * TSTAGE;                  \
    const int _cb = (ch) * 32;                                              \
    _Pragma("unroll")                                                       \
    for (int _p = 0; _p < 4; _p++)                                          \
        cpasync16(_sd + _p * PLANE, pr[_p] + _cb);                          \
    CP_COMMIT();                                                            \
} while (0)

    ISSUE(0);
    ISSUE(1);
    if (nch > 2) ISSUE(2);

    const uint32_t lmoff = (uint32_t)((lane & 15) * 80 + (lane >> 4) * 16);

    for (int ch = 0; ch < nch; ch++) {
        const int rem = nch - 1 - ch;
        if (rem >= 2)      { CP_WAIT(2); }
        else if (rem == 1) { CP_WAIT(1); }
        else               { CP_WAIT(0); }
        __syncthreads();
        if (ch + 3 < nch) ISSUE(ch + 3);

        const uint32_t sAh = sbu + (uint32_t)(ch & 3) * TSTAGE;
        const uint32_t sBh = sAh + 2 * PLANE;
#pragma unroll
        for (int kk = 0; kk < 2; kk++) {
            uint32_t ah[2][4], al[2][4], bh[2][4], bl[2][4];
#pragma unroll
            for (int mt = 0; mt < 2; mt++) {
                uint32_t aaddr = sAh + (uint32_t)((wm * 32 + mt * 16) * 80 + kk * 32) + lmoff;
                ldsm4(ah[mt], aaddr);
                ldsm4(al[mt], aaddr + PLANE);
            }
#pragma unroll
            for (int ng = 0; ng < 2; ng++) {
                uint32_t baddr = sBh + (uint32_t)((wn * 32 + ng * 16) * 80 + kk * 32) + lmoff;
                ldsm4(bh[ng], baddr);
                ldsm4(bl[ng], baddr + PLANE);
            }
#pragma unroll
            for (int ng = 0; ng < 2; ng++)
#pragma unroll
                for (int mt = 0; mt < 2; mt++)
#pragma unroll
                    for (int h2 = 0; h2 < 2; h2++)
                        mma_f16(acc[mt][ng * 2 + h2], ah[mt], bh[ng][h2], bh[ng][h2 + 2]);
#pragma unroll
            for (int ng = 0; ng < 2; ng++)
#pragma unroll
                for (int mt = 0; mt < 2; mt++)
#pragma unroll
                    for (int h2 = 0; h2 < 2; h2++)
                        mma_f16(acc[mt][ng * 2 + h2], ah[mt], bl[ng][h2], bl[ng][h2 + 2]);
#pragma unroll
            for (int ng = 0; ng < 2; ng++)
#pragma unroll
                for (int mt = 0; mt < 2; mt++)
#pragma unroll
                    for (int h2 = 0; h2 < 2; h2++)
                        mma_f16(acc[mt][ng * 2 + h2], al[mt], bh[ng][h2], bh[ng][h2 + 2]);
        }
    }
#undef ISSUE

    const float GC = 0.7978845608028654f;
    const int crow = m0 + wm * 32 + (lane >> 2);
    const int ccol = n0 + wn * 32 + (lane & 3) * 2;

    float* Cfz = Cf ? Cf + (size_t)z * sC : (float*)0;
    __half* Chz = Ch0 ? Ch0 + (size_t)z * sCp : (__half*)0;
    __half* Clz = Chz ? Chz + loC : (__half*)0;
#pragma unroll
    for (int mt = 0; mt < 2; mt++) {
#pragma unroll
        for (int n8 = 0; n8 < 4; n8++) {
            const float* c = acc[mt][n8];
            const int col = ccol + n8 * 8;
            float b0 = bias ? bias[col]     : 0.0f;
            float b1 = bias ? bias[col + 1] : 0.0f;
#pragma unroll
            for (int h = 0; h < 2; h++) {
                const int row = crow + mt * 16 + h * 8;
                float x0 = c[h * 2 + 0] * alpha + b0;
                float x1 = c[h * 2 + 1] * alpha + b1;
                if (epi == 1) {
                    x0 = 0.5f * x0 * (1.0f + tanhf(GC * (x0 + 0.044715f * x0 * x0 * x0)));
                    x1 = 0.5f * x1 * (1.0f + tanhf(GC * (x1 + 0.044715f * x1 * x1 * x1)));
                }
                if (Cfz)
                    *(float2*)&Cfz[(size_t)row * N + col] = make_float2(x0, x1);
                if (Chz) {
                    __half2 hh, ll;
                    split_pair(x0, x1, hh, ll);
                    *(__half2*)&Chz[(size_t)row * N + col] = hh;
                    *(__half2*)&Clz[(size_t)row * N + col] = ll;
                }
            }
        }
    }
}

static void tg3(const __half* Ah, long long loA, long long sA,
                const __half* Bh, long long loB, long long sB,
                const float* bias, float* Cf, long long sC,
                __half* Ch, long long loC, long long sCp,
                int M, int N, int K, int batch, float alpha, int epi,
                cudaStream_t st)
{
    dim3 grid(N / 128, M / 128, batch);
    tgemm3<<<grid, 512, TG_SMEM, st>>>(Ah, Bh, bias, Cf, Ch, M, N, K,
                                       loA, loB, loC, sA, sB, sC, sCp, alpha, epi);
}

// ---------------------------------------------------------------------------
// 1-term GEMM (hi planes only). epi: 0 = plain, 2 = QKV rope epilogue
//   epi=2: cols<1024 rope -> Ch0/Ch2 hi planes;
//          cols>=1024 -> V fp16 TRANSPOSED to Cf (as __half*, [D,S] per batch)
// ---------------------------------------------------------------------------
#define T1STAGE 20480
#define T1_SMEM (4 * 20480)

__global__ void __launch_bounds__(512)
tgemm1(const __half* __restrict__ Ah0, const __half* __restrict__ Bh0,
       const float* __restrict__ bias, float* __restrict__ Cf,
       __half* __restrict__ Ch0, __half* __restrict__ Ch2,
       int M, int N, int K, long long loC,
       long long sA, long long sB, long long sC, long long sCp,
       float alpha, int epi)
{
    extern __shared__ char smem[];
    const uint32_t sbu = smem_u32(smem);
    const int t = threadIdx.x, w = t >> 5, lane = t & 31;
    const int wm = w & 3, wn = w >> 2;
    const int z = blockIdx.z;
    const int m0 = blockIdx.y * 128, n0 = blockIdx.x * 128;

    const __half* Ap = Ah0 + (size_t)z * sA + (size_t)(m0 + (t >> 2)) * K + (t & 3) * 8;
    const __half* Bp = Bh0 + (size_t)z * sB + (size_t)(n0 + (t >> 2)) * K + (t & 3) * 8;

    float acc[2][4][4];
#pragma unroll
    for (int i = 0; i < 2; i++)
#pragma unroll
        for (int j = 0; j < 4; j++)
#pragma unroll
            for (int e = 0; e < 4; e++) acc[i][j][e] = 0.0f;

    const int nch = K >> 5;
    const uint32_t sdbase = sbu + (uint32_t)((t >> 2) * 80 + (t & 3) * 16);

#define ISSUE1(ch) do {                                                     \
    uint32_t _sd = sdbase + (uint32_t)((ch) & 3) * T1STAGE;                 \
    const int _cb = (ch) * 32;                                              \
    cpasync16(_sd,         Ap + _cb);                                       \
    cpasync16(_sd + PLANE, Bp + _cb);                                       \
    CP_COMMIT();                                                            \
} while (0)

    ISSUE1(0);
    ISSUE1(1);
    if (nch > 2) ISSUE1(2);

    const uint32_t lmoff = (uint32_t)((lane & 15) * 80 + (lane >> 4) * 16);

    for (int ch = 0; ch < nch; ch++) {
        const int rem = nch - 1 - ch;
        if (rem >= 2)      { CP_WAIT(2); }
        else if (rem == 1) { CP_WAIT(1); }
        else               { CP_WAIT(0); }
        __syncthreads();
        if (ch + 3 < nch) ISSUE1(ch + 3);

        const uint32_t sAh = sbu + (uint32_t)(ch & 3) * T1STAGE;
        const uint32_t sBh = sAh + PLANE;
#pragma unroll
        for (int kk = 0; kk < 2; kk++) {
            uint32_t ah[2][4], bh[2][4];
#pragma unroll
            for (int mt = 0; mt < 2; mt++)
                ldsm4(ah[mt], sAh + (uint32_t)((wm * 32 + mt * 16) * 80 + kk * 32) + lmoff);
#pragma unroll
            for (int ng = 0; ng < 2; ng++)
                ldsm4(bh[ng], sBh + (uint32_t)((wn * 32 + ng * 16) * 80 + kk * 32) + lmoff);
#pragma unroll
            for (int ng = 0; ng < 2; ng++)
#pragma unroll
                for (int mt = 0; mt < 2; mt++)
#pragma unroll
                    for (int h2 = 0; h2 < 2; h2++)
                        mma_f16(acc[mt][ng * 2 + h2], ah[mt], bh[ng][h2], bh[ng][h2 + 2]);
        }
    }
#undef ISSUE1

    const int crow = m0 + wm * 32 + (lane >> 2);
    const int ccol = n0 + wn * 32 + (lane & 3) * 2;

    if (epi == 2) {
        __half* Vt = (__half*)Cf;
#pragma unroll
        for (int mt = 0; mt < 2; mt++) {
#pragma unroll
            for (int n8 = 0; n8 < 4; n8++) {
                const float* c = acc[mt][n8];
                const int col = ccol + n8 * 8;
                float b0 = bias[col], b1 = bias[col + 1];
#pragma unroll
                for (int h = 0; h < 2; h++) {
                    const int row = crow + mt * 16 + h * 8;
                    float x0 = c[h * 2 + 0] + b0;
                    float x1 = c[h * 2 + 1] + b1;
                    if (col < 1024) {
                        const int s = row & (SS - 1);
                        const int i = (col & 511) >> 1;
                        float sn = g_sin[s * 256 + i];
                        float cs = g_cos[s * 256 + i];
                        float y0 = x0 * cs - x1 * sn;
                        float y1 = x0 * sn + x1 * cs;
                        __half* dst = (col < 512) ? Ch0 : Ch2;
                        size_t off = (size_t)row * 512 + (col & 511);
                        *(__half2*)&dst[off] = __floats2half2_rn(y0, y1);
                    } else {
                        const int b = row >> 10, srow = row & 1023;
                        size_t base = (size_t)b * 524288 +
                                      (size_t)(col - 1024) * 1024 + srow;
                        Vt[base]        = __float2half_rn(x0);
                        Vt[base + 1024] = __float2half_rn(x1);
                    }
                }
            }
        }
        return;
    }

    float* Cfz = Cf ? Cf + (size_t)z * sC : (float*)0;
    __half* Chz = Ch0 ? Ch0 + (size_t)z * sCp : (__half*)0;
    __half* Clz = (Chz && loC) ? Chz + loC : (__half*)0;
#pragma unroll
    for (int mt = 0; mt < 2; mt++) {
#pragma unroll
        for (int n8 = 0; n8 < 4; n8++) {
            const float* c = acc[mt][n8];
            const int col = ccol + n8 * 8;
            float b0 = bias ? bias[col]     : 0.0f;
            float b1 = bias ? bias[col + 1] : 0.0f;
#pragma unroll
            for (int h = 0; h < 2; h++) {
                const int row = crow + mt * 16 + h * 8;
                float x0 = c[h * 2 + 0] * alpha + b0;
                float x1 = c[h * 2 + 1] * alpha + b1;
                if (Cfz)
                    *(float2*)&Cfz[(size_t)row * N + col] = make_float2(x0, x1);
                if (Chz) {
                    __half2 hh, ll;
                    split_pair(x0, x1, hh, ll);
                    *(__half2*)&Chz[(size_t)row * N + col] = hh;
                    if (Clz) *(__half2*)&Clz[(size_t)row * N + col] = ll;
                }
            }
        }
    }
}

static void tg1(const __half* Ah, long long sA, const __half* Bh, long long sB,
                const float* bias, float* Cf, long long sC,
                __half* Ch, __half* Ch2, long long loC, long long sCp,
                int M, int N, int K, int batch, float alpha, int epi,
                cudaStream_t st)
{
    dim3 grid(N / 128, M / 128, batch);
    tgemm1<<<grid, 512, T1_SMEM, st>>>(Ah, Bh, bias, Cf, Ch, Ch2, M, N, K, loC,
                                       sA, sB, sC, sCp, alpha, epi);
}

// 1-term, N-tile 64
#define B1STAGE 15360
#define T1N_SMEM (4 * 15360)

__global__ void __launch_bounds__(256)
tgemm1n64(const __half* __restrict__ Ah0, const __half* __restrict__ Bh0,
          float* __restrict__ Cf, int M, int N, int K, float alpha)
{
    extern __shared__ char smem[];
    const uint32_t sbu = smem_u32(smem);
    const int t = threadIdx.x, w = t >> 5, lane = t & 31;
    const int wm = w & 3, wn = w >> 2;
    const int m0 = blockIdx.y * 128, n0 = blockIdx.x * 64;

    const int arow = t >> 1, aseg = (t & 1) * 2;
    const int brow = t >> 2, bseg = t & 3;
    const __half* pa = Ah0 + (size_t)(m0 + arow) * K + aseg * 8;
    const __half* pb = Bh0 + (size_t)(n0 + brow) * K + bseg * 8;
    const uint32_t adst = sbu + (uint32_t)(arow * 80 + aseg * 16);
    const uint32_t bdst = sbu + 10240u + (uint32_t)(brow * 80 + bseg * 16);

    float acc[2][4][4];
#pragma unroll
    for (int i = 0; i < 2; i++)
#pragma unroll
        for (int j = 0; j < 4; j++)
#pragma unroll
            for (int e = 0; e < 4; e++) acc[i][j][e] = 0.0f;

    const int nch = K >> 5;

#define ISSUEN(ch) do {                                                     \
    uint32_t _st = (uint32_t)((ch) & 3) * B1STAGE;                          \
    const int _cb = (ch) * 32;                                              \
    cpasync16(adst + _st,      pa + _cb);                                   \
    cpasync16(adst + _st + 16, pa + _cb + 8);                               \
    cpasync16(bdst + _st,      pb + _cb);                                   \
    CP_COMMIT();                                                            \
} while (0)

    ISSUEN(0);
    ISSUEN(1);
    if (nch > 2) ISSUEN(2);

    const uint32_t lmoff = (uint32_t)((lane & 15) * 80 + (lane >> 4) * 16);

    for (int ch = 0; ch < nch; ch++) {
        const int rem = nch - 1 - ch;
        if (rem >= 2)      { CP_WAIT(2); }
        else if (rem == 1) { CP_WAIT(1); }
        else               { CP_WAIT(0); }
        __syncthreads();
        if (ch + 3 < nch) ISSUEN(ch + 3);

        const uint32_t sAh = sbu + (uint32_t)(ch & 3) * B1STAGE;
        const uint32_t sBh = sAh + 10240u;
#pragma unroll
        for (int kk = 0; kk < 2; kk++) {
            uint32_t ah[2][4], bh[2][4];
#pragma unroll
            for (int mt = 0; mt < 2; mt++)
                ldsm4(ah[mt], sAh + (uint32_t)((wm * 32 + mt * 16) * 80 + kk * 32) + lmoff);
#pragma unroll
            for (int ng = 0; ng < 2; ng++)
                ldsm4(bh[ng], sBh + (uint32_t)((wn * 32 + ng * 16) * 80 + kk * 32) + lmoff);
#pragma unroll
            for (int ng = 0; ng < 2; ng++)
#pragma unroll
                for (int mt = 0; mt < 2; mt++)
#pragma unroll
                    for (int h2 = 0; h2 < 2; h2++)
                        mma_f16(acc[mt][ng * 2 + h2], ah[mt], bh[ng][h2], bh[ng][h2 + 2]);
        }
    }
#undef ISSUEN

    const int crow = m0 + wm * 32 + (lane >> 2);
    const int ccol = n0 + wn * 32 + (lane & 3) * 2;
#pragma unroll
    for (int mt = 0; mt < 2; mt++)
#pragma unroll
        for (int n8 = 0; n8 < 4; n8++) {
            const float* c = acc[mt][n8];
            const int col = ccol + n8 * 8;
#pragma unroll
            for (int h = 0; h < 2; h++) {
                const int row = crow + mt * 16 + h * 8;
                *(float2*)&Cf[(size_t)row * N + col] =
                    make_float2(c[h * 2] * alpha, c[h * 2 + 1] * alpha);
            }
        }
}

// ---------------------------------------------------------------------------
__global__ void trans_conv(const float* __restrict__ in, __half* __restrict__ oh,
                           long long loOff, int R, int C,
                           long long sI, long long sO, const int* __restrict__ ids)
{
    __shared__ float tile[32][33];
    const int z = blockIdx.z;
    size_t ib = ids ? (size_t)ids[z] * sI : (size_t)z * sI;
    const float* ip = in + ib;
    __half* ohz = oh + (size_t)z * sO;
    __half* olz = loOff ? ohz + loOff : (__half*)0;
    const int c0 = blockIdx.x * 32, r0 = blockIdx.y * 32;
    const int tx = threadIdx.x, ty = threadIdx.y;
#pragma unroll
    for (int k = 0; k < 32; k += 8)
        tile[ty + k][tx] = ip[(size_t)(r0 + ty + k) * C + c0 + tx];
    __syncthreads();
    const int rr = (tx & 15) * 2, chf = tx >> 4;
#pragma unroll
    for (int k = 0; k < 2; k++) {
        int cc = ty + chf * 8 + k * 16;
        __half2 h, l;
        split_pair(tile[rr][cc], tile[rr + 1][cc], h, l);
        *(__half2*)&ohz[(size_t)(c0 + cc) * R + r0 + rr] = h;
        if (olz) *(__half2*)&olz[(size_t)(c0 + cc) * R + r0 + rr] = l;
    }
}

__global__ void conv_planes(const float* __restrict__ in, __half* __restrict__ oh,
                            long long lo)
{
    size_t idx = (size_t)blockIdx.x * 512 + (size_t)threadIdx.x * 2;
    float2 v = *(const float2*)&in[idx];
    __half2 h, l;
    split_pair(v.x, v.y, h, l);
    *(__half2*)&oh[idx] = h;
    if (lo) *(__half2*)&(oh + lo)[idx] = l;
}

__global__ void rope_table_kernel()
{
    int s = blockIdx.x;
    int i = threadIdx.x;
    float invf = 1.0f / powf(10000.0f, (float)i / 256.0f);
    float angf = (float)s * invf;
    double ang = (double)angf;
    g_sin[s * 256 + i] = (float)sin(ang);
    g_cos[s * 256 + i] = (float)cos(ang);
}

__global__ void bias_prep(const float* __restrict__ pos, float* __restrict__ out, int mode)
{
    int n = blockIdx.x, t = threadIdx.x;
    for (int c = t; c < 1024; c += 256) {
        float p = pos[n * 1024 + c];
        out[n * 1024 + c] = (mode == 1) ? logf(p) : (logf(p) - log1pf(-p));
    }
}

// Softmax 1024 cols (fp16 scores) + bias -> hi plane; shuffle reductions
__global__ void softmax1024_planes(const __half* __restrict__ S, const float* __restrict__ bias,
                                   __half* __restrict__ oh)
{
    const int row = blockIdx.x, t = threadIdx.x;
    const int lane = t & 31, w = t >> 5;
    const __half* sr = S + (size_t)row * 1024;
    const float* pb = bias + (size_t)(row >> 10) * 1024;
    __half2 a  = *(const __half2*)&sr[2 * t];
    __half2 b2 = *(const __half2*)&sr[512 + 2 * t];
    float2 ba = *(const float2*)&pb[2 * t];
    float2 bb = *(const float2*)&pb[512 + 2 * t];
    float v0 = __low2float(a) + ba.x,  v1 = __high2float(a) + ba.y;
    float v2 = __low2float(b2) + bb.x, v3 = __high2float(b2) + bb.y;

    __shared__ float red[8];
    float mx = fmaxf(fmaxf(v0, v1), fmaxf(v2, v3));
#pragma unroll
    for (int k = 16; k > 0; k >>= 1)
        mx = fmaxf(mx, __shfl_xor_sync(0xFFFFFFFFu, mx, k));
    if (lane == 0) red[w] = mx;
    __syncthreads();
    mx = red[0];
#pragma unroll
    for (int i = 1; i < 8; i++) mx = fmaxf(mx, red[i]);
    __syncthreads();

    float e0 = expf(v0 - mx), e1 = expf(v1 - mx), e2 = expf(v2 - mx), e3 = expf(v3 - mx);
    float s = e0 + e1 + e2 + e3;
#pragma unroll
    for (int k = 16; k > 0; k >>= 1)
        s += __shfl_xor_sync(0xFFFFFFFFu, s, k);
    if (lane == 0) red[w] = s;
    __syncthreads();
    float tot = 0.0f;
#pragma unroll
    for (int i = 0; i < 8; i++) tot += red[i];
    float inv = 1.0f / tot;

    size_t o = (size_t)row * 1024 + 2 * t;
    *(__half2*)&oh[o]       = __floats2half2_rn(e0 * inv, e1 * inv);
    *(__half2*)&oh[o + 512] = __floats2half2_rn(e2 * inv, e3 * inv);
}

__global__ void softmax64_planes(const float* __restrict__ S, __half* __restrict__ oh)
{
    const int row = blockIdx.x * 8 + (threadIdx.x >> 5);
    const int lane = threadIdx.x & 31;
    const float* sr = S + (size_t)row * 64;
    float2 v = *(const float2*)&sr[lane * 2];
    float mx = fmaxf(v.x, v.y);
#pragma unroll
    for (int o = 16; o > 0; o >>= 1)
        mx = fmaxf(mx, __shfl_xor_sync(0xFFFFFFFF, mx, o));
    float e0 = expf(v.x - mx), e1 = expf(v.y - mx);
    float s = e0 + e1;
#pragma unroll
    for (int o = 16; o > 0; o >>= 1)
        s += __shfl_xor_sync(0xFFFFFFFF, s, o);
    float inv = 1.0f / s;
    *(__half2*)&oh[(size_t)row * 64 + lane * 2] = __floats2half2_rn(e0 * inv, e1 * inv);
}

__global__ void softmax_f32(float* __restrict__ S, const float* __restrict__ bias,
                            int cols, int rpb)
{
    int row = blockIdx.x;
    float* sr = S + (size_t)row * cols;
    const float* pb = bias + (size_t)(row / rpb) * cols;
    int t = threadIdx.x;
    __shared__ float red[256];

    float mx = -1e30f;
    for (int c = t; c < cols; c += 256) {
        float v = sr[c] + pb[c];
        sr[c] = v;
        mx = fmaxf(mx, v);
    }
    red[t] = mx; __syncthreads();
    for (int s = 128; s > 0; s >>= 1) { if (t < s) red[t] = fmaxf(red[t], red[t + s]); __syncthreads(); }
    mx = red[0]; __syncthreads();

    float sum = 0.0f;
    for (int c = t; c < cols; c += 256) {
        float e = expf(sr[c] - mx);
        sr[c] = e;
        sum += e;
    }
    red[t] = sum; __syncthreads();
    for (int s = 128; s > 0; s >>= 1) { if (t < s) red[t] += red[t + s]; __syncthreads(); }
    float inv = 1.0f / red[0];
    for (int c = t; c < cols; c += 256) sr[c] *= inv;
}

// LayerNorm: Xin from f32 (XinF) or planes (XinH hi + loIn lo); out planes only.
__global__ void ln_kernel(const float* __restrict__ XinF,
                          const __half* __restrict__ XinH, long long loIn,
                          const float* __restrict__ R,
                          const float* __restrict__ g, const float* __restrict__ b,
                          __half* __restrict__ oh, long long lo)
{
    const int row = blockIdx.x, t = threadIdx.x;
    const int lane = t & 31, w = t >> 5;
    const size_t o = (size_t)row * DD + 2 * t;

    float v0, v1;
    if (XinF) {
        float2 x = *(const float2*)&XinF[o];
        v0 = x.x; v1 = x.y;
    } else {
        __half2 h = *(const __half2*)&XinH[o];
        __half2 l = *(const __half2*)&(XinH + loIn)[o];
        v0 = __low2float(h) + __low2float(l);
        v1 = __high2float(h) + __high2float(l);
    }
    float2 r = *(const float2*)&R[o];
    v0 += r.x; v1 += r.y;

    __shared__ float red[8];
    float s = v0 + v1;
#pragma unroll
    for (int k = 16; k > 0; k >>= 1)
        s += __shfl_xor_sync(0xFFFFFFFFu, s, k);
    if (lane == 0) red[w] = s;
    __syncthreads();
    float m = 0.0f;
#pragma unroll
    for (int i = 0; i < 8; i++) m += red[i];
    m *= (1.0f / 512.0f);
    __syncthreads();

    float d0 = v0 - m, d1 = v1 - m;
    float q = d0 * d0 + d1 * d1;
#pragma unroll
    for (int k = 16; k > 0; k >>= 1)
        q += __shfl_xor_sync(0xFFFFFFFFu, q, k);
    if (lane == 0) red[w] = q;
    __syncthreads();
    float var = 0.0f;
#pragma unroll
    for (int i = 0; i < 8; i++) var += red[i];
    var *= (1.0f / 512.0f);
    float inv = rsqrtf(var + 1e-5f);

    float o0 = d0 * inv * g[2 * t]     + b[2 * t];
    float o1 = d1 * inv * g[2 * t + 1] + b[2 * t + 1];

    __half2 hh, ll;
    split_pair(o0, o1, hh, ll);
    *(__half2*)&oh[o] = hh;
    *(__half2*)&(oh + lo)[o] = ll;
}

// V = raw * sigmoid(F . W_ig + b_ig), F from planes
__global__ void vgate_kernel(const __half* __restrict__ Fh, long long loF,
                             const float* __restrict__ raw,
                             const float* __restrict__ Wig, const float* __restrict__ big,
                             float* __restrict__ V)
{
    const int row = blockIdx.x, t = threadIdx.x;
    const int lane = t & 31, w = t >> 5;
    const size_t o = (size_t)row * DD + 2 * t;
    __half2 h = *(const __half2*)&Fh[o];
    __half2 l = *(const __half2*)&(Fh + loF)[o];
    float f0 = __low2float(h) + __low2float(l);
    float f1 = __high2float(h) + __high2float(l);

    __shared__ float red[8];
    float s = f0 * Wig[2 * t] + f1 * Wig[2 * t + 1];
#pragma unroll
    for (int k = 16; k > 0; k >>= 1)
        s += __shfl_xor_sync(0xFFFFFFFFu, s, k);
    if (lane == 0) red[w] = s;
    __syncthreads();
    float tot = 0.0f;
#pragma unroll
    for (int i = 0; i < 8; i++) tot += red[i];
    float gte = 1.0f / (1.0f + expf(-(tot + big[0])));

    float2 rr = *(const float2*)&raw[o];
    *(float2*)&V[o] = make_float2(rr.x * gte, rr.y * gte);
}

// Final gate + output; FU from planes
__global__ void out_kernel(const __half* __restrict__ FUh, long long loF,
                           const float* __restrict__ A2,
                           const float* __restrict__ PD,
                           const float* __restrict__ Wu1, const float* __restrict__ bu1,
                           const float* __restrict__ Wu2, const float* __restrict__ bu2,
                           const float* __restrict__ b1,
                           float* __restrict__ out, float* __restrict__ gate)
{
    const int row = blockIdx.x, t = threadIdx.x;
    const int lane = t & 31, w = t >> 5;
    const size_t o = (size_t)row * DD + 2 * t;
    __half2 h = *(const __half2*)&FUh[o];
    __half2 l = *(const __half2*)&(FUh + loF)[o];
    float f0 = __low2float(h) + __low2float(l);
    float f1 = __high2float(h) + __high2float(l);
    float2 a2 = *(const float2*)&A2[o];
    float2 pd = *(const float2*)&PD[o];

    __shared__ float red[8];
    float s = f0 * Wu1[2 * t] + f1 * Wu1[2 * t + 1]
            + a2.x * Wu2[2 * t] + a2.y * Wu2[2 * t + 1];
#pragma unroll
    for (int k = 16; k > 0; k >>= 1)
        s += __shfl_xor_sync(0xFFFFFFFFu, s, k);
    if (lane == 0) red[w] = s;
    __syncthreads();
    float tot = 0.0f;
#pragma unroll
    for (int i = 0; i < 8; i++) tot += red[i];
    float z = tot + bu1[0] + bu2[0] + b1[0] - 4.0f;
    float g = 1.0f / (1.0f + expf(-z));

    *(float2*)&out[o] = make_float2(pd.x * (1.0f - g) + a2.x * g,
                                    pd.y * (1.0f - g) + a2.y * g);
    if (t == 0) gate[row] = g;
}

#define BM 64
#define BN 64
#define BK 16

__global__ void gemm_kernel(const float* __restrict__ A,
                            const float* __restrict__ Bm,
                            const float* __restrict__ bias,
                            float* __restrict__ C,
                            int M, int N, int K,
                            long long sA, long long sB, long long sC,
                            float alpha, int transB, int epi)
{
    const int bz = blockIdx.z;
    A  += (size_t)bz * sA;
    Bm += (size_t)bz * sB;
    C  += (size_t)bz * sC;

    const int m0 = blockIdx.y * BM;
    const int n0 = blockIdx.x * BN;

    __shared__ float As[BK][BM + 4];
    __shared__ float Bs[BK][BN + 4];

    const int t  = threadIdx.x;
    const int tx = t & 15;
    const int ty = t >> 4;

    float acc[4][4] = {};

    const int arow = t >> 2;
    const int akc  = (t & 3) * 4;
    const int kb   = t >> 4;
    const int nb   = (t & 15) * 4;

    for (int k0 = 0; k0 < K; k0 += BK) {
        float4 av = *(const float4*)&A[(size_t)(m0 + arow) * K + k0 + akc];
        As[akc + 0][arow] = av.x;
        As[akc + 1][arow] = av.y;
        As[akc + 2][arow] = av.z;
        As[akc + 3][arow] = av.w;

        if (!transB) {
            float4 bv = *(const float4*)&Bm[(size_t)(k0 + kb) * N + n0 + nb];
            *(float4*)&Bs[kb][nb] = bv;
        } else {
            float4 bv = *(const float4*)&Bm[(size_t)(n0 + arow) * K + k0 + akc];
            Bs[akc + 0][arow] = bv.x;
            Bs[akc + 1][arow] = bv.y;
            Bs[akc + 2][arow] = bv.z;
            Bs[akc + 3][arow] = bv.w;
        }
        __syncthreads();

#pragma unroll
        for (int k = 0; k < BK; k++) {
            float4 a = *(const float4*)&As[k][ty * 4];
            float4 b = *(const float4*)&Bs[k][tx * 4];
            acc[0][0] += a.x * b.x; acc[0][1] += a.x * b.y;
            acc[0][2] += a.x * b.z; acc[0][3] += a.x * b.w;
            acc[1][0] += a.y * b.x; acc[1][1] += a.y * b.y;
            acc[1][2] += a.y * b.z; acc[1][3] += a.y * b.w;
            acc[2][0] += a.z * b.x; acc[2][1] += a.z * b.y;
            acc[2][2] += a.z * b.z; acc[2][3] += a.z * b.w;
            acc[3][0] += a.w * b.x; acc[3][1] += a.w * b.y;
            acc[3][2] += a.w * b.z; acc[3][3] += a.w * b.w;
        }
        __syncthreads();
    }

#pragma unroll
    for (int i = 0; i < 4; i++) {
        const int row = m0 + ty * 4 + i;
        float v[4];
#pragma unroll
        for (int j = 0; j < 4; j++) {
            float x = acc[i][j] * alpha;
            if (bias) x += bias[n0 + tx * 4 + j];
            v[j] = x;
        }
        *(float4*)&C[(size_t)row * N + n0 + tx * 4] = make_float4(v[0], v[1], v[2], v[3]);
    }
}

static void sgemm_launch(const float* A, const float* B, const float* bias, float* C,
                         int M, int N, int K, int batch,
                         long long sA, long long sB, long long sC,
                         float alpha, int transB, cudaStream_t st)
{
    dim3 grid(N / BN, M / BM, batch);
    gemm_kernel<<<grid, 256, 0, st>>>(A, B, bias, C, M, N, K, sA, sB, sC, alpha, transB, 0);
}

// ---------------------------------------------------------------------------
// Encoder. QKV 1-term fused rope + transposed-V; Wo/FF 3-term; X in planes.
// ---------------------------------------------------------------------------
static void run_encoder(const float* Xin0, int nb,
                        const __half* initHi,
                        const float* biasRows, const __half* PW,
                        const float* bqkv, const float* bo,
                        const float* ln, const float* bff,
                        float* bK, __half* Sh,
                        __half* Pq, __half* Pk, __half* Pvt,
                        __half* Pp, __half* Pbq, __half* Ph,
                        __half* Px, long long lo, cudaStream_t st)
{
    const int rows = nb * SS;
    const float sc = 1.0f / sqrtf((float)DD);
    for (int l = 0; l < 2; l++) {
        const __half* AP = (l == 0) ? initHi : Px;
        tg1(AP, 0, PW + (size_t)(l * 3) * 262144, 0,
            bqkv + (size_t)l * 1536, (float*)Pvt, 0, Pq, Pk, 0, 0,
            rows, 1536, 512, 1, 1.0f, 2, st);
        tg1(Pq, 524288, Pk, 524288, nullptr, nullptr, 0, Sh, nullptr, 0, 1048576,
            1024, 1024, 512, nb, sc, 0, st);
        softmax1024_planes<<<rows, 256, 0, st>>>(Sh, biasRows, Pp);
        tg1(Pp, 1048576, Pvt, 524288, nullptr, nullptr, 0, Pbq, nullptr, lo, 524288,
            1024, 512, 1024, nb, 1.0f, 0, st);
        tg3(Pbq, lo, 0, PW + (size_t)(6 + l) * 262144, WLO, 0, bo + l * 512,
            bK, 0, nullptr, 0, 0, rows, 512, 512, 1, 1.0f, 0, st);
        ln_kernel<<<rows, 256, 0, st>>>((l == 0) ? Xin0 : nullptr,
                                        (l == 0) ? nullptr : Px, lo,
                                        bK, ln + l * 2048, ln + l * 2048 + 512, Px, lo);
        tg3(Px, lo, 0, PW + (size_t)(8 + 2 * l) * 262144, WLO, 0, bff + l * 1024,
            nullptr, 0, Ph, lo, 0, rows, 512, 512, 1, 1.0f, 1, st);
        tg3(Ph, lo, 0, PW + (size_t)(9 + 2 * l) * 262144, WLO, 0, bff + l * 1024 + 512,
            bK, 0, nullptr, 0, 0, rows, 512, 512, 1, 1.0f, 0, st);
        ln_kernel<<<rows, 256, 0, st>>>(nullptr, Px, lo, bK,
                                        ln + l * 2048 + 1024, ln + l * 2048 + 1536,
                                        Px, lo);
    }
}

extern "C" void kernel_launch(void* const* d_in, const int* in_sizes, int n_in,
                              void* d_out, int out_size)
{
    const float* raw_emb   = (const float*)d_in[0];
    const float* pos_w     = (const float*)d_in[1];
    const float* post_dec  = (const float*)d_in[2];
    const float* pos_r     = (const float*)d_in[3];
    const float* questions = (const float*)d_in[4];
    const float* W_k       = (const float*)d_in[5];
    const float* W_ig      = (const float*)d_in[6];
    const float* b_ig      = (const float*)d_in[7];
    const float* W_u1      = (const float*)d_in[8];
    const float* b_u1      = (const float*)d_in[9];
    const float* W_u2      = (const float*)d_in[10];
    const float* b_u2      = (const float*)d_in[11];
    const float* b1        = (const float*)d_in[12];
    const float* W_ok      = (const float*)d_in[13];
    const float* b_ok      = (const float*)d_in[14];
    const float* encw_Wqkv = (const float*)d_in[15];
    const float* encw_bqkv = (const float*)d_in[16];
    const float* encw_Wo   = (const float*)d_in[17];
    const float* encw_bo   = (const float*)d_in[18];
    const float* encw_ln   = (const float*)d_in[19];
    const float* encw_Wff  = (const float*)d_in[20];
    const float* encw_bff  = (const float*)d_in[21];
    const float* encr_Wqkv = (const float*)d_in[22];
    const float* encr_bqkv = (const float*)d_in[23];
    const float* encr_Wo   = (const float*)d_in[24];
    const float* encr_bo   = (const float*)d_in[25];
    const float* encr_ln   = (const float*)d_in[26];
    const float* encr_Wff  = (const float*)d_in[27];
    const float* encr_bff  = (const float*)d_in[28];
    const int*   lookup    = (const int*)d_in[29];

    float* out  = (float*)d_out;
    float* gate = out + (size_t)NBB * SS * DD;

    float *pK, *pKw, *pS1, *pKd, *pVd, *pA1, *pA2s, *pA2, *pBW, *pBR;
    __half *pPW, *pPraw, *pPpd, *pPx, *pPq, *pPk, *pPvt, *pPp, *pPbq, *pPh, *pSh;
    __half *pPxw, *pPqw, *pPkw, *pPvtw, *pPpw, *pPbqw, *pPhw, *pShw;
    __half *pPk2, *pPa2, *pPsel, *pPqst;
    cudaGetSymbolAddress((void**)&pK,    g_Kb);
    cudaGetSymbolAddress((void**)&pKw,   g_Kw);
    cudaGetSymbolAddress((void**)&pS1,   g_S1);
    cudaGetSymbolAddress((void**)&pKd,   g_Kdoc);
    cudaGetSymbolAddress((void**)&pVd,   g_Vdoc);
    cudaGetSymbolAddress((void**)&pA1,   g_A1S);
    cudaGetSymbolAddress((void**)&pA2s,  g_A2SC);
    cudaGetSymbolAddress((void**)&pA2,   g_A2);
    cudaGetSymbolAddress((void**)&pBW,   g_BIASW);
    cudaGetSymbolAddress((void**)&pBR,   g_BIASR);
    cudaGetSymbolAddress((void**)&pPW,   g_PW);
    cudaGetSymbolAddress((void**)&pPraw, g_Praw);
    cudaGetSymbolAddress((void**)&pPpd,  g_Ppd);
    cudaGetSymbolAddress((void**)&pPx,   g_Px);
    cudaGetSymbolAddress((void**)&pPq,   g_Pq);
    cudaGetSymbolAddress((void**)&pPk,   g_Pk);
    cudaGetSymbolAddress((void**)&pPvt,  g_Pvt);
    cudaGetSymbolAddress((void**)&pPp,   g_Pp);
    cudaGetSymbolAddress((void**)&pPbq,  g_Pbq);
    cudaGetSymbolAddress((void**)&pPh,   g_Ph);
    cudaGetSymbolAddress((void**)&pSh,   g_Sh);
    cudaGetSymbolAddress((void**)&pPxw,  g_Pxw);
    cudaGetSymbolAddress((void**)&pPqw,  g_Pqw);
    cudaGetSymbolAddress((void**)&pPkw,  g_Pkw);
    cudaGetSymbolAddress((void**)&pPvtw, g_Pvtw);
    cudaGetSymbolAddress((void**)&pPpw,  g_Ppw);
    cudaGetSymbolAddress((void**)&pPbqw, g_Pbqw);
    cudaGetSymbolAddress((void**)&pPhw,  g_Phw);
    cudaGetSymbolAddress((void**)&pShw,  g_Shw);
    cudaGetSymbolAddress((void**)&pPk2,  g_Pk2);
    cudaGetSymbolAddress((void**)&pPa2,  g_Pa2);
    cudaGetSymbolAddress((void**)&pPsel, g_Psel);
    cudaGetSymbolAddress((void**)&pPqst, g_Pqst);

    cudaFuncSetAttribute(tgemm3,    cudaFuncAttributeMaxDynamicSharedMemorySize, TG_SMEM);
    cudaFuncSetAttribute(tgemm1,    cudaFuncAttributeMaxDynamicSharedMemorySize, T1_SMEM);
    cudaFuncSetAttribute(tgemm1n64, cudaFuncAttributeMaxDynamicSharedMemorySize, T1N_SMEM);

    const float scD = 1.0f / sqrtf((float)DD);

    cudaStream_t s2;
    cudaStreamCreateWithFlags(&s2, cudaStreamNonBlocking);
    cudaEvent_t evF, evJ;
    cudaEventCreateWithFlags(&evF, cudaEventDisableTiming);
    cudaEventCreateWithFlags(&evJ, cudaEventDisableTiming);
    cudaStream_t s0 = 0;

    // ---- common prep on s0 ----
    rope_table_kernel<<<1024, 256, 0, s0>>>();
    conv_planes<<<NBB * SS, 256, 0, s0>>>(post_dec, pPpd, 0);

    cudaEventRecord(evF, s0);
    cudaStreamWaitEvent(s2, evF, 0);

    // ================= s2: write side + independent k2/a2 path =============
    trans_conv<<<dim3(16, 16, 6), dim3(32, 8), 0, s2>>>(encw_Wqkv, pPW + 0LL * 262144, WLO, 512, 512, 262144, 262144, nullptr);
    trans_conv<<<dim3(16, 16, 2), dim3(32, 8), 0, s2>>>(encw_Wo,   pPW + 6LL * 262144, WLO, 512, 512, 262144, 262144, nullptr);
    trans_conv<<<dim3(16, 16, 4), dim3(32, 8), 0, s2>>>(encw_Wff,  pPW + 8LL * 262144, WLO, 512, 512, 262144, 262144, nullptr);
    conv_planes<<<NDOC * SS, 256, 0, s2>>>(raw_emb, pPraw, 0);
    bias_prep<<<NDOC, 256, 0, s2>>>(pos_w, pBW, 1);

    run_encoder(raw_emb, NDOC, pPraw, pBW,
                pPW, encw_bqkv, encw_bo, encw_ln, encw_bff,
                pKw, pShw, pPqw, pPkw, pPvtw, pPpw, pPbqw, pPhw, pPxw,
                LOW, s2);

    vgate_kernel<<<NDOC * SS, 256, 0, s2>>>(pPxw, LOW, raw_emb, W_ig, b_ig, pVd);
    trans_conv<<<dim3(16, 16, 1), dim3(32, 8), 0, s2>>>(W_k, pPW + 24LL * 262144, WLO, 512, 512, 262144, 262144, nullptr);
    tg1(pPraw, 0, pPW + 24LL * 262144, 0, nullptr, pKd, 0, nullptr, nullptr, 0, 0,
        NDOC * SS, 512, 512, 1, 1.0f, 0, s2);
    sgemm_launch(questions, pKd, nullptr, pS1, QQ, SS, DD, NDOC, 0, 524288, 65536, scD, 1, s2);
    softmax_f32<<<NDOC * QQ, 256, 0, s2>>>(pS1, pBW, SS, QQ);
    sgemm_launch(pS1, pVd, nullptr, pA1, QQ, DD, SS, NDOC, 65536, 524288, 32768, 1.0f, 0, s2);
    trans_conv<<<dim3(16, 2, 16), dim3(32, 8), 0, s2>>>(pA1, pPsel, 0, 64, 512, 32768, 32768, lookup);

    // independent k2/a2/A2 chain
    trans_conv<<<dim3(16, 16, 1), dim3(32, 8), 0, s2>>>(W_ok, pPW + 25LL * 262144, WLO, 512, 512, 262144, 262144, nullptr);
    conv_planes<<<QQ, 256, 0, s2>>>(questions, pPqst, 0);
    tg1(pPpd, 0, pPW + 25LL * 262144, 0, b_ok, nullptr, 0, pPk2, nullptr, 0, 0,
        NBB * SS, 512, 512, 1, 1.0f, 0, s2);
    {
        dim3 grid(1, (NBB * SS) / 128, 1);
        tgemm1n64<<<grid, 256, T1N_SMEM, s2>>>(pPk2, pPqst, pA2s, NBB * SS, QQ, DD, 0.125f);
    }
    softmax64_planes<<<NBB * SS / 8, 256, 0, s2>>>(pA2s, pPa2);
    tg1(pPa2, 65536, pPsel, 32768, nullptr, pA2, 524288, nullptr, nullptr, 0, 0,
        1024, 512, 64, NBB, 1.0f, 0, s2);

    cudaEventRecord(evJ, s2);

    // ================= s0: read-side encoder (long pole) ====================
    trans_conv<<<dim3(16, 16, 6), dim3(32, 8), 0, s0>>>(encr_Wqkv, pPW + 12LL * 262144, WLO, 512, 512, 262144, 262144, nullptr);
    trans_conv<<<dim3(16, 16, 2), dim3(32, 8), 0, s0>>>(encr_Wo,   pPW + 18LL * 262144, WLO, 512, 512, 262144, 262144, nullptr);
    trans_conv<<<dim3(16, 16, 4), dim3(32, 8), 0, s0>>>(encr_Wff,  pPW + 20LL * 262144, WLO, 512, 512, 262144, 262144, nullptr);
    bias_prep<<<NBB, 256, 0, s0>>>(pos_r, pBR, 2);

    run_encoder(post_dec, NBB, pPpd, pBR,
                pPW + 12LL * 262144, encr_bqkv, encr_bo, encr_ln, encr_bff,
                pK, pSh, pPq, pPk, pPvt, pPp, pPbq, pPh, pPx,
                LO, s0);

    // join + final
    cudaStreamWaitEvent(s0, evJ, 0);
    out_kernel<<<NBB * SS, 256, 0, s0>>>(pPx, LO, pA2, post_dec,
                                         W_u1, b_u1, W_u2, b_u2, b1,
                                         out, gate);

    (void)in_sizes; (void)n_in; (void)out_size;
}